// round 7
// baseline (speedup 1.0000x reference)
#include <cuda_runtime.h>
#include <cuda_bf16.h>
#include <cstdint>

namespace {
constexpr int P_     = 256;
constexpr int H_     = 32;
constexpr int DM     = 2048;
constexpr int HD     = 64;
constexpr int PATCH_ = 256;

constexpr int BM = 64;
constexpr int BN = 64;
constexpr int KC = 32;                  // k per smem stage
constexpr int N_TILES = 3 * (DM / KC);  // 3 split passes x 64 = 192
constexpr int PADK  = 40;               // bf16 stride: 80B, conflict-free
constexpr int PANEL = BM * PADK * 2;    // 5120 B
constexpr int STAGE = 6 * PANEL;        // 30720 B
constexpr int SMEM_GEMM = 2 * STAGE;    // 61440 B (dynamic)
}

// ------------------------- device scratch (static) -------------------------
__device__ float g_vr[P_ * DM];
__device__ float g_vi[P_ * DM];
__device__ float g_yr[P_ * DM];
__device__ float g_yi[P_ * DM];

__device__ __nv_bfloat16 g_Yr_hi[P_ * DM];
__device__ __nv_bfloat16 g_Yr_lo[P_ * DM];
__device__ __nv_bfloat16 g_Yi_hi[P_ * DM];
__device__ __nv_bfloat16 g_Yi_lo[P_ * DM];
__device__ __nv_bfloat16 g_Ys_hi[P_ * DM];
__device__ __nv_bfloat16 g_Ys_lo[P_ * DM];

__device__ __nv_bfloat16 g_WtR_hi[DM * DM];   // [n][k] = w0R_k[k][n]
__device__ __nv_bfloat16 g_WtR_lo[DM * DM];
__device__ __nv_bfloat16 g_WtI_hi[DM * DM];
__device__ __nv_bfloat16 g_WtI_lo[DM * DM];
__device__ __nv_bfloat16 g_WtS_hi[DM * DM];   // WR + WI
__device__ __nv_bfloat16 g_WtS_lo[DM * DM];

__device__ __forceinline__ int clampi(int i, int sz) { return i < sz ? i : sz - 1; }

// ------------------------- asm helpers -------------------------
__device__ __forceinline__ uint32_t smem_u32(const void* p) {
    uint32_t a;
    asm("{ .reg .u64 t; cvta.to.shared.u64 t, %1; cvt.u32.u64 %0, t; }"
        : "=r"(a) : "l"(p));
    return a;
}
__device__ __forceinline__ void cpasync16(uint32_t s, const void* g) {
    asm volatile("cp.async.cg.shared.global [%0], [%1], 16;" :: "r"(s), "l"(g));
}
__device__ __forceinline__ void cp_commit() {
    asm volatile("cp.async.commit_group;");
}
__device__ __forceinline__ void cp_wait1() {
    asm volatile("cp.async.wait_group 1;");
}
__device__ __forceinline__ void cp_wait0() {
    asm volatile("cp.async.wait_group 0;");
}
__device__ __forceinline__ void ldmx4(uint32_t* r, uint32_t addr) {
    asm volatile("ldmatrix.sync.aligned.m8n8.x4.shared.b16 {%0,%1,%2,%3}, [%4];"
                 : "=r"(r[0]), "=r"(r[1]), "=r"(r[2]), "=r"(r[3]) : "r"(addr));
}
#define MMA_BF16(d, a, b0_, b1_)                                               \
    asm volatile(                                                              \
        "mma.sync.aligned.m16n8k16.row.col.f32.bf16.bf16.f32 "                 \
        "{%0,%1,%2,%3}, {%4,%5,%6,%7}, {%8,%9}, {%0,%1,%2,%3};"                \
        : "+f"(d[0]), "+f"(d[1]), "+f"(d[2]), "+f"(d[3])                       \
        : "r"(a[0]), "r"(a[1]), "r"(a[2]), "r"(a[3]), "r"(b0_), "r"(b1_))

// ---------------------------------------------------------------------------
// Kernel 1: vr = x @ vR_k + vR_b ; vi = x @ vI_k + vI_b   (fp32)
// ---------------------------------------------------------------------------
__global__ void gemm_v(const float* __restrict__ x, int sx,
                       const float* __restrict__ Wr, const float* __restrict__ br,
                       const float* __restrict__ Wi, const float* __restrict__ bi,
                       int sw, int sb)
{
    constexpr int K = PATCH_, N = DM;
    const float* W = blockIdx.z ? Wi : Wr;
    const float* b = blockIdx.z ? bi : br;
    float* C       = blockIdx.z ? g_vi : g_vr;

    __shared__ __align__(16) float As[64][17];
    __shared__ __align__(16) float Bs[16][64];

    const int tid = threadIdx.x;
    const int tx = tid & 15, ty = tid >> 4;
    const int row0 = blockIdx.y * 64, col0 = blockIdx.x * 64;

    float acc[4][4] = {};

    for (int k0 = 0; k0 < K; k0 += 16) {
        #pragma unroll
        for (int l = 0; l < 4; l++) {
            int idx = tid + l * 256;
            As[idx >> 4][idx & 15] =
                x[clampi((row0 + (idx >> 4)) * K + k0 + (idx & 15), sx)];
        }
        #pragma unroll
        for (int l = 0; l < 4; l++) {
            int idx = tid + l * 256;
            Bs[idx >> 6][idx & 63] =
                W[clampi((k0 + (idx >> 6)) * N + col0 + (idx & 63), sw)];
        }
        __syncthreads();
        #pragma unroll
        for (int kk = 0; kk < 16; kk++) {
            float a[4];
            #pragma unroll
            for (int i = 0; i < 4; i++) a[i] = As[ty * 4 + i][kk];
            float4 bv = *(const float4*)&Bs[kk][tx * 4];
            float bb[4] = {bv.x, bv.y, bv.z, bv.w};
            #pragma unroll
            for (int i = 0; i < 4; i++)
                #pragma unroll
                for (int j = 0; j < 4; j++)
                    acc[i][j] = fmaf(a[i], bb[j], acc[i][j]);
        }
        __syncthreads();
    }

    #pragma unroll
    for (int i = 0; i < 4; i++) {
        int r = row0 + ty * 4 + i;
        #pragma unroll
        for (int j = 0; j < 4; j++) {
            int c = col0 + tx * 4 + j;
            C[r * N + c] = acc[i][j] + b[clampi(c, sb)];
        }
    }
}

// ---------------------------------------------------------------------------
// Kernel 2: circulant shift-attention (fp32), 32-row s-tiles for occupancy.
// grid = (8 s-tiles, 32 heads), 256 threads; block = 32 s x 64 d.
// ---------------------------------------------------------------------------
__global__ void circ_att(const float* __restrict__ JR,
                         const float* __restrict__ JI, int sj)
{
    const int h  = blockIdx.y;
    const int s0 = blockIdx.x * 32;

    __shared__ __align__(16) float jr_s[512];
    __shared__ __align__(16) float ji_s[512];
    __shared__ __align__(16) float vr_s[64][64];
    __shared__ __align__(16) float vi_s[64][64];

    const int tid = threadIdx.x;
    const int tx = tid & 15, ty = tid >> 4;

    for (int t = tid; t < 512; t += 256) {
        int ji = clampi((t & 255) * H_ + h, sj);
        jr_s[t] = JR[ji];
        ji_s[t] = JI[ji];
    }

    float accR[2][4] = {}, accI[2][4] = {};

    for (int q0 = 0; q0 < P_; q0 += 64) {
        __syncthreads();
        #pragma unroll
        for (int l = 0; l < 16; l++) {
            int idx = tid + l * 256;
            int qq = idx >> 6, d = idx & 63;
            int gi = (q0 + qq) * DM + h * HD + d;
            vr_s[qq][d] = g_vr[gi];
            vi_s[qq][d] = g_vi[gi];
        }
        __syncthreads();

        #pragma unroll 4
        for (int kk = 0; kk < 64; kk++) {
            int q = q0 + kk;
            float jr[2], ji[2];
            #pragma unroll
            for (int i = 0; i < 2; i++) {
                jr[i] = jr_s[q + s0 + ty * 2 + i];
                ji[i] = ji_s[q + s0 + ty * 2 + i];
            }
            float4 vr4 = *(const float4*)&vr_s[kk][tx * 4];
            float4 vi4 = *(const float4*)&vi_s[kk][tx * 4];
            float vr[4] = {vr4.x, vr4.y, vr4.z, vr4.w};
            float vi[4] = {vi4.x, vi4.y, vi4.z, vi4.w};
            #pragma unroll
            for (int i = 0; i < 2; i++)
                #pragma unroll
                for (int j = 0; j < 4; j++) {
                    accR[i][j] = fmaf(jr[i], vr[j], accR[i][j]);
                    accR[i][j] = fmaf(-ji[i], vi[j], accR[i][j]);
                    accI[i][j] = fmaf(jr[i], vi[j], accI[i][j]);
                    accI[i][j] = fmaf(ji[i], vr[j], accI[i][j]);
                }
        }
    }

    #pragma unroll
    for (int i = 0; i < 2; i++) {
        int s = s0 + ty * 2 + i;
        #pragma unroll
        for (int j = 0; j < 4; j++) {
            int d = tx * 4 + j;
            g_yr[s * DM + h * HD + d] = accR[i][j];
            g_yi[s * DM + h * HD + d] = accI[i][j];
        }
    }
}

// ---------------------------------------------------------------------------
// Kernel 3a: split y (and ys = yr+yi) into bf16 hi/lo
// ---------------------------------------------------------------------------
__global__ void split_y()
{
    int i = blockIdx.x * 256 + threadIdx.x;
    if (i >= P_ * DM) return;
    float a = g_yr[i];
    float b = g_yi[i];
    float s = a + b;
    __nv_bfloat16 ha = __float2bfloat16(a);
    __nv_bfloat16 hb = __float2bfloat16(b);
    __nv_bfloat16 hs = __float2bfloat16(s);
    g_Yr_hi[i] = ha;  g_Yr_lo[i] = __float2bfloat16(a - __bfloat162float(ha));
    g_Yi_hi[i] = hb;  g_Yi_lo[i] = __float2bfloat16(b - __bfloat162float(hb));
    g_Ys_hi[i] = hs;  g_Ys_lo[i] = __float2bfloat16(s - __bfloat162float(hs));
}

// ---------------------------------------------------------------------------
// Kernel 3b: fused transpose + split of WR, WI, WR+WI -> 6 bf16 panels [n][k]
// grid (64, 64) 32x32 tiles, 256 threads. bf16x2 stores.
// ---------------------------------------------------------------------------
__global__ void split_wt(const float* __restrict__ WR,
                         const float* __restrict__ WI, int sw)
{
    __shared__ float tR[32][33];
    __shared__ float tI[32][33];
    const int tid = threadIdx.x;
    const int n0 = blockIdx.x * 32, k0 = blockIdx.y * 32;

    #pragma unroll
    for (int i = 0; i < 4; i++) {
        int idx = tid + i * 256;
        int kk = idx >> 5, nn = idx & 31;
        int gi = clampi((k0 + kk) * DM + n0 + nn, sw);
        tR[nn][kk] = WR[gi];
        tI[nn][kk] = WI[gi];
    }
    __syncthreads();

    const int kp  = tid & 15;       // k pair
    const int nn2 = tid >> 4;       // 0..15
    #pragma unroll
    for (int half = 0; half < 2; half++) {
        int n = nn2 + half * 16;
        int k = kp * 2;
        float r0 = tR[n][k],     r1 = tR[n][k + 1];
        float i0 = tI[n][k],     i1 = tI[n][k + 1];
        float s0 = r0 + i0,      s1 = r1 + i1;
        int oi = (n0 + n) * DM + k0 + k;

        __nv_bfloat16 h0, h1;
        h0 = __float2bfloat16(r0); h1 = __float2bfloat16(r1);
        *(__nv_bfloat162*)&g_WtR_hi[oi] = __nv_bfloat162(h0, h1);
        *(__nv_bfloat162*)&g_WtR_lo[oi] = __nv_bfloat162(
            __float2bfloat16(r0 - __bfloat162float(h0)),
            __float2bfloat16(r1 - __bfloat162float(h1)));

        h0 = __float2bfloat16(i0); h1 = __float2bfloat16(i1);
        *(__nv_bfloat162*)&g_WtI_hi[oi] = __nv_bfloat162(h0, h1);
        *(__nv_bfloat162*)&g_WtI_lo[oi] = __nv_bfloat162(
            __float2bfloat16(i0 - __bfloat162float(h0)),
            __float2bfloat16(i1 - __bfloat162float(h1)));

        h0 = __float2bfloat16(s0); h1 = __float2bfloat16(s1);
        *(__nv_bfloat162*)&g_WtS_hi[oi] = __nv_bfloat162(h0, h1);
        *(__nv_bfloat162*)&g_WtS_lo[oi] = __nv_bfloat162(
            __float2bfloat16(s0 - __bfloat162float(h0)),
            __float2bfloat16(s1 - __bfloat162float(h1)));
    }
}

// ---------------------------------------------------------------------------
// Kernel 4: Karatsuba bf16-split GEMM (mma.sync + ldmatrix + cp.async)
//   C1 = yr*WR, C2 = yi*WI, C3 = (yr+yi)*(WR+WI)
//   Re = C1 - C2 + bR;  Im = C3 - C1 - C2 + bI;  out = Re(log_cosh)
// grid (32, 4), 128 threads (2x2 warps of 32x32), 61440B dynamic smem.
// ---------------------------------------------------------------------------
__global__ void __launch_bounds__(128)
gemm_out_mma(const float* __restrict__ bR, const float* __restrict__ bI, int sb,
             float* __restrict__ out, int out_floats, int mode)
{
    extern __shared__ __align__(16) char smem[];
    const uint32_t sbase = smem_u32(smem);

    const int tid  = threadIdx.x;
    const int lane = tid & 31, wid = tid >> 5;
    const int g    = lane >> 2, tig = lane & 3;
    const int wm   = wid >> 1, wn = wid & 1;
    const int m0   = blockIdx.y * BM, n0 = blockIdx.x * BN;

    // ldmatrix per-lane address offsets (within a panel)
    const int a_row_off = (lane & 7) + ((lane >> 3) & 1) * 8;
    const int a_col_off = (lane >> 4) * 8;
    const int b_row_off = (lane & 7) + (lane >> 4) * 8;
    const int b_col_off = ((lane >> 3) & 1) * 8;

    float acc[3][2][4][4] = {};   // [chain][mm][nn][c]

    // cp.async tile issue: per thread 12 x 16B (6 panels x 2)
    const int row  = tid >> 1;        // 0..63
    const int half = tid & 1;

    auto issue_stage = [&](int t) {
        const int pass = t >> 6, kt = t & 63, k0 = kt * KC;
        const __nv_bfloat16* Ap[3];
        const __nv_bfloat16* Bp[3];
        Ap[0] = (pass < 2) ? g_Yr_hi : g_Yr_lo;
        Ap[1] = (pass < 2) ? g_Yi_hi : g_Yi_lo;
        Ap[2] = (pass < 2) ? g_Ys_hi : g_Ys_lo;
        Bp[0] = (pass == 1) ? g_WtR_lo : g_WtR_hi;
        Bp[1] = (pass == 1) ? g_WtI_lo : g_WtI_hi;
        Bp[2] = (pass == 1) ? g_WtS_lo : g_WtS_hi;
        const uint32_t sb_ = sbase + (t & 1) * STAGE;
        #pragma unroll
        for (int p = 0; p < 3; p++) {
            const __nv_bfloat16* ga = Ap[p] + (m0 + row) * DM + k0 + half * 16;
            uint32_t sa = sb_ + p * PANEL + row * 80 + half * 32;
            cpasync16(sa, ga);
            cpasync16(sa + 16, ga + 8);
            const __nv_bfloat16* gb = Bp[p] + (n0 + row) * DM + k0 + half * 16;
            uint32_t sbb = sb_ + (3 + p) * PANEL + row * 80 + half * 32;
            cpasync16(sbb, gb);
            cpasync16(sbb + 16, gb + 8);
        }
        cp_commit();
    };

    issue_stage(0);

    for (int t = 0; t < N_TILES; t++) {
        const int s = t & 1;
        if (t + 1 < N_TILES) { issue_stage(t + 1); cp_wait1(); }
        else                 { cp_wait0(); }
        __syncthreads();

        const uint32_t base = sbase + s * STAGE;
        #pragma unroll
        for (int kk = 0; kk < KC; kk += 16) {
            #pragma unroll
            for (int c = 0; c < 3; c++) {
                uint32_t a[2][4];
                #pragma unroll
                for (int mm = 0; mm < 2; mm++) {
                    int r0 = wm * 32 + mm * 16;
                    ldmx4(a[mm], base + c * PANEL +
                                 (r0 + a_row_off) * 80 + (kk + a_col_off) * 2);
                }
                uint32_t b[2][4];
                #pragma unroll
                for (int nb = 0; nb < 2; nb++) {
                    int nr = wn * 32 + nb * 16;
                    ldmx4(b[nb], base + (3 + c) * PANEL +
                                 (nr + b_row_off) * 80 + (kk + b_col_off) * 2);
                }
                #pragma unroll
                for (int mm = 0; mm < 2; mm++)
                    #pragma unroll
                    for (int nn = 0; nn < 4; nn++)
                        MMA_BF16(acc[c][mm][nn], a[mm],
                                 b[nn >> 1][(nn & 1) * 2],
                                 b[nn >> 1][(nn & 1) * 2 + 1]);
            }
        }
        __syncthreads();
    }

    // ------------------ epilogue: bias + log_cosh (real part) ---------------
    const float LN2 = 0.69314718055994531f;
    #pragma unroll
    for (int mm = 0; mm < 2; mm++) {
        #pragma unroll
        for (int nn = 0; nn < 4; nn++) {
            int mi = m0 + wm * 32 + mm * 16 + g;
            int ni = n0 + wn * 32 + nn * 8 + tig * 2;
            #pragma unroll
            for (int c = 0; c < 4; c++) {
                int m = mi + (c >> 1) * 8;
                int n = ni + (c & 1);
                float C1 = acc[0][mm][nn][c];
                float C2 = acc[1][mm][nn][c];
                float C3 = acc[2][mm][nn][c];
                float re = C1 - C2 + bR[clampi(n, sb)];
                float im = C3 - C1 - C2 + bI[clampi(n, sb)];
                float sgn = (__float_as_int(re) < 0) ? -1.0f : 1.0f;
                float a = re * sgn;
                float b = im * sgn;
                float e = expf(-2.0f * a);
                float s2, c2;
                __sincosf(2.0f * b, &s2, &c2);
                float wr = e * c2, wi = -e * s2;
                float u = 1.0f + wr;
                float res_re = a + 0.5f * logf(u * u + wi * wi) - LN2;
                if (mode == 0) {
                    int fi = m * DM + n;
                    if (fi < out_floats) out[fi] = res_re;
                } else {
                    float res_im = b + atan2f(wi, u);
                    int fi = (m * DM + n) * 2;
                    if (fi < out_floats)     out[fi]     = res_re;
                    if (fi + 1 < out_floats) out[fi + 1] = res_im;
                }
            }
        }
    }
}

// ---------------------------------------------------------------------------
extern "C" void kernel_launch(void* const* d_in, const int* in_sizes, int n_in,
                              void* d_out, int out_size)
{
    const float* x = nullptr;   int sx = 0;
    const float* vk[2] = {};    int svk = 0;
    const float* J[2]  = {};    int sj = 0;
    const float* wk[2] = {};    int swk = 0;
    const float* bs[4] = {};    int sb = 0;
    int nvk = 0, nj = 0, nwk = 0, nb = 0;

    for (int i = 0; i < n_in; i++) {
        const float* p = (const float*)d_in[i];
        int sz = in_sizes[i];
        if      (sz == 65536   && !x)      { x = p; sx = sz; }
        else if (sz == 524288  && nvk < 2) { vk[nvk++] = p; svk = sz; }
        else if (sz == 8192    && nj  < 2) { J[nj++]   = p; sj  = sz; }
        else if (sz == 4194304 && nwk < 2) { wk[nwk++] = p; swk = sz; }
        else if (sz == 2048    && nb  < 4) { bs[nb++]  = p; sb  = sz; }
    }

    if (!(x && nvk == 2 && nj == 2 && nwk == 2 && nb == 4)) {
        if (n_in < 11) return;
        x     = (const float*)d_in[0];  sx  = in_sizes[0];
        vk[0] = (const float*)d_in[1];  bs[0] = (const float*)d_in[2];
        vk[1] = (const float*)d_in[3];  bs[1] = (const float*)d_in[4];
        J[0]  = (const float*)d_in[5];  J[1]  = (const float*)d_in[6];
        wk[0] = (const float*)d_in[7];  bs[2] = (const float*)d_in[8];
        wk[1] = (const float*)d_in[9];  bs[3] = (const float*)d_in[10];
        svk = in_sizes[1]; sj = in_sizes[5]; swk = in_sizes[7]; sb = in_sizes[2];
    }

    int mode       = (out_size == 2 * P_ * DM) ? 1 : 0;
    int out_floats = out_size;

    static bool attr_done = false;
    if (!attr_done) {
        cudaFuncSetAttribute(gemm_out_mma,
                             cudaFuncAttributeMaxDynamicSharedMemorySize, SMEM_GEMM);
        attr_done = true;
    }

    gemm_v  <<<dim3(DM / 64, P_ / 64, 2), 256>>>(x, sx, vk[0], bs[0], vk[1], bs[1],
                                                 svk, sb);
    circ_att<<<dim3(P_ / 32, H_), 256>>>(J[0], J[1], sj);
    split_y <<<(P_ * DM + 255) / 256, 256>>>();
    split_wt<<<dim3(DM / 32, DM / 32), 256>>>(wk[0], wk[1], swk);
    gemm_out_mma<<<dim3(DM / BN, P_ / BM), 128, SMEM_GEMM>>>(
        bs[2], bs[3], sb, (float*)d_out, out_floats, mode);
}

// round 8
// speedup vs baseline: 1.0928x; 1.0928x over previous
#include <cuda_runtime.h>
#include <cuda_bf16.h>
#include <cstdint>

namespace {
constexpr int P_     = 256;
constexpr int H_     = 32;
constexpr int DM     = 2048;
constexpr int HD     = 64;
constexpr int PATCH_ = 256;

constexpr int BM = 64;
constexpr int BN = 64;
constexpr int KC = 64;                  // k per smem stage
constexpr int N_TILES = 3 * (DM / KC);  // 3 split passes x 32 = 96
constexpr int PADK  = 72;               // bf16 stride: 144B (conflict-free)
constexpr int PANEL = BM * PADK * 2;    // 9216 B
constexpr int STAGE = 6 * PANEL;        // 55296 B
constexpr int SMEM_GEMM = 2 * STAGE;    // 110592 B (dynamic)
}

// ------------------------- device scratch (static) -------------------------
__device__ float g_vr[P_ * DM];
__device__ float g_vi[P_ * DM];
__device__ float g_yr[P_ * DM];
__device__ float g_yi[P_ * DM];

__device__ __nv_bfloat16 g_Yr_hi[P_ * DM];
__device__ __nv_bfloat16 g_Yr_lo[P_ * DM];
__device__ __nv_bfloat16 g_Yi_hi[P_ * DM];
__device__ __nv_bfloat16 g_Yi_lo[P_ * DM];
__device__ __nv_bfloat16 g_Ys_hi[P_ * DM];
__device__ __nv_bfloat16 g_Ys_lo[P_ * DM];

__device__ __nv_bfloat16 g_WtR_hi[DM * DM];   // [n][k] = w0R_k[k][n]
__device__ __nv_bfloat16 g_WtR_lo[DM * DM];
__device__ __nv_bfloat16 g_WtI_hi[DM * DM];
__device__ __nv_bfloat16 g_WtI_lo[DM * DM];
__device__ __nv_bfloat16 g_WtS_hi[DM * DM];   // WR + WI
__device__ __nv_bfloat16 g_WtS_lo[DM * DM];

__device__ __forceinline__ int clampi(int i, int sz) { return i < sz ? i : sz - 1; }

// ------------------------- asm helpers -------------------------
__device__ __forceinline__ uint32_t smem_u32(const void* p) {
    uint32_t a;
    asm("{ .reg .u64 t; cvta.to.shared.u64 t, %1; cvt.u32.u64 %0, t; }"
        : "=r"(a) : "l"(p));
    return a;
}
__device__ __forceinline__ void cpasync16(uint32_t s, const void* g) {
    asm volatile("cp.async.cg.shared.global [%0], [%1], 16;" :: "r"(s), "l"(g));
}
__device__ __forceinline__ void cp_commit() { asm volatile("cp.async.commit_group;"); }
__device__ __forceinline__ void cp_wait1()  { asm volatile("cp.async.wait_group 1;"); }
__device__ __forceinline__ void cp_wait0()  { asm volatile("cp.async.wait_group 0;"); }
__device__ __forceinline__ void ldmx4(uint32_t* r, uint32_t addr) {
    asm volatile("ldmatrix.sync.aligned.m8n8.x4.shared.b16 {%0,%1,%2,%3}, [%4];"
                 : "=r"(r[0]), "=r"(r[1]), "=r"(r[2]), "=r"(r[3]) : "r"(addr));
}
#define MMA_BF16(d, a, b0_, b1_)                                               \
    asm volatile(                                                              \
        "mma.sync.aligned.m16n8k16.row.col.f32.bf16.bf16.f32 "                 \
        "{%0,%1,%2,%3}, {%4,%5,%6,%7}, {%8,%9}, {%0,%1,%2,%3};"                \
        : "+f"(d[0]), "+f"(d[1]), "+f"(d[2]), "+f"(d[3])                       \
        : "r"(a[0]), "r"(a[1]), "r"(a[2]), "r"(a[3]), "r"(b0_), "r"(b1_))

// ---------------------------------------------------------------------------
// Kernel 1: vr = x @ vR_k + vR_b ; vi = x @ vI_k + vI_b   (fp32)
// ---------------------------------------------------------------------------
__global__ void gemm_v(const float* __restrict__ x, int sx,
                       const float* __restrict__ Wr, const float* __restrict__ br,
                       const float* __restrict__ Wi, const float* __restrict__ bi,
                       int sw, int sb)
{
    constexpr int K = PATCH_, N = DM;
    const float* W = blockIdx.z ? Wi : Wr;
    const float* b = blockIdx.z ? bi : br;
    float* C       = blockIdx.z ? g_vi : g_vr;

    __shared__ __align__(16) float As[64][17];
    __shared__ __align__(16) float Bs[16][64];

    const int tid = threadIdx.x;
    const int tx = tid & 15, ty = tid >> 4;
    const int row0 = blockIdx.y * 64, col0 = blockIdx.x * 64;

    float acc[4][4] = {};

    for (int k0 = 0; k0 < K; k0 += 16) {
        #pragma unroll
        for (int l = 0; l < 4; l++) {
            int idx = tid + l * 256;
            As[idx >> 4][idx & 15] =
                x[clampi((row0 + (idx >> 4)) * K + k0 + (idx & 15), sx)];
        }
        #pragma unroll
        for (int l = 0; l < 4; l++) {
            int idx = tid + l * 256;
            Bs[idx >> 6][idx & 63] =
                W[clampi((k0 + (idx >> 6)) * N + col0 + (idx & 63), sw)];
        }
        __syncthreads();
        #pragma unroll
        for (int kk = 0; kk < 16; kk++) {
            float a[4];
            #pragma unroll
            for (int i = 0; i < 4; i++) a[i] = As[ty * 4 + i][kk];
            float4 bv = *(const float4*)&Bs[kk][tx * 4];
            float bb[4] = {bv.x, bv.y, bv.z, bv.w};
            #pragma unroll
            for (int i = 0; i < 4; i++)
                #pragma unroll
                for (int j = 0; j < 4; j++)
                    acc[i][j] = fmaf(a[i], bb[j], acc[i][j]);
        }
        __syncthreads();
    }

    #pragma unroll
    for (int i = 0; i < 4; i++) {
        int r = row0 + ty * 4 + i;
        #pragma unroll
        for (int j = 0; j < 4; j++) {
            int c = col0 + tx * 4 + j;
            C[r * N + c] = acc[i][j] + b[clampi(c, sb)];
        }
    }
}

// ---------------------------------------------------------------------------
// Kernel 2: circulant shift-attention (fp32) — R6 64-row tiling (known good)
// grid = (4 s-tiles, 32 heads), 256 threads. Block computes 64 s x 64 d.
// ---------------------------------------------------------------------------
__global__ void circ_att(const float* __restrict__ JR,
                         const float* __restrict__ JI, int sj)
{
    const int h  = blockIdx.y;
    const int s0 = blockIdx.x * 64;

    __shared__ __align__(16) float jr_s[512];
    __shared__ __align__(16) float ji_s[512];
    __shared__ __align__(16) float vr_s[64][64];
    __shared__ __align__(16) float vi_s[64][64];

    const int tid = threadIdx.x;
    const int tx = tid & 15, ty = tid >> 4;

    for (int t = tid; t < 512; t += 256) {
        int ji = clampi((t & 255) * H_ + h, sj);
        jr_s[t] = JR[ji];
        ji_s[t] = JI[ji];
    }

    float accR[4][4] = {}, accI[4][4] = {};

    for (int q0 = 0; q0 < P_; q0 += 64) {
        __syncthreads();
        #pragma unroll
        for (int l = 0; l < 16; l++) {
            int idx = tid + l * 256;
            int qq = idx >> 6, d = idx & 63;
            int gi = (q0 + qq) * DM + h * HD + d;
            vr_s[qq][d] = g_vr[gi];
            vi_s[qq][d] = g_vi[gi];
        }
        __syncthreads();

        #pragma unroll 4
        for (int kk = 0; kk < 64; kk++) {
            int q = q0 + kk;
            float jr[4], ji[4];
            #pragma unroll
            for (int i = 0; i < 4; i++) {
                jr[i] = jr_s[q + s0 + ty * 4 + i];
                ji[i] = ji_s[q + s0 + ty * 4 + i];
            }
            float4 vr4 = *(const float4*)&vr_s[kk][tx * 4];
            float4 vi4 = *(const float4*)&vi_s[kk][tx * 4];
            float vr[4] = {vr4.x, vr4.y, vr4.z, vr4.w};
            float vi[4] = {vi4.x, vi4.y, vi4.z, vi4.w};
            #pragma unroll
            for (int i = 0; i < 4; i++)
                #pragma unroll
                for (int j = 0; j < 4; j++) {
                    accR[i][j] = fmaf(jr[i], vr[j], accR[i][j]);
                    accR[i][j] = fmaf(-ji[i], vi[j], accR[i][j]);
                    accI[i][j] = fmaf(jr[i], vi[j], accI[i][j]);
                    accI[i][j] = fmaf(ji[i], vr[j], accI[i][j]);
                }
        }
    }

    #pragma unroll
    for (int i = 0; i < 4; i++) {
        int s = s0 + ty * 4 + i;
        #pragma unroll
        for (int j = 0; j < 4; j++) {
            int d = tx * 4 + j;
            g_yr[s * DM + h * HD + d] = accR[i][j];
            g_yi[s * DM + h * HD + d] = accI[i][j];
        }
    }
}

// ---------------------------------------------------------------------------
// Kernel 3a: split y (and ys = yr+yi) into bf16 hi/lo
// ---------------------------------------------------------------------------
__global__ void split_y()
{
    int i = blockIdx.x * 256 + threadIdx.x;
    if (i >= P_ * DM) return;
    float a = g_yr[i];
    float b = g_yi[i];
    float s = a + b;
    __nv_bfloat16 ha = __float2bfloat16(a);
    __nv_bfloat16 hb = __float2bfloat16(b);
    __nv_bfloat16 hs = __float2bfloat16(s);
    g_Yr_hi[i] = ha;  g_Yr_lo[i] = __float2bfloat16(a - __bfloat162float(ha));
    g_Yi_hi[i] = hb;  g_Yi_lo[i] = __float2bfloat16(b - __bfloat162float(hb));
    g_Ys_hi[i] = hs;  g_Ys_lo[i] = __float2bfloat16(s - __bfloat162float(hs));
}

// ---------------------------------------------------------------------------
// Kernel 3b: fused transpose + split of WR, WI, WR+WI -> 6 bf16 panels [n][k]
// grid (64, 64) 32x32 tiles, 256 threads. bf16x2 stores. (measured win in R7)
// ---------------------------------------------------------------------------
__global__ void split_wt(const float* __restrict__ WR,
                         const float* __restrict__ WI, int sw)
{
    __shared__ float tR[32][33];
    __shared__ float tI[32][33];
    const int tid = threadIdx.x;
    const int n0 = blockIdx.x * 32, k0 = blockIdx.y * 32;

    #pragma unroll
    for (int i = 0; i < 4; i++) {
        int idx = tid + i * 256;
        int kk = idx >> 5, nn = idx & 31;
        int gi = clampi((k0 + kk) * DM + n0 + nn, sw);
        tR[nn][kk] = WR[gi];
        tI[nn][kk] = WI[gi];
    }
    __syncthreads();

    const int kp  = tid & 15;
    const int nn2 = tid >> 4;
    #pragma unroll
    for (int half = 0; half < 2; half++) {
        int n = nn2 + half * 16;
        int k = kp * 2;
        float r0 = tR[n][k],     r1 = tR[n][k + 1];
        float i0 = tI[n][k],     i1 = tI[n][k + 1];
        float s0 = r0 + i0,      s1 = r1 + i1;
        int oi = (n0 + n) * DM + k0 + k;

        __nv_bfloat16 h0, h1;
        h0 = __float2bfloat16(r0); h1 = __float2bfloat16(r1);
        *(__nv_bfloat162*)&g_WtR_hi[oi] = __nv_bfloat162(h0, h1);
        *(__nv_bfloat162*)&g_WtR_lo[oi] = __nv_bfloat162(
            __float2bfloat16(r0 - __bfloat162float(h0)),
            __float2bfloat16(r1 - __bfloat162float(h1)));

        h0 = __float2bfloat16(i0); h1 = __float2bfloat16(i1);
        *(__nv_bfloat162*)&g_WtI_hi[oi] = __nv_bfloat162(h0, h1);
        *(__nv_bfloat162*)&g_WtI_lo[oi] = __nv_bfloat162(
            __float2bfloat16(i0 - __bfloat162float(h0)),
            __float2bfloat16(i1 - __bfloat162float(h1)));

        h0 = __float2bfloat16(s0); h1 = __float2bfloat16(s1);
        *(__nv_bfloat162*)&g_WtS_hi[oi] = __nv_bfloat162(h0, h1);
        *(__nv_bfloat162*)&g_WtS_lo[oi] = __nv_bfloat162(
            __float2bfloat16(s0 - __bfloat162float(h0)),
            __float2bfloat16(s1 - __bfloat162float(h1)));
    }
}

// ---------------------------------------------------------------------------
// Kernel 4: Karatsuba bf16-split GEMM, 256 threads (8 warps, 32x16 warp tile)
//   C1 = yr*WR, C2 = yi*WI, C3 = (yr+yi)*(WR+WI)
//   Re = C1 - C2 + bR;  Im = C3 - C1 - C2 + bI;  out = Re(log_cosh)
// grid (32, 4) = 128 CTAs, KC=64 stages (96 total), 110592B dynamic smem.
// ---------------------------------------------------------------------------
__global__ void __launch_bounds__(256)
gemm_out_mma(const float* __restrict__ bR, const float* __restrict__ bI, int sb,
             float* __restrict__ out, int out_floats, int mode)
{
    extern __shared__ __align__(16) char smem[];
    const uint32_t sbase = smem_u32(smem);

    const int tid  = threadIdx.x;
    const int lane = tid & 31, wid = tid >> 5;
    const int g    = lane >> 2, tig = lane & 3;
    const int wm   = wid >> 2, wn = wid & 3;     // 2 x 4 warp grid
    const int m0   = blockIdx.y * BM, n0 = blockIdx.x * BN;

    // ldmatrix per-lane offsets (within a panel, stride PADK*2 = 144B)
    const int a_row_off = (lane & 7) + ((lane >> 3) & 1) * 8;
    const int a_col_off = (lane >> 4) * 8;
    const int b_row_off = (lane & 7) + (lane >> 4) * 8;
    const int b_col_off = ((lane >> 3) & 1) * 8;

    float acc[3][2][2][4] = {};   // [chain][mm][nn][c]

    // cp.async: per stage 6 panels x 64 rows x 128B = 512 chunks/panel? no:
    // per panel 64 rows x 8 chunks(16B) = 512 chunks; 256 threads -> 2 each.
    const int ch_row0 = tid >> 2;            // chunk A: row 0..63
    const int ch_q0   = (tid & 3);           // q 0..3
    const int ch_q1   = (tid & 3) + 4;       // chunk B: q 4..7

    auto issue_stage = [&](int t) {
        const int pass = t >> 5, kt = t & 31, k0 = kt * KC;
        const __nv_bfloat16* Ap[3];
        const __nv_bfloat16* Bp[3];
        Ap[0] = (pass < 2) ? g_Yr_hi : g_Yr_lo;
        Ap[1] = (pass < 2) ? g_Yi_hi : g_Yi_lo;
        Ap[2] = (pass < 2) ? g_Ys_hi : g_Ys_lo;
        Bp[0] = (pass == 1) ? g_WtR_lo : g_WtR_hi;
        Bp[1] = (pass == 1) ? g_WtI_lo : g_WtI_hi;
        Bp[2] = (pass == 1) ? g_WtS_lo : g_WtS_hi;
        const uint32_t sb_ = sbase + (t & 1) * STAGE;
        #pragma unroll
        for (int p = 0; p < 3; p++) {
            const __nv_bfloat16* ga = Ap[p] + (m0 + ch_row0) * DM + k0;
            uint32_t sa = sb_ + p * PANEL + ch_row0 * 144;
            cpasync16(sa + ch_q0 * 16, ga + ch_q0 * 8);
            cpasync16(sa + ch_q1 * 16, ga + ch_q1 * 8);
            const __nv_bfloat16* gb = Bp[p] + (n0 + ch_row0) * DM + k0;
            uint32_t sbb = sb_ + (3 + p) * PANEL + ch_row0 * 144;
            cpasync16(sbb + ch_q0 * 16, gb + ch_q0 * 8);
            cpasync16(sbb + ch_q1 * 16, gb + ch_q1 * 8);
        }
        cp_commit();
    };

    issue_stage(0);

    for (int t = 0; t < N_TILES; t++) {
        const int s = t & 1;
        if (t + 1 < N_TILES) { issue_stage(t + 1); cp_wait1(); }
        else                 { cp_wait0(); }
        __syncthreads();

        const uint32_t base = sbase + s * STAGE;
        #pragma unroll
        for (int kk = 0; kk < KC; kk += 16) {
            #pragma unroll
            for (int c = 0; c < 3; c++) {
                uint32_t a[2][4];
                #pragma unroll
                for (int mm = 0; mm < 2; mm++) {
                    int r0 = wm * 32 + mm * 16;
                    ldmx4(a[mm], base + c * PANEL +
                                 (r0 + a_row_off) * 144 + (kk + a_col_off) * 2);
                }
                uint32_t b[4];
                {
                    int nr = wn * 16;
                    ldmx4(b, base + (3 + c) * PANEL +
                             (nr + b_row_off) * 144 + (kk + b_col_off) * 2);
                }
                #pragma unroll
                for (int mm = 0; mm < 2; mm++)
                    #pragma unroll
                    for (int nn = 0; nn < 2; nn++)
                        MMA_BF16(acc[c][mm][nn], a[mm], b[nn * 2], b[nn * 2 + 1]);
            }
        }
        __syncthreads();
    }

    // ------------------ epilogue: bias + log_cosh (real part) ---------------
    const float LN2 = 0.69314718055994531f;
    #pragma unroll
    for (int mm = 0; mm < 2; mm++) {
        #pragma unroll
        for (int nn = 0; nn < 2; nn++) {
            int mi = m0 + wm * 32 + mm * 16 + g;
            int ni = n0 + wn * 16 + nn * 8 + tig * 2;
            #pragma unroll
            for (int c = 0; c < 4; c++) {
                int m = mi + (c >> 1) * 8;
                int n = ni + (c & 1);
                float C1 = acc[0][mm][nn][c];
                float C2 = acc[1][mm][nn][c];
                float C3 = acc[2][mm][nn][c];
                float re = C1 - C2 + bR[clampi(n, sb)];
                float im = C3 - C1 - C2 + bI[clampi(n, sb)];
                float sgn = (__float_as_int(re) < 0) ? -1.0f : 1.0f;
                float a = re * sgn;
                float b = im * sgn;
                float e = expf(-2.0f * a);
                float s2, c2;
                __sincosf(2.0f * b, &s2, &c2);
                float wr = e * c2, wi = -e * s2;
                float u = 1.0f + wr;
                float res_re = a + 0.5f * logf(u * u + wi * wi) - LN2;
                if (mode == 0) {
                    int fi = m * DM + n;
                    if (fi < out_floats) out[fi] = res_re;
                } else {
                    float res_im = b + atan2f(wi, u);
                    int fi = (m * DM + n) * 2;
                    if (fi < out_floats)     out[fi]     = res_re;
                    if (fi + 1 < out_floats) out[fi + 1] = res_im;
                }
            }
        }
    }
}

// ---------------------------------------------------------------------------
extern "C" void kernel_launch(void* const* d_in, const int* in_sizes, int n_in,
                              void* d_out, int out_size)
{
    const float* x = nullptr;   int sx = 0;
    const float* vk[2] = {};    int svk = 0;
    const float* J[2]  = {};    int sj = 0;
    const float* wk[2] = {};    int swk = 0;
    const float* bs[4] = {};    int sb = 0;
    int nvk = 0, nj = 0, nwk = 0, nb = 0;

    for (int i = 0; i < n_in; i++) {
        const float* p = (const float*)d_in[i];
        int sz = in_sizes[i];
        if      (sz == 65536   && !x)      { x = p; sx = sz; }
        else if (sz == 524288  && nvk < 2) { vk[nvk++] = p; svk = sz; }
        else if (sz == 8192    && nj  < 2) { J[nj++]   = p; sj  = sz; }
        else if (sz == 4194304 && nwk < 2) { wk[nwk++] = p; swk = sz; }
        else if (sz == 2048    && nb  < 4) { bs[nb++]  = p; sb  = sz; }
    }

    if (!(x && nvk == 2 && nj == 2 && nwk == 2 && nb == 4)) {
        if (n_in < 11) return;
        x     = (const float*)d_in[0];  sx  = in_sizes[0];
        vk[0] = (const float*)d_in[1];  bs[0] = (const float*)d_in[2];
        vk[1] = (const float*)d_in[3];  bs[1] = (const float*)d_in[4];
        J[0]  = (const float*)d_in[5];  J[1]  = (const float*)d_in[6];
        wk[0] = (const float*)d_in[7];  bs[2] = (const float*)d_in[8];
        wk[1] = (const float*)d_in[9];  bs[3] = (const float*)d_in[10];
        svk = in_sizes[1]; sj = in_sizes[5]; swk = in_sizes[7]; sb = in_sizes[2];
    }

    int mode       = (out_size == 2 * P_ * DM) ? 1 : 0;
    int out_floats = out_size;

    static bool attr_done = false;
    if (!attr_done) {
        cudaFuncSetAttribute(gemm_out_mma,
                             cudaFuncAttributeMaxDynamicSharedMemorySize, SMEM_GEMM);
        attr_done = true;
    }

    gemm_v  <<<dim3(DM / 64, P_ / 64, 2), 256>>>(x, sx, vk[0], bs[0], vk[1], bs[1],
                                                 svk, sb);
    circ_att<<<dim3(P_ / 64, H_), 256>>>(J[0], J[1], sj);
    split_y <<<(P_ * DM + 255) / 256, 256>>>();
    split_wt<<<dim3(DM / 32, DM / 32), 256>>>(wk[0], wk[1], swk);
    gemm_out_mma<<<dim3(DM / BN, P_ / BM), 256, SMEM_GEMM>>>(
        bs[2], bs[3], sb, (float*)d_out, out_floats, mode);
}

// round 9
// speedup vs baseline: 1.1459x; 1.0486x over previous
#include <cuda_runtime.h>
#include <cuda_bf16.h>
#include <cstdint>

namespace {
constexpr int P_     = 256;
constexpr int H_     = 32;
constexpr int DM     = 2048;
constexpr int HD     = 64;
constexpr int PATCH_ = 256;

constexpr int BM = 64;
constexpr int BN = 64;
constexpr int KC = 64;                  // k per smem stage
constexpr int N_TILES  = 3 * (DM / KC);     // gemm_out: 96 stages
constexpr int NV_TILES = 3 * (PATCH_ / KC); // gemm_v:   12 stages
constexpr int PADK  = 72;               // bf16 stride: 144B (conflict-free)
constexpr int PANEL = BM * PADK * 2;    // 9216 B
constexpr int STAGE = 6 * PANEL;        // 55296 B (gemm_out: 6 panels)
constexpr int SMEM_GEMM = 2 * STAGE;    // 110592 B
constexpr int VSTAGE = 3 * PANEL;       // gemm_v: 3 panels (A shared)
constexpr int SMEM_V  = 2 * VSTAGE;     // 55296 B
}

// ------------------------- device scratch (static) -------------------------
__device__ float g_vr[P_ * DM];
__device__ float g_vi[P_ * DM];

__device__ __nv_bfloat16 g_X_hi[P_ * PATCH_];
__device__ __nv_bfloat16 g_X_lo[P_ * PATCH_];
__device__ __nv_bfloat16 g_VtR_hi[DM * PATCH_];   // [n][k] = vR_k[k][n]
__device__ __nv_bfloat16 g_VtR_lo[DM * PATCH_];
__device__ __nv_bfloat16 g_VtI_hi[DM * PATCH_];
__device__ __nv_bfloat16 g_VtI_lo[DM * PATCH_];

__device__ __nv_bfloat16 g_Yr_hi[P_ * DM];
__device__ __nv_bfloat16 g_Yr_lo[P_ * DM];
__device__ __nv_bfloat16 g_Yi_hi[P_ * DM];
__device__ __nv_bfloat16 g_Yi_lo[P_ * DM];
__device__ __nv_bfloat16 g_Ys_hi[P_ * DM];
__device__ __nv_bfloat16 g_Ys_lo[P_ * DM];

__device__ __nv_bfloat16 g_WtR_hi[DM * DM];   // [n][k] = w0R_k[k][n]
__device__ __nv_bfloat16 g_WtR_lo[DM * DM];
__device__ __nv_bfloat16 g_WtI_hi[DM * DM];
__device__ __nv_bfloat16 g_WtI_lo[DM * DM];
__device__ __nv_bfloat16 g_WtS_hi[DM * DM];   // WR + WI
__device__ __nv_bfloat16 g_WtS_lo[DM * DM];

__device__ __forceinline__ int clampi(int i, int sz) { return i < sz ? i : sz - 1; }

// ------------------------- asm helpers -------------------------
__device__ __forceinline__ uint32_t smem_u32(const void* p) {
    uint32_t a;
    asm("{ .reg .u64 t; cvta.to.shared.u64 t, %1; cvt.u32.u64 %0, t; }"
        : "=r"(a) : "l"(p));
    return a;
}
__device__ __forceinline__ void cpasync16(uint32_t s, const void* g) {
    asm volatile("cp.async.cg.shared.global [%0], [%1], 16;" :: "r"(s), "l"(g));
}
__device__ __forceinline__ void cp_commit() { asm volatile("cp.async.commit_group;"); }
__device__ __forceinline__ void cp_wait1()  { asm volatile("cp.async.wait_group 1;"); }
__device__ __forceinline__ void cp_wait0()  { asm volatile("cp.async.wait_group 0;"); }
__device__ __forceinline__ void ldmx4(uint32_t* r, uint32_t addr) {
    asm volatile("ldmatrix.sync.aligned.m8n8.x4.shared.b16 {%0,%1,%2,%3}, [%4];"
                 : "=r"(r[0]), "=r"(r[1]), "=r"(r[2]), "=r"(r[3]) : "r"(addr));
}
#define MMA_BF16(d, a, b0_, b1_)                                               \
    asm volatile(                                                              \
        "mma.sync.aligned.m16n8k16.row.col.f32.bf16.bf16.f32 "                 \
        "{%0,%1,%2,%3}, {%4,%5,%6,%7}, {%8,%9}, {%0,%1,%2,%3};"                \
        : "+f"(d[0]), "+f"(d[1]), "+f"(d[2]), "+f"(d[3])                       \
        : "r"(a[0]), "r"(a[1]), "r"(a[2]), "r"(a[3]), "r"(b0_), "r"(b1_))

// ---------------------------------------------------------------------------
// Kernel 0a: split x into bf16 hi/lo
// ---------------------------------------------------------------------------
__global__ void split_x(const float* __restrict__ x, int sx)
{
    int i = blockIdx.x * 256 + threadIdx.x;
    if (i >= P_ * PATCH_) return;
    float a = x[clampi(i, sx)];
    __nv_bfloat16 h = __float2bfloat16(a);
    g_X_hi[i] = h;
    g_X_lo[i] = __float2bfloat16(a - __bfloat162float(h));
}

// ---------------------------------------------------------------------------
// Kernel 0b: transpose + split vR_k, vI_k -> 4 bf16 panels [n][k]
// vK: [PATCH][DM] row-major. grid (DM/32=64, PATCH/32=8), 256 threads.
// ---------------------------------------------------------------------------
__global__ void split_vk(const float* __restrict__ VR,
                         const float* __restrict__ VI, int sv)
{
    __shared__ float tR[32][33];
    __shared__ float tI[32][33];
    const int tid = threadIdx.x;
    const int n0 = blockIdx.x * 32, k0 = blockIdx.y * 32;

    #pragma unroll
    for (int i = 0; i < 4; i++) {
        int idx = tid + i * 256;
        int kk = idx >> 5, nn = idx & 31;
        int gi = clampi((k0 + kk) * DM + n0 + nn, sv);
        tR[nn][kk] = VR[gi];
        tI[nn][kk] = VI[gi];
    }
    __syncthreads();

    const int kp  = tid & 15;
    const int nn2 = tid >> 4;
    #pragma unroll
    for (int half = 0; half < 2; half++) {
        int n = nn2 + half * 16;
        int k = kp * 2;
        float r0 = tR[n][k], r1 = tR[n][k + 1];
        float i0 = tI[n][k], i1 = tI[n][k + 1];
        int oi = (n0 + n) * PATCH_ + k0 + k;

        __nv_bfloat16 h0, h1;
        h0 = __float2bfloat16(r0); h1 = __float2bfloat16(r1);
        *(__nv_bfloat162*)&g_VtR_hi[oi] = __nv_bfloat162(h0, h1);
        *(__nv_bfloat162*)&g_VtR_lo[oi] = __nv_bfloat162(
            __float2bfloat16(r0 - __bfloat162float(h0)),
            __float2bfloat16(r1 - __bfloat162float(h1)));

        h0 = __float2bfloat16(i0); h1 = __float2bfloat16(i1);
        *(__nv_bfloat162*)&g_VtI_hi[oi] = __nv_bfloat162(h0, h1);
        *(__nv_bfloat162*)&g_VtI_lo[oi] = __nv_bfloat162(
            __float2bfloat16(i0 - __bfloat162float(h0)),
            __float2bfloat16(i1 - __bfloat162float(h1)));
    }
}

// ---------------------------------------------------------------------------
// Kernel 1: gemm_v via mma.sync split-bf16 (3-pass).
//   vr = x @ vR_k + br ; vi = x @ vI_k + bi   -> fp32 g_vr / g_vi
// grid (32, 4), 256 threads, warp tile 32x16. A panel (x) shared by chains.
// ---------------------------------------------------------------------------
__global__ void __launch_bounds__(256)
gemm_v_mma(const float* __restrict__ br, const float* __restrict__ bi, int sb)
{
    extern __shared__ __align__(16) char smem[];
    const uint32_t sbase = smem_u32(smem);

    const int tid  = threadIdx.x;
    const int lane = tid & 31, wid = tid >> 5;
    const int g    = lane >> 2, tig = lane & 3;
    const int wm   = wid >> 2, wn = wid & 3;
    const int m0   = blockIdx.y * BM, n0 = blockIdx.x * BN;

    const int a_row_off = (lane & 7) + ((lane >> 3) & 1) * 8;
    const int a_col_off = (lane >> 4) * 8;
    const int b_row_off = (lane & 7) + (lane >> 4) * 8;
    const int b_col_off = ((lane >> 3) & 1) * 8;

    float acc[2][2][2][4] = {};   // [chain][mm][nn][c]

    const int ch_row0 = tid >> 2;
    const int ch_q0   = (tid & 3);
    const int ch_q1   = (tid & 3) + 4;

    auto issue_stage = [&](int t) {
        const int pass = t >> 2, kt = t & 3, k0 = kt * KC;
        const __nv_bfloat16* Ap = (pass < 2) ? g_X_hi : g_X_lo;
        const __nv_bfloat16* B0 = (pass == 1) ? g_VtR_lo : g_VtR_hi;
        const __nv_bfloat16* B1 = (pass == 1) ? g_VtI_lo : g_VtI_hi;
        const uint32_t sb_ = sbase + (t & 1) * VSTAGE;
        {
            const __nv_bfloat16* ga = Ap + (m0 + ch_row0) * PATCH_ + k0;
            uint32_t sa = sb_ + ch_row0 * 144;
            cpasync16(sa + ch_q0 * 16, ga + ch_q0 * 8);
            cpasync16(sa + ch_q1 * 16, ga + ch_q1 * 8);
        }
        {
            const __nv_bfloat16* gb = B0 + (n0 + ch_row0) * PATCH_ + k0;
            uint32_t sbb = sb_ + PANEL + ch_row0 * 144;
            cpasync16(sbb + ch_q0 * 16, gb + ch_q0 * 8);
            cpasync16(sbb + ch_q1 * 16, gb + ch_q1 * 8);
        }
        {
            const __nv_bfloat16* gb = B1 + (n0 + ch_row0) * PATCH_ + k0;
            uint32_t sbb = sb_ + 2 * PANEL + ch_row0 * 144;
            cpasync16(sbb + ch_q0 * 16, gb + ch_q0 * 8);
            cpasync16(sbb + ch_q1 * 16, gb + ch_q1 * 8);
        }
        cp_commit();
    };

    issue_stage(0);

    for (int t = 0; t < NV_TILES; t++) {
        const int s = t & 1;
        if (t + 1 < NV_TILES) { issue_stage(t + 1); cp_wait1(); }
        else                  { cp_wait0(); }
        __syncthreads();

        const uint32_t base = sbase + s * VSTAGE;
        #pragma unroll
        for (int kk = 0; kk < KC; kk += 16) {
            uint32_t a[2][4];
            #pragma unroll
            for (int mm = 0; mm < 2; mm++) {
                int r0 = wm * 32 + mm * 16;
                ldmx4(a[mm], base + (r0 + a_row_off) * 144 + (kk + a_col_off) * 2);
            }
            #pragma unroll
            for (int c = 0; c < 2; c++) {
                uint32_t b[4];
                int nr = wn * 16;
                ldmx4(b, base + (1 + c) * PANEL +
                         (nr + b_row_off) * 144 + (kk + b_col_off) * 2);
                #pragma unroll
                for (int mm = 0; mm < 2; mm++)
                    #pragma unroll
                    for (int nn = 0; nn < 2; nn++)
                        MMA_BF16(acc[c][mm][nn], a[mm], b[nn * 2], b[nn * 2 + 1]);
            }
        }
        __syncthreads();
    }

    #pragma unroll
    for (int mm = 0; mm < 2; mm++) {
        #pragma unroll
        for (int nn = 0; nn < 2; nn++) {
            int mi = m0 + wm * 32 + mm * 16 + g;
            int ni = n0 + wn * 16 + nn * 8 + tig * 2;
            #pragma unroll
            for (int c = 0; c < 4; c++) {
                int m = mi + (c >> 1) * 8;
                int n = ni + (c & 1);
                g_vr[m * DM + n] = acc[0][mm][nn][c] + br[clampi(n, sb)];
                g_vi[m * DM + n] = acc[1][mm][nn][c] + bi[clampi(n, sb)];
            }
        }
    }
}

// ---------------------------------------------------------------------------
// Kernel 2: circulant shift-attention (fp32) + FUSED bf16 hi/lo split epilogue
// grid = (4 s-tiles, 32 heads), 256 threads. Block computes 64 s x 64 d.
// ---------------------------------------------------------------------------
__global__ void circ_att(const float* __restrict__ JR,
                         const float* __restrict__ JI, int sj)
{
    const int h  = blockIdx.y;
    const int s0 = blockIdx.x * 64;

    __shared__ __align__(16) float jr_s[512];
    __shared__ __align__(16) float ji_s[512];
    __shared__ __align__(16) float vr_s[64][64];
    __shared__ __align__(16) float vi_s[64][64];

    const int tid = threadIdx.x;
    const int tx = tid & 15, ty = tid >> 4;

    for (int t = tid; t < 512; t += 256) {
        int ji = clampi((t & 255) * H_ + h, sj);
        jr_s[t] = JR[ji];
        ji_s[t] = JI[ji];
    }

    float accR[4][4] = {}, accI[4][4] = {};

    for (int q0 = 0; q0 < P_; q0 += 64) {
        __syncthreads();
        #pragma unroll
        for (int l = 0; l < 16; l++) {
            int idx = tid + l * 256;
            int qq = idx >> 6, d = idx & 63;
            int gi = (q0 + qq) * DM + h * HD + d;
            vr_s[qq][d] = g_vr[gi];
            vi_s[qq][d] = g_vi[gi];
        }
        __syncthreads();

        #pragma unroll 4
        for (int kk = 0; kk < 64; kk++) {
            int q = q0 + kk;
            float jr[4], ji[4];
            #pragma unroll
            for (int i = 0; i < 4; i++) {
                jr[i] = jr_s[q + s0 + ty * 4 + i];
                ji[i] = ji_s[q + s0 + ty * 4 + i];
            }
            float4 vr4 = *(const float4*)&vr_s[kk][tx * 4];
            float4 vi4 = *(const float4*)&vi_s[kk][tx * 4];
            float vr[4] = {vr4.x, vr4.y, vr4.z, vr4.w};
            float vi[4] = {vi4.x, vi4.y, vi4.z, vi4.w};
            #pragma unroll
            for (int i = 0; i < 4; i++)
                #pragma unroll
                for (int j = 0; j < 4; j++) {
                    accR[i][j] = fmaf(jr[i], vr[j], accR[i][j]);
                    accR[i][j] = fmaf(-ji[i], vi[j], accR[i][j]);
                    accI[i][j] = fmaf(jr[i], vi[j], accI[i][j]);
                    accI[i][j] = fmaf(ji[i], vr[j], accI[i][j]);
                }
        }
    }

    // fused split epilogue: write 6 bf16 panels directly from registers
    #pragma unroll
    for (int i = 0; i < 4; i++) {
        int s = s0 + ty * 4 + i;
        #pragma unroll
        for (int j = 0; j < 4; j++) {
            int idx = s * DM + h * HD + tx * 4 + j;
            float a = accR[i][j];
            float b = accI[i][j];
            float sm = a + b;
            __nv_bfloat16 ha = __float2bfloat16(a);
            __nv_bfloat16 hb = __float2bfloat16(b);
            __nv_bfloat16 hs = __float2bfloat16(sm);
            g_Yr_hi[idx] = ha;
            g_Yr_lo[idx] = __float2bfloat16(a - __bfloat162float(ha));
            g_Yi_hi[idx] = hb;
            g_Yi_lo[idx] = __float2bfloat16(b - __bfloat162float(hb));
            g_Ys_hi[idx] = hs;
            g_Ys_lo[idx] = __float2bfloat16(sm - __bfloat162float(hs));
        }
    }
}

// ---------------------------------------------------------------------------
// Kernel 3: fused transpose + split of WR, WI, WR+WI -> 6 bf16 panels [n][k]
// ---------------------------------------------------------------------------
__global__ void split_wt(const float* __restrict__ WR,
                         const float* __restrict__ WI, int sw)
{
    __shared__ float tR[32][33];
    __shared__ float tI[32][33];
    const int tid = threadIdx.x;
    const int n0 = blockIdx.x * 32, k0 = blockIdx.y * 32;

    #pragma unroll
    for (int i = 0; i < 4; i++) {
        int idx = tid + i * 256;
        int kk = idx >> 5, nn = idx & 31;
        int gi = clampi((k0 + kk) * DM + n0 + nn, sw);
        tR[nn][kk] = WR[gi];
        tI[nn][kk] = WI[gi];
    }
    __syncthreads();

    const int kp  = tid & 15;
    const int nn2 = tid >> 4;
    #pragma unroll
    for (int half = 0; half < 2; half++) {
        int n = nn2 + half * 16;
        int k = kp * 2;
        float r0 = tR[n][k],     r1 = tR[n][k + 1];
        float i0 = tI[n][k],     i1 = tI[n][k + 1];
        float s0 = r0 + i0,      s1 = r1 + i1;
        int oi = (n0 + n) * DM + k0 + k;

        __nv_bfloat16 h0, h1;
        h0 = __float2bfloat16(r0); h1 = __float2bfloat16(r1);
        *(__nv_bfloat162*)&g_WtR_hi[oi] = __nv_bfloat162(h0, h1);
        *(__nv_bfloat162*)&g_WtR_lo[oi] = __nv_bfloat162(
            __float2bfloat16(r0 - __bfloat162float(h0)),
            __float2bfloat16(r1 - __bfloat162float(h1)));

        h0 = __float2bfloat16(i0); h1 = __float2bfloat16(i1);
        *(__nv_bfloat162*)&g_WtI_hi[oi] = __nv_bfloat162(h0, h1);
        *(__nv_bfloat162*)&g_WtI_lo[oi] = __nv_bfloat162(
            __float2bfloat16(i0 - __bfloat162float(h0)),
            __float2bfloat16(i1 - __bfloat162float(h1)));

        h0 = __float2bfloat16(s0); h1 = __float2bfloat16(s1);
        *(__nv_bfloat162*)&g_WtS_hi[oi] = __nv_bfloat162(h0, h1);
        *(__nv_bfloat162*)&g_WtS_lo[oi] = __nv_bfloat162(
            __float2bfloat16(s0 - __bfloat162float(h0)),
            __float2bfloat16(s1 - __bfloat162float(h1)));
    }
}

// ---------------------------------------------------------------------------
// Kernel 4: Karatsuba bf16-split GEMM, 256 threads (8 warps, 32x16 warp tile)
// ---------------------------------------------------------------------------
__global__ void __launch_bounds__(256)
gemm_out_mma(const float* __restrict__ bR, const float* __restrict__ bI, int sb,
             float* __restrict__ out, int out_floats, int mode)
{
    extern __shared__ __align__(16) char smem[];
    const uint32_t sbase = smem_u32(smem);

    const int tid  = threadIdx.x;
    const int lane = tid & 31, wid = tid >> 5;
    const int g    = lane >> 2, tig = lane & 3;
    const int wm   = wid >> 2, wn = wid & 3;
    const int m0   = blockIdx.y * BM, n0 = blockIdx.x * BN;

    const int a_row_off = (lane & 7) + ((lane >> 3) & 1) * 8;
    const int a_col_off = (lane >> 4) * 8;
    const int b_row_off = (lane & 7) + (lane >> 4) * 8;
    const int b_col_off = ((lane >> 3) & 1) * 8;

    float acc[3][2][2][4] = {};

    const int ch_row0 = tid >> 2;
    const int ch_q0   = (tid & 3);
    const int ch_q1   = (tid & 3) + 4;

    auto issue_stage = [&](int t) {
        const int pass = t >> 5, kt = t & 31, k0 = kt * KC;
        const __nv_bfloat16* Ap[3];
        const __nv_bfloat16* Bp[3];
        Ap[0] = (pass < 2) ? g_Yr_hi : g_Yr_lo;
        Ap[1] = (pass < 2) ? g_Yi_hi : g_Yi_lo;
        Ap[2] = (pass < 2) ? g_Ys_hi : g_Ys_lo;
        Bp[0] = (pass == 1) ? g_WtR_lo : g_WtR_hi;
        Bp[1] = (pass == 1) ? g_WtI_lo : g_WtI_hi;
        Bp[2] = (pass == 1) ? g_WtS_lo : g_WtS_hi;
        const uint32_t sb_ = sbase + (t & 1) * STAGE;
        #pragma unroll
        for (int p = 0; p < 3; p++) {
            const __nv_bfloat16* ga = Ap[p] + (m0 + ch_row0) * DM + k0;
            uint32_t sa = sb_ + p * PANEL + ch_row0 * 144;
            cpasync16(sa + ch_q0 * 16, ga + ch_q0 * 8);
            cpasync16(sa + ch_q1 * 16, ga + ch_q1 * 8);
            const __nv_bfloat16* gb = Bp[p] + (n0 + ch_row0) * DM + k0;
            uint32_t sbb = sb_ + (3 + p) * PANEL + ch_row0 * 144;
            cpasync16(sbb + ch_q0 * 16, gb + ch_q0 * 8);
            cpasync16(sbb + ch_q1 * 16, gb + ch_q1 * 8);
        }
        cp_commit();
    };

    issue_stage(0);

    for (int t = 0; t < N_TILES; t++) {
        const int s = t & 1;
        if (t + 1 < N_TILES) { issue_stage(t + 1); cp_wait1(); }
        else                 { cp_wait0(); }
        __syncthreads();

        const uint32_t base = sbase + s * STAGE;
        #pragma unroll
        for (int kk = 0; kk < KC; kk += 16) {
            #pragma unroll
            for (int c = 0; c < 3; c++) {
                uint32_t a[2][4];
                #pragma unroll
                for (int mm = 0; mm < 2; mm++) {
                    int r0 = wm * 32 + mm * 16;
                    ldmx4(a[mm], base + c * PANEL +
                                 (r0 + a_row_off) * 144 + (kk + a_col_off) * 2);
                }
                uint32_t b[4];
                {
                    int nr = wn * 16;
                    ldmx4(b, base + (3 + c) * PANEL +
                             (nr + b_row_off) * 144 + (kk + b_col_off) * 2);
                }
                #pragma unroll
                for (int mm = 0; mm < 2; mm++)
                    #pragma unroll
                    for (int nn = 0; nn < 2; nn++)
                        MMA_BF16(acc[c][mm][nn], a[mm], b[nn * 2], b[nn * 2 + 1]);
            }
        }
        __syncthreads();
    }

    const float LN2 = 0.69314718055994531f;
    #pragma unroll
    for (int mm = 0; mm < 2; mm++) {
        #pragma unroll
        for (int nn = 0; nn < 2; nn++) {
            int mi = m0 + wm * 32 + mm * 16 + g;
            int ni = n0 + wn * 16 + nn * 8 + tig * 2;
            #pragma unroll
            for (int c = 0; c < 4; c++) {
                int m = mi + (c >> 1) * 8;
                int n = ni + (c & 1);
                float C1 = acc[0][mm][nn][c];
                float C2 = acc[1][mm][nn][c];
                float C3 = acc[2][mm][nn][c];
                float re = C1 - C2 + bR[clampi(n, sb)];
                float im = C3 - C1 - C2 + bI[clampi(n, sb)];
                float sgn = (__float_as_int(re) < 0) ? -1.0f : 1.0f;
                float a = re * sgn;
                float b = im * sgn;
                float e = expf(-2.0f * a);
                float s2, c2;
                __sincosf(2.0f * b, &s2, &c2);
                float wr = e * c2, wi = -e * s2;
                float u = 1.0f + wr;
                float res_re = a + 0.5f * logf(u * u + wi * wi) - LN2;
                if (mode == 0) {
                    int fi = m * DM + n;
                    if (fi < out_floats) out[fi] = res_re;
                } else {
                    float res_im = b + atan2f(wi, u);
                    int fi = (m * DM + n) * 2;
                    if (fi < out_floats)     out[fi]     = res_re;
                    if (fi + 1 < out_floats) out[fi + 1] = res_im;
                }
            }
        }
    }
}

// ---------------------------------------------------------------------------
extern "C" void kernel_launch(void* const* d_in, const int* in_sizes, int n_in,
                              void* d_out, int out_size)
{
    const float* x = nullptr;   int sx = 0;
    const float* vk[2] = {};    int svk = 0;
    const float* J[2]  = {};    int sj = 0;
    const float* wk[2] = {};    int swk = 0;
    const float* bs[4] = {};    int sb = 0;
    int nvk = 0, nj = 0, nwk = 0, nb = 0;

    for (int i = 0; i < n_in; i++) {
        const float* p = (const float*)d_in[i];
        int sz = in_sizes[i];
        if      (sz == 65536   && !x)      { x = p; sx = sz; }
        else if (sz == 524288  && nvk < 2) { vk[nvk++] = p; svk = sz; }
        else if (sz == 8192    && nj  < 2) { J[nj++]   = p; sj  = sz; }
        else if (sz == 4194304 && nwk < 2) { wk[nwk++] = p; swk = sz; }
        else if (sz == 2048    && nb  < 4) { bs[nb++]  = p; sb  = sz; }
    }

    if (!(x && nvk == 2 && nj == 2 && nwk == 2 && nb == 4)) {
        if (n_in < 11) return;
        x     = (const float*)d_in[0];  sx  = in_sizes[0];
        vk[0] = (const float*)d_in[1];  bs[0] = (const float*)d_in[2];
        vk[1] = (const float*)d_in[3];  bs[1] = (const float*)d_in[4];
        J[0]  = (const float*)d_in[5];  J[1]  = (const float*)d_in[6];
        wk[0] = (const float*)d_in[7];  bs[2] = (const float*)d_in[8];
        wk[1] = (const float*)d_in[9];  bs[3] = (const float*)d_in[10];
        svk = in_sizes[1]; sj = in_sizes[5]; swk = in_sizes[7]; sb = in_sizes[2];
    }

    int mode       = (out_size == 2 * P_ * DM) ? 1 : 0;
    int out_floats = out_size;

    static bool attr_done = false;
    if (!attr_done) {
        cudaFuncSetAttribute(gemm_out_mma,
                             cudaFuncAttributeMaxDynamicSharedMemorySize, SMEM_GEMM);
        cudaFuncSetAttribute(gemm_v_mma,
                             cudaFuncAttributeMaxDynamicSharedMemorySize, SMEM_V);
        attr_done = true;
    }

    split_x   <<<(P_ * PATCH_ + 255) / 256, 256>>>(x, sx);
    split_vk  <<<dim3(DM / 32, PATCH_ / 32), 256>>>(vk[0], vk[1], svk);
    gemm_v_mma<<<dim3(DM / BN, P_ / BM), 256, SMEM_V>>>(bs[0], bs[1], sb);
    circ_att  <<<dim3(P_ / 64, H_), 256>>>(J[0], J[1], sj);
    split_wt  <<<dim3(DM / 32, DM / 32), 256>>>(wk[0], wk[1], swk);
    gemm_out_mma<<<dim3(DM / BN, P_ / BM), 256, SMEM_GEMM>>>(
        bs[2], bs[3], sb, (float*)d_out, out_floats, mode);
}

// round 10
// speedup vs baseline: 1.2135x; 1.0589x over previous
#include <cuda_runtime.h>
#include <cuda_bf16.h>
#include <cstdint>

namespace {
constexpr int P_     = 256;
constexpr int H_     = 32;
constexpr int DM     = 2048;
constexpr int HD     = 64;
constexpr int PATCH_ = 256;

constexpr int BM = 64;
constexpr int BN = 64;
constexpr int KC = 64;                  // k per smem stage
constexpr int N_TILES  = 3 * (DM / KC);     // gemm_out: 96 stages
constexpr int NV_TILES = 3 * (PATCH_ / KC); // gemm_v:   12 stages
constexpr int PADK  = 72;               // bf16 stride: 144B (conflict-free)
constexpr int PANEL = BM * PADK * 2;    // 9216 B
constexpr int STAGE = 6 * PANEL;        // 55296 B (gemm_out: 6 panels)
constexpr int SMEM_GEMM = 2 * STAGE;    // 110592 B
constexpr int VSTAGE = 3 * PANEL;       // gemm_v: 3 panels (A shared)
constexpr int SMEM_V  = 2 * VSTAGE;     // 55296 B

// circ_att_mma: B-only stages (A synthesized from circulant pair table)
constexpr int CPANEL = 64 * 144;        // 9216 B
constexpr int CSTAGE = 3 * CPANEL;      // 27648 B
constexpr int NC_TILES = 3 * (P_ / KC); // 3 passes x 4 k-tiles = 12
constexpr int SMEM_C  = 2 * CSTAGE + 6 * 512 * 4;  // 67584 B
}

// ------------------------- device scratch (static) -------------------------
__device__ float g_vr[P_ * DM];
__device__ float g_vi[P_ * DM];

__device__ __nv_bfloat16 g_X_hi[P_ * PATCH_];
__device__ __nv_bfloat16 g_X_lo[P_ * PATCH_];
__device__ __nv_bfloat16 g_VtR_hi[DM * PATCH_];   // [n][k] = vR_k[k][n]
__device__ __nv_bfloat16 g_VtR_lo[DM * PATCH_];
__device__ __nv_bfloat16 g_VtI_hi[DM * PATCH_];
__device__ __nv_bfloat16 g_VtI_lo[DM * PATCH_];

// vT panels for circ_att_mma: [n = h*64+d][q], stride P_
__device__ __nv_bfloat16 g_vTr_hi[DM * P_];
__device__ __nv_bfloat16 g_vTr_lo[DM * P_];
__device__ __nv_bfloat16 g_vTi_hi[DM * P_];
__device__ __nv_bfloat16 g_vTi_lo[DM * P_];
__device__ __nv_bfloat16 g_vTs_hi[DM * P_];
__device__ __nv_bfloat16 g_vTs_lo[DM * P_];

__device__ __nv_bfloat16 g_Yr_hi[P_ * DM];
__device__ __nv_bfloat16 g_Yr_lo[P_ * DM];
__device__ __nv_bfloat16 g_Yi_hi[P_ * DM];
__device__ __nv_bfloat16 g_Yi_lo[P_ * DM];
__device__ __nv_bfloat16 g_Ys_hi[P_ * DM];
__device__ __nv_bfloat16 g_Ys_lo[P_ * DM];

__device__ __nv_bfloat16 g_WtR_hi[DM * DM];   // [n][k] = w0R_k[k][n]
__device__ __nv_bfloat16 g_WtR_lo[DM * DM];
__device__ __nv_bfloat16 g_WtI_hi[DM * DM];
__device__ __nv_bfloat16 g_WtI_lo[DM * DM];
__device__ __nv_bfloat16 g_WtS_hi[DM * DM];   // WR + WI
__device__ __nv_bfloat16 g_WtS_lo[DM * DM];

__device__ __forceinline__ int clampi(int i, int sz) { return i < sz ? i : sz - 1; }

// ------------------------- asm helpers -------------------------
__device__ __forceinline__ uint32_t smem_u32(const void* p) {
    uint32_t a;
    asm("{ .reg .u64 t; cvta.to.shared.u64 t, %1; cvt.u32.u64 %0, t; }"
        : "=r"(a) : "l"(p));
    return a;
}
__device__ __forceinline__ void cpasync16(uint32_t s, const void* g) {
    asm volatile("cp.async.cg.shared.global [%0], [%1], 16;" :: "r"(s), "l"(g));
}
__device__ __forceinline__ void cp_commit() { asm volatile("cp.async.commit_group;"); }
__device__ __forceinline__ void cp_wait1()  { asm volatile("cp.async.wait_group 1;"); }
__device__ __forceinline__ void cp_wait0()  { asm volatile("cp.async.wait_group 0;"); }
__device__ __forceinline__ void ldmx4(uint32_t* r, uint32_t addr) {
    asm volatile("ldmatrix.sync.aligned.m8n8.x4.shared.b16 {%0,%1,%2,%3}, [%4];"
                 : "=r"(r[0]), "=r"(r[1]), "=r"(r[2]), "=r"(r[3]) : "r"(addr));
}
#define MMA_BF16(d, a, b0_, b1_)                                               \
    asm volatile(                                                              \
        "mma.sync.aligned.m16n8k16.row.col.f32.bf16.bf16.f32 "                 \
        "{%0,%1,%2,%3}, {%4,%5,%6,%7}, {%8,%9}, {%0,%1,%2,%3};"                \
        : "+f"(d[0]), "+f"(d[1]), "+f"(d[2]), "+f"(d[3])                       \
        : "r"(a[0]), "r"(a[1]), "r"(a[2]), "r"(a[3]), "r"(b0_), "r"(b1_))

__device__ __forceinline__ uint16_t bf_bits(__nv_bfloat16 h) {
    return *reinterpret_cast<uint16_t*>(&h);
}

// ---------------------------------------------------------------------------
// Kernel 0a: split x into bf16 hi/lo
// ---------------------------------------------------------------------------
__global__ void split_x(const float* __restrict__ x, int sx)
{
    int i = blockIdx.x * 256 + threadIdx.x;
    if (i >= P_ * PATCH_) return;
    float a = x[clampi(i, sx)];
    __nv_bfloat16 h = __float2bfloat16(a);
    g_X_hi[i] = h;
    g_X_lo[i] = __float2bfloat16(a - __bfloat162float(h));
}

// ---------------------------------------------------------------------------
// Kernel 0b: transpose + split vR_k, vI_k -> 4 bf16 panels [n][k]
// ---------------------------------------------------------------------------
__global__ void split_vk(const float* __restrict__ VR,
                         const float* __restrict__ VI, int sv)
{
    __shared__ float tR[32][33];
    __shared__ float tI[32][33];
    const int tid = threadIdx.x;
    const int n0 = blockIdx.x * 32, k0 = blockIdx.y * 32;

    #pragma unroll
    for (int i = 0; i < 4; i++) {
        int idx = tid + i * 256;
        int kk = idx >> 5, nn = idx & 31;
        int gi = clampi((k0 + kk) * DM + n0 + nn, sv);
        tR[nn][kk] = VR[gi];
        tI[nn][kk] = VI[gi];
    }
    __syncthreads();

    const int kp  = tid & 15;
    const int nn2 = tid >> 4;
    #pragma unroll
    for (int half = 0; half < 2; half++) {
        int n = nn2 + half * 16;
        int k = kp * 2;
        float r0 = tR[n][k], r1 = tR[n][k + 1];
        float i0 = tI[n][k], i1 = tI[n][k + 1];
        int oi = (n0 + n) * PATCH_ + k0 + k;

        __nv_bfloat16 h0, h1;
        h0 = __float2bfloat16(r0); h1 = __float2bfloat16(r1);
        *(__nv_bfloat162*)&g_VtR_hi[oi] = __nv_bfloat162(h0, h1);
        *(__nv_bfloat162*)&g_VtR_lo[oi] = __nv_bfloat162(
            __float2bfloat16(r0 - __bfloat162float(h0)),
            __float2bfloat16(r1 - __bfloat162float(h1)));

        h0 = __float2bfloat16(i0); h1 = __float2bfloat16(i1);
        *(__nv_bfloat162*)&g_VtI_hi[oi] = __nv_bfloat162(h0, h1);
        *(__nv_bfloat162*)&g_VtI_lo[oi] = __nv_bfloat162(
            __float2bfloat16(i0 - __bfloat162float(h0)),
            __float2bfloat16(i1 - __bfloat162float(h1)));
    }
}

// ---------------------------------------------------------------------------
// Kernel 1: gemm_v via mma.sync split-bf16 (3-pass). -> fp32 g_vr / g_vi
// ---------------------------------------------------------------------------
__global__ void __launch_bounds__(256)
gemm_v_mma(const float* __restrict__ br, const float* __restrict__ bi, int sb)
{
    extern __shared__ __align__(16) char smem[];
    const uint32_t sbase = smem_u32(smem);

    const int tid  = threadIdx.x;
    const int lane = tid & 31, wid = tid >> 5;
    const int g    = lane >> 2, tig = lane & 3;
    const int wm   = wid >> 2, wn = wid & 3;
    const int m0   = blockIdx.y * BM, n0 = blockIdx.x * BN;

    const int a_row_off = (lane & 7) + ((lane >> 3) & 1) * 8;
    const int a_col_off = (lane >> 4) * 8;
    const int b_row_off = (lane & 7) + (lane >> 4) * 8;
    const int b_col_off = ((lane >> 3) & 1) * 8;

    float acc[2][2][2][4] = {};

    const int ch_row0 = tid >> 2;
    const int ch_q0   = (tid & 3);
    const int ch_q1   = (tid & 3) + 4;

    auto issue_stage = [&](int t) {
        const int pass = t >> 2, kt = t & 3, k0 = kt * KC;
        const __nv_bfloat16* Ap = (pass < 2) ? g_X_hi : g_X_lo;
        const __nv_bfloat16* B0 = (pass == 1) ? g_VtR_lo : g_VtR_hi;
        const __nv_bfloat16* B1 = (pass == 1) ? g_VtI_lo : g_VtI_hi;
        const uint32_t sb_ = sbase + (t & 1) * VSTAGE;
        {
            const __nv_bfloat16* ga = Ap + (m0 + ch_row0) * PATCH_ + k0;
            uint32_t sa = sb_ + ch_row0 * 144;
            cpasync16(sa + ch_q0 * 16, ga + ch_q0 * 8);
            cpasync16(sa + ch_q1 * 16, ga + ch_q1 * 8);
        }
        {
            const __nv_bfloat16* gb = B0 + (n0 + ch_row0) * PATCH_ + k0;
            uint32_t sbb = sb_ + PANEL + ch_row0 * 144;
            cpasync16(sbb + ch_q0 * 16, gb + ch_q0 * 8);
            cpasync16(sbb + ch_q1 * 16, gb + ch_q1 * 8);
        }
        {
            const __nv_bfloat16* gb = B1 + (n0 + ch_row0) * PATCH_ + k0;
            uint32_t sbb = sb_ + 2 * PANEL + ch_row0 * 144;
            cpasync16(sbb + ch_q0 * 16, gb + ch_q0 * 8);
            cpasync16(sbb + ch_q1 * 16, gb + ch_q1 * 8);
        }
        cp_commit();
    };

    issue_stage(0);

    for (int t = 0; t < NV_TILES; t++) {
        const int s = t & 1;
        if (t + 1 < NV_TILES) { issue_stage(t + 1); cp_wait1(); }
        else                  { cp_wait0(); }
        __syncthreads();

        const uint32_t base = sbase + s * VSTAGE;
        #pragma unroll
        for (int kk = 0; kk < KC; kk += 16) {
            uint32_t a[2][4];
            #pragma unroll
            for (int mm = 0; mm < 2; mm++) {
                int r0 = wm * 32 + mm * 16;
                ldmx4(a[mm], base + (r0 + a_row_off) * 144 + (kk + a_col_off) * 2);
            }
            #pragma unroll
            for (int c = 0; c < 2; c++) {
                uint32_t b[4];
                int nr = wn * 16;
                ldmx4(b, base + (1 + c) * PANEL +
                         (nr + b_row_off) * 144 + (kk + b_col_off) * 2);
                #pragma unroll
                for (int mm = 0; mm < 2; mm++)
                    #pragma unroll
                    for (int nn = 0; nn < 2; nn++)
                        MMA_BF16(acc[c][mm][nn], a[mm], b[nn * 2], b[nn * 2 + 1]);
            }
        }
        __syncthreads();
    }

    #pragma unroll
    for (int mm = 0; mm < 2; mm++) {
        #pragma unroll
        for (int nn = 0; nn < 2; nn++) {
            int mi = m0 + wm * 32 + mm * 16 + g;
            int ni = n0 + wn * 16 + nn * 8 + tig * 2;
            #pragma unroll
            for (int c = 0; c < 4; c++) {
                int m = mi + (c >> 1) * 8;
                int n = ni + (c & 1);
                g_vr[m * DM + n] = acc[0][mm][nn][c] + br[clampi(n, sb)];
                g_vi[m * DM + n] = acc[1][mm][nn][c] + bi[clampi(n, sb)];
            }
        }
    }
}

// ---------------------------------------------------------------------------
// Kernel 2a: transpose + split v -> 6 bf16 panels vT[n][q] (stride P_)
// grid (DM/32=64, P_/32=8), 256 threads.
// ---------------------------------------------------------------------------
__global__ void split_vt()
{
    __shared__ float tR[32][33];
    __shared__ float tI[32][33];
    const int tid = threadIdx.x;
    const int n0 = blockIdx.x * 32, q0 = blockIdx.y * 32;

    #pragma unroll
    for (int i = 0; i < 4; i++) {
        int idx = tid + i * 256;
        int qq = idx >> 5, nn = idx & 31;
        int gi = (q0 + qq) * DM + n0 + nn;   // provably in-bounds
        tR[nn][qq] = g_vr[gi];
        tI[nn][qq] = g_vi[gi];
    }
    __syncthreads();

    const int qp  = tid & 15;
    const int nn2 = tid >> 4;
    #pragma unroll
    for (int half = 0; half < 2; half++) {
        int n = nn2 + half * 16;
        int q = qp * 2;
        float r0 = tR[n][q],     r1 = tR[n][q + 1];
        float i0 = tI[n][q],     i1 = tI[n][q + 1];
        float s0 = r0 + i0,      s1 = r1 + i1;
        int oi = (n0 + n) * P_ + q0 + q;

        __nv_bfloat16 h0, h1;
        h0 = __float2bfloat16(r0); h1 = __float2bfloat16(r1);
        *(__nv_bfloat162*)&g_vTr_hi[oi] = __nv_bfloat162(h0, h1);
        *(__nv_bfloat162*)&g_vTr_lo[oi] = __nv_bfloat162(
            __float2bfloat16(r0 - __bfloat162float(h0)),
            __float2bfloat16(r1 - __bfloat162float(h1)));

        h0 = __float2bfloat16(i0); h1 = __float2bfloat16(i1);
        *(__nv_bfloat162*)&g_vTi_hi[oi] = __nv_bfloat162(h0, h1);
        *(__nv_bfloat162*)&g_vTi_lo[oi] = __nv_bfloat162(
            __float2bfloat16(i0 - __bfloat162float(h0)),
            __float2bfloat16(i1 - __bfloat162float(h1)));

        h0 = __float2bfloat16(s0); h1 = __float2bfloat16(s1);
        *(__nv_bfloat162*)&g_vTs_hi[oi] = __nv_bfloat162(h0, h1);
        *(__nv_bfloat162*)&g_vTs_lo[oi] = __nv_bfloat162(
            __float2bfloat16(s0 - __bfloat162float(h0)),
            __float2bfloat16(s1 - __bfloat162float(h1)));
    }
}

// ---------------------------------------------------------------------------
// Kernel 2b: circulant attention via mma.sync.
//   A[s][q] = J[(s+q) % 256] — synthesized from smem pair table (circulant).
//   B = vT[h*64+d][q].  Karatsuba: C1=Jr*vr, C2=Ji*vi, C3=Js*vs.
//   yr = C1-C2, yi = C3-C1-C2. Epilogue writes 6 Y split panels.
// grid (P_/64=4, H=32), 256 threads (8 warps: wm in {0,1} x wn in {0..3}).
// ---------------------------------------------------------------------------
__global__ void __launch_bounds__(256)
circ_att_mma(const float* __restrict__ JR, const float* __restrict__ JI, int sj)
{
    extern __shared__ __align__(16) char smem[];
    const uint32_t sbase = smem_u32(smem);
    uint32_t* pair = (uint32_t*)(smem + 2 * CSTAGE);   // [6][512]

    const int tid  = threadIdx.x;
    const int lane = tid & 31, wid = tid >> 5;
    const int g    = lane >> 2, tig = lane & 3;
    const int wm   = wid >> 2, wn = wid & 3;
    const int h    = blockIdx.y;
    const int s0   = blockIdx.x * 64;

    const int b_row_off = (lane & 7) + (lane >> 4) * 8;
    const int b_col_off = ((lane >> 3) & 1) * 8;

    // build circulant pair tables: pair[v][t] = (J2v[t], J2v[t+1])
    for (int t = tid; t < 512; t += 256) {
        float jr0 = JR[clampi(((t) & 255) * H_ + h, sj)];
        float jr1 = JR[clampi(((t + 1) & 255) * H_ + h, sj)];
        float ji0 = JI[clampi(((t) & 255) * H_ + h, sj)];
        float ji1 = JI[clampi(((t + 1) & 255) * H_ + h, sj)];
        float v0[3] = {jr0, ji0, jr0 + ji0};
        float v1[3] = {jr1, ji1, jr1 + ji1};
        #pragma unroll
        for (int c = 0; c < 3; c++) {
            __nv_bfloat16 h0 = __float2bfloat16(v0[c]);
            __nv_bfloat16 h1 = __float2bfloat16(v1[c]);
            __nv_bfloat16 l0 = __float2bfloat16(v0[c] - __bfloat162float(h0));
            __nv_bfloat16 l1 = __float2bfloat16(v1[c] - __bfloat162float(h1));
            pair[(c * 2 + 0) * 512 + t] =
                (uint32_t)bf_bits(h0) | ((uint32_t)bf_bits(h1) << 16);
            pair[(c * 2 + 1) * 512 + t] =
                (uint32_t)bf_bits(l0) | ((uint32_t)bf_bits(l1) << 16);
        }
    }

    float acc[3][2][2][4] = {};

    const int ch_row0 = tid >> 2;
    const int ch_q0   = (tid & 3);
    const int ch_q1   = (tid & 3) + 4;

    auto issue_stage = [&](int t) {
        const int pass = t >> 2, kt = t & 3, k0 = kt * KC;
        const __nv_bfloat16* Bp[3];
        Bp[0] = (pass == 1) ? g_vTr_lo : g_vTr_hi;
        Bp[1] = (pass == 1) ? g_vTi_lo : g_vTi_hi;
        Bp[2] = (pass == 1) ? g_vTs_lo : g_vTs_hi;
        const uint32_t sb_ = sbase + (t & 1) * CSTAGE;
        #pragma unroll
        for (int c = 0; c < 3; c++) {
            const __nv_bfloat16* gb = Bp[c] + (h * HD + ch_row0) * P_ + k0;
            uint32_t s = sb_ + c * CPANEL + ch_row0 * 144;
            cpasync16(s + ch_q0 * 16, gb + ch_q0 * 8);
            cpasync16(s + ch_q1 * 16, gb + ch_q1 * 8);
        }
        cp_commit();
    };

    __syncthreads();   // pair table ready before mainloop reads it
    issue_stage(0);

    for (int t = 0; t < NC_TILES; t++) {
        const int s = t & 1;
        if (t + 1 < NC_TILES) { issue_stage(t + 1); cp_wait1(); }
        else                  { cp_wait0(); }
        __syncthreads();

        const uint32_t base = sbase + s * CSTAGE;
        const int pass = t >> 2, kt = t & 3;
        const int aoff = (pass < 2) ? 0 : 1;     // A hi for passes 0,1; lo for 2
        #pragma unroll
        for (int kk = 0; kk < KC; kk += 16) {
            const int tbase = s0 + wm * 32 + g + kt * 64 + kk + tig * 2;
            #pragma unroll
            for (int c = 0; c < 3; c++) {
                const uint32_t* Pt = &pair[(c * 2 + aoff) * 512];
                uint32_t u0 = Pt[tbase],      u1 = Pt[tbase + 8];
                uint32_t u2 = Pt[tbase + 16], u3 = Pt[tbase + 24];
                uint32_t u4 = Pt[tbase + 32];
                uint32_t a0[4] = {u0, u1, u1, u2};
                uint32_t a1[4] = {u2, u3, u3, u4};
                uint32_t b[4];
                ldmx4(b, base + c * CPANEL +
                         (wn * 16 + b_row_off) * 144 + (kk + b_col_off) * 2);
                MMA_BF16(acc[c][0][0], a0, b[0], b[1]);
                MMA_BF16(acc[c][0][1], a0, b[2], b[3]);
                MMA_BF16(acc[c][1][0], a1, b[0], b[1]);
                MMA_BF16(acc[c][1][1], a1, b[2], b[3]);
            }
        }
        __syncthreads();
    }

    // epilogue: Karatsuba combine + split write of 6 Y panels
    #pragma unroll
    for (int mm = 0; mm < 2; mm++) {
        #pragma unroll
        for (int nn = 0; nn < 2; nn++) {
            #pragma unroll
            for (int c2 = 0; c2 < 4; c2++) {
                int m = s0 + wm * 32 + mm * 16 + g + (c2 >> 1) * 8;
                int n = h * HD + wn * 16 + nn * 8 + tig * 2 + (c2 & 1);
                float C1 = acc[0][mm][nn][c2];
                float C2 = acc[1][mm][nn][c2];
                float C3 = acc[2][mm][nn][c2];
                float a  = C1 - C2;
                float b  = C3 - C1 - C2;
                float sm = a + b;
                int idx = m * DM + n;
                __nv_bfloat16 ha = __float2bfloat16(a);
                __nv_bfloat16 hb = __float2bfloat16(b);
                __nv_bfloat16 hs = __float2bfloat16(sm);
                g_Yr_hi[idx] = ha;
                g_Yr_lo[idx] = __float2bfloat16(a - __bfloat162float(ha));
                g_Yi_hi[idx] = hb;
                g_Yi_lo[idx] = __float2bfloat16(b - __bfloat162float(hb));
                g_Ys_hi[idx] = hs;
                g_Ys_lo[idx] = __float2bfloat16(sm - __bfloat162float(hs));
            }
        }
    }
}

// ---------------------------------------------------------------------------
// Kernel 3: fused transpose + split of WR, WI, WR+WI -> 6 bf16 panels [n][k]
// ---------------------------------------------------------------------------
__global__ void split_wt(const float* __restrict__ WR,
                         const float* __restrict__ WI, int sw)
{
    __shared__ float tR[32][33];
    __shared__ float tI[32][33];
    const int tid = threadIdx.x;
    const int n0 = blockIdx.x * 32, k0 = blockIdx.y * 32;

    #pragma unroll
    for (int i = 0; i < 4; i++) {
        int idx = tid + i * 256;
        int kk = idx >> 5, nn = idx & 31;
        int gi = clampi((k0 + kk) * DM + n0 + nn, sw);
        tR[nn][kk] = WR[gi];
        tI[nn][kk] = WI[gi];
    }
    __syncthreads();

    const int kp  = tid & 15;
    const int nn2 = tid >> 4;
    #pragma unroll
    for (int half = 0; half < 2; half++) {
        int n = nn2 + half * 16;
        int k = kp * 2;
        float r0 = tR[n][k],     r1 = tR[n][k + 1];
        float i0 = tI[n][k],     i1 = tI[n][k + 1];
        float s0 = r0 + i0,      s1 = r1 + i1;
        int oi = (n0 + n) * DM + k0 + k;

        __nv_bfloat16 h0, h1;
        h0 = __float2bfloat16(r0); h1 = __float2bfloat16(r1);
        *(__nv_bfloat162*)&g_WtR_hi[oi] = __nv_bfloat162(h0, h1);
        *(__nv_bfloat162*)&g_WtR_lo[oi] = __nv_bfloat162(
            __float2bfloat16(r0 - __bfloat162float(h0)),
            __float2bfloat16(r1 - __bfloat162float(h1)));

        h0 = __float2bfloat16(i0); h1 = __float2bfloat16(i1);
        *(__nv_bfloat162*)&g_WtI_hi[oi] = __nv_bfloat162(h0, h1);
        *(__nv_bfloat162*)&g_WtI_lo[oi] = __nv_bfloat162(
            __float2bfloat16(i0 - __bfloat162float(h0)),
            __float2bfloat16(i1 - __bfloat162float(h1)));

        h0 = __float2bfloat16(s0); h1 = __float2bfloat16(s1);
        *(__nv_bfloat162*)&g_WtS_hi[oi] = __nv_bfloat162(h0, h1);
        *(__nv_bfloat162*)&g_WtS_lo[oi] = __nv_bfloat162(
            __float2bfloat16(s0 - __bfloat162float(h0)),
            __float2bfloat16(s1 - __bfloat162float(h1)));
    }
}

// ---------------------------------------------------------------------------
// Kernel 4: Karatsuba bf16-split GEMM, 256 threads (8 warps, 32x16 warp tile)
// ---------------------------------------------------------------------------
__global__ void __launch_bounds__(256)
gemm_out_mma(const float* __restrict__ bR, const float* __restrict__ bI, int sb,
             float* __restrict__ out, int out_floats, int mode)
{
    extern __shared__ __align__(16) char smem[];
    const uint32_t sbase = smem_u32(smem);

    const int tid  = threadIdx.x;
    const int lane = tid & 31, wid = tid >> 5;
    const int g    = lane >> 2, tig = lane & 3;
    const int wm   = wid >> 2, wn = wid & 3;
    const int m0   = blockIdx.y * BM, n0 = blockIdx.x * BN;

    const int a_row_off = (lane & 7) + ((lane >> 3) & 1) * 8;
    const int a_col_off = (lane >> 4) * 8;
    const int b_row_off = (lane & 7) + (lane >> 4) * 8;
    const int b_col_off = ((lane >> 3) & 1) * 8;

    float acc[3][2][2][4] = {};

    const int ch_row0 = tid >> 2;
    const int ch_q0   = (tid & 3);
    const int ch_q1   = (tid & 3) + 4;

    auto issue_stage = [&](int t) {
        const int pass = t >> 5, kt = t & 31, k0 = kt * KC;
        const __nv_bfloat16* Ap[3];
        const __nv_bfloat16* Bp[3];
        Ap[0] = (pass < 2) ? g_Yr_hi : g_Yr_lo;
        Ap[1] = (pass < 2) ? g_Yi_hi : g_Yi_lo;
        Ap[2] = (pass < 2) ? g_Ys_hi : g_Ys_lo;
        Bp[0] = (pass == 1) ? g_WtR_lo : g_WtR_hi;
        Bp[1] = (pass == 1) ? g_WtI_lo : g_WtI_hi;
        Bp[2] = (pass == 1) ? g_WtS_lo : g_WtS_hi;
        const uint32_t sb_ = sbase + (t & 1) * STAGE;
        #pragma unroll
        for (int p = 0; p < 3; p++) {
            const __nv_bfloat16* ga = Ap[p] + (m0 + ch_row0) * DM + k0;
            uint32_t sa = sb_ + p * PANEL + ch_row0 * 144;
            cpasync16(sa + ch_q0 * 16, ga + ch_q0 * 8);
            cpasync16(sa + ch_q1 * 16, ga + ch_q1 * 8);
            const __nv_bfloat16* gb = Bp[p] + (n0 + ch_row0) * DM + k0;
            uint32_t sbb = sb_ + (3 + p) * PANEL + ch_row0 * 144;
            cpasync16(sbb + ch_q0 * 16, gb + ch_q0 * 8);
            cpasync16(sbb + ch_q1 * 16, gb + ch_q1 * 8);
        }
        cp_commit();
    };

    issue_stage(0);

    for (int t = 0; t < N_TILES; t++) {
        const int s = t & 1;
        if (t + 1 < N_TILES) { issue_stage(t + 1); cp_wait1(); }
        else                 { cp_wait0(); }
        __syncthreads();

        const uint32_t base = sbase + s * STAGE;
        #pragma unroll
        for (int kk = 0; kk < KC; kk += 16) {
            #pragma unroll
            for (int c = 0; c < 3; c++) {
                uint32_t a[2][4];
                #pragma unroll
                for (int mm = 0; mm < 2; mm++) {
                    int r0 = wm * 32 + mm * 16;
                    ldmx4(a[mm], base + c * PANEL +
                                 (r0 + a_row_off) * 144 + (kk + a_col_off) * 2);
                }
                uint32_t b[4];
                {
                    int nr = wn * 16;
                    ldmx4(b, base + (3 + c) * PANEL +
                             (nr + b_row_off) * 144 + (kk + b_col_off) * 2);
                }
                #pragma unroll
                for (int mm = 0; mm < 2; mm++)
                    #pragma unroll
                    for (int nn = 0; nn < 2; nn++)
                        MMA_BF16(acc[c][mm][nn], a[mm], b[nn * 2], b[nn * 2 + 1]);
            }
        }
        __syncthreads();
    }

    const float LN2 = 0.69314718055994531f;
    #pragma unroll
    for (int mm = 0; mm < 2; mm++) {
        #pragma unroll
        for (int nn = 0; nn < 2; nn++) {
            int mi = m0 + wm * 32 + mm * 16 + g;
            int ni = n0 + wn * 16 + nn * 8 + tig * 2;
            #pragma unroll
            for (int c = 0; c < 4; c++) {
                int m = mi + (c >> 1) * 8;
                int n = ni + (c & 1);
                float C1 = acc[0][mm][nn][c];
                float C2 = acc[1][mm][nn][c];
                float C3 = acc[2][mm][nn][c];
                float re = C1 - C2 + bR[clampi(n, sb)];
                float im = C3 - C1 - C2 + bI[clampi(n, sb)];
                float sgn = (__float_as_int(re) < 0) ? -1.0f : 1.0f;
                float a = re * sgn;
                float b = im * sgn;
                float e = expf(-2.0f * a);
                float s2, c2;
                __sincosf(2.0f * b, &s2, &c2);
                float wr = e * c2, wi = -e * s2;
                float u = 1.0f + wr;
                float res_re = a + 0.5f * logf(u * u + wi * wi) - LN2;
                if (mode == 0) {
                    int fi = m * DM + n;
                    if (fi < out_floats) out[fi] = res_re;
                } else {
                    float res_im = b + atan2f(wi, u);
                    int fi = (m * DM + n) * 2;
                    if (fi < out_floats)     out[fi]     = res_re;
                    if (fi + 1 < out_floats) out[fi + 1] = res_im;
                }
            }
        }
    }
}

// ---------------------------------------------------------------------------
extern "C" void kernel_launch(void* const* d_in, const int* in_sizes, int n_in,
                              void* d_out, int out_size)
{
    const float* x = nullptr;   int sx = 0;
    const float* vk[2] = {};    int svk = 0;
    const float* J[2]  = {};    int sj = 0;
    const float* wk[2] = {};    int swk = 0;
    const float* bs[4] = {};    int sb = 0;
    int nvk = 0, nj = 0, nwk = 0, nb = 0;

    for (int i = 0; i < n_in; i++) {
        const float* p = (const float*)d_in[i];
        int sz = in_sizes[i];
        if      (sz == 65536   && !x)      { x = p; sx = sz; }
        else if (sz == 524288  && nvk < 2) { vk[nvk++] = p; svk = sz; }
        else if (sz == 8192    && nj  < 2) { J[nj++]   = p; sj  = sz; }
        else if (sz == 4194304 && nwk < 2) { wk[nwk++] = p; swk = sz; }
        else if (sz == 2048    && nb  < 4) { bs[nb++]  = p; sb  = sz; }
    }

    if (!(x && nvk == 2 && nj == 2 && nwk == 2 && nb == 4)) {
        if (n_in < 11) return;
        x     = (const float*)d_in[0];  sx  = in_sizes[0];
        vk[0] = (const float*)d_in[1];  bs[0] = (const float*)d_in[2];
        vk[1] = (const float*)d_in[3];  bs[1] = (const float*)d_in[4];
        J[0]  = (const float*)d_in[5];  J[1]  = (const float*)d_in[6];
        wk[0] = (const float*)d_in[7];  bs[2] = (const float*)d_in[8];
        wk[1] = (const float*)d_in[9];  bs[3] = (const float*)d_in[10];
        svk = in_sizes[1]; sj = in_sizes[5]; swk = in_sizes[7]; sb = in_sizes[2];
    }

    int mode       = (out_size == 2 * P_ * DM) ? 1 : 0;
    int out_floats = out_size;

    static bool attr_done = false;
    if (!attr_done) {
        cudaFuncSetAttribute(gemm_out_mma,
                             cudaFuncAttributeMaxDynamicSharedMemorySize, SMEM_GEMM);
        cudaFuncSetAttribute(gemm_v_mma,
                             cudaFuncAttributeMaxDynamicSharedMemorySize, SMEM_V);
        cudaFuncSetAttribute(circ_att_mma,
                             cudaFuncAttributeMaxDynamicSharedMemorySize, SMEM_C);
        attr_done = true;
    }

    split_x   <<<(P_ * PATCH_ + 255) / 256, 256>>>(x, sx);
    split_vk  <<<dim3(DM / 32, PATCH_ / 32), 256>>>(vk[0], vk[1], svk);
    gemm_v_mma<<<dim3(DM / BN, P_ / BM), 256, SMEM_V>>>(bs[0], bs[1], sb);
    split_vt  <<<dim3(DM / 32, P_ / 32), 256>>>();
    circ_att_mma<<<dim3(P_ / 64, H_), 256, SMEM_C>>>(J[0], J[1], sj);
    split_wt  <<<dim3(DM / 32, DM / 32), 256>>>(wk[0], wk[1], swk);
    gemm_out_mma<<<dim3(DM / BN, P_ / BM), 256, SMEM_GEMM>>>(
        bs[2], bs[3], sb, (float*)d_out, out_floats, mode);
}

// round 11
// speedup vs baseline: 1.2335x; 1.0165x over previous
#include <cuda_runtime.h>
#include <cuda_bf16.h>
#include <cstdint>

namespace {
constexpr int P_     = 256;
constexpr int H_     = 32;
constexpr int DM     = 2048;
constexpr int HD     = 64;
constexpr int PATCH_ = 256;

constexpr int BM = 64;
constexpr int BN = 64;
constexpr int KC = 64;                  // k per smem stage
constexpr int N_TILES  = 3 * (DM / KC);     // gemm_out: 96 stages
constexpr int NV_TILES = 3 * (PATCH_ / KC); // gemm_v:   12 stages
constexpr int PADK  = 72;               // bf16 stride: 144B (conflict-free)
constexpr int PANEL = BM * PADK * 2;    // 9216 B
constexpr int STAGE = 6 * PANEL;        // 55296 B (gemm_out: 6 panels)
constexpr int SMEM_GEMM = 2 * STAGE;    // 110592 B
constexpr int VSTAGE = 3 * PANEL;       // gemm_v: 3 panels (A shared)
constexpr int SMEM_V  = 2 * VSTAGE;     // 55296 B

// circ_att_mma: B-only stages (A synthesized from circulant pair table)
constexpr int CPANEL = 64 * 144;        // 9216 B
constexpr int CSTAGE = 3 * CPANEL;      // 27648 B
constexpr int NC_TILES = 3 * (P_ / KC); // 3 passes x 4 k-tiles = 12
constexpr int SMEM_C  = 2 * CSTAGE + 6 * 512 * 4;  // 67584 B
}

// ------------------------- device scratch (static) -------------------------
__device__ __nv_bfloat16 g_X_hi[P_ * PATCH_];
__device__ __nv_bfloat16 g_X_lo[P_ * PATCH_];
__device__ __nv_bfloat16 g_VtR_hi[DM * PATCH_];   // [n][k] = vR_k[k][n]
__device__ __nv_bfloat16 g_VtR_lo[DM * PATCH_];
__device__ __nv_bfloat16 g_VtI_hi[DM * PATCH_];
__device__ __nv_bfloat16 g_VtI_lo[DM * PATCH_];

// v panels in natural [q][DM] layout (written by gemm_v_mma epilogue)
__device__ __nv_bfloat16 g_vr_hi[P_ * DM];
__device__ __nv_bfloat16 g_vr_lo[P_ * DM];
__device__ __nv_bfloat16 g_vi_hi[P_ * DM];
__device__ __nv_bfloat16 g_vi_lo[P_ * DM];
__device__ __nv_bfloat16 g_vs_hi[P_ * DM];
__device__ __nv_bfloat16 g_vs_lo[P_ * DM];

__device__ __nv_bfloat16 g_Yr_hi[P_ * DM];
__device__ __nv_bfloat16 g_Yr_lo[P_ * DM];
__device__ __nv_bfloat16 g_Yi_hi[P_ * DM];
__device__ __nv_bfloat16 g_Yi_lo[P_ * DM];
__device__ __nv_bfloat16 g_Ys_hi[P_ * DM];
__device__ __nv_bfloat16 g_Ys_lo[P_ * DM];

__device__ __nv_bfloat16 g_WtR_hi[DM * DM];   // [n][k] = w0R_k[k][n]
__device__ __nv_bfloat16 g_WtR_lo[DM * DM];
__device__ __nv_bfloat16 g_WtI_hi[DM * DM];
__device__ __nv_bfloat16 g_WtI_lo[DM * DM];
__device__ __nv_bfloat16 g_WtS_hi[DM * DM];   // WR + WI
__device__ __nv_bfloat16 g_WtS_lo[DM * DM];

__device__ __forceinline__ int clampi(int i, int sz) { return i < sz ? i : sz - 1; }

// ------------------------- asm helpers -------------------------
__device__ __forceinline__ uint32_t smem_u32(const void* p) {
    uint32_t a;
    asm("{ .reg .u64 t; cvta.to.shared.u64 t, %1; cvt.u32.u64 %0, t; }"
        : "=r"(a) : "l"(p));
    return a;
}
__device__ __forceinline__ void cpasync16(uint32_t s, const void* g) {
    asm volatile("cp.async.cg.shared.global [%0], [%1], 16;" :: "r"(s), "l"(g));
}
__device__ __forceinline__ void cp_commit() { asm volatile("cp.async.commit_group;"); }
__device__ __forceinline__ void cp_wait1()  { asm volatile("cp.async.wait_group 1;"); }
__device__ __forceinline__ void cp_wait0()  { asm volatile("cp.async.wait_group 0;"); }
__device__ __forceinline__ void ldmx4(uint32_t* r, uint32_t addr) {
    asm volatile("ldmatrix.sync.aligned.m8n8.x4.shared.b16 {%0,%1,%2,%3}, [%4];"
                 : "=r"(r[0]), "=r"(r[1]), "=r"(r[2]), "=r"(r[3]) : "r"(addr));
}
__device__ __forceinline__ void ldmx4t(uint32_t* r, uint32_t addr) {
    asm volatile("ldmatrix.sync.aligned.m8n8.x4.trans.shared.b16 {%0,%1,%2,%3}, [%4];"
                 : "=r"(r[0]), "=r"(r[1]), "=r"(r[2]), "=r"(r[3]) : "r"(addr));
}
#define MMA_BF16(d, a, b0_, b1_)                                               \
    asm volatile(                                                              \
        "mma.sync.aligned.m16n8k16.row.col.f32.bf16.bf16.f32 "                 \
        "{%0,%1,%2,%3}, {%4,%5,%6,%7}, {%8,%9}, {%0,%1,%2,%3};"                \
        : "+f"(d[0]), "+f"(d[1]), "+f"(d[2]), "+f"(d[3])                       \
        : "r"(a[0]), "r"(a[1]), "r"(a[2]), "r"(a[3]), "r"(b0_), "r"(b1_))

__device__ __forceinline__ uint16_t bf_bits(__nv_bfloat16 h) {
    return *reinterpret_cast<uint16_t*>(&h);
}
__device__ __forceinline__ void store_split2(__nv_bfloat16* hi, __nv_bfloat16* lo,
                                             int oi, float a, float b) {
    __nv_bfloat16 h0 = __float2bfloat16(a);
    __nv_bfloat16 h1 = __float2bfloat16(b);
    *(__nv_bfloat162*)&hi[oi] = __nv_bfloat162(h0, h1);
    *(__nv_bfloat162*)&lo[oi] = __nv_bfloat162(
        __float2bfloat16(a - __bfloat162float(h0)),
        __float2bfloat16(b - __bfloat162float(h1)));
}

// ---------------------------------------------------------------------------
// Kernel 0a: split x into bf16 hi/lo
// ---------------------------------------------------------------------------
__global__ void split_x(const float* __restrict__ x, int sx)
{
    int i = blockIdx.x * 256 + threadIdx.x;
    if (i >= P_ * PATCH_) return;
    float a = x[clampi(i, sx)];
    __nv_bfloat16 h = __float2bfloat16(a);
    g_X_hi[i] = h;
    g_X_lo[i] = __float2bfloat16(a - __bfloat162float(h));
}

// ---------------------------------------------------------------------------
// Kernel 0b: transpose + split vR_k, vI_k -> 4 bf16 panels [n][k]
// ---------------------------------------------------------------------------
__global__ void split_vk(const float* __restrict__ VR,
                         const float* __restrict__ VI, int sv)
{
    __shared__ float tR[32][33];
    __shared__ float tI[32][33];
    const int tid = threadIdx.x;
    const int n0 = blockIdx.x * 32, k0 = blockIdx.y * 32;

    #pragma unroll
    for (int i = 0; i < 4; i++) {
        int idx = tid + i * 256;
        int kk = idx >> 5, nn = idx & 31;
        int gi = clampi((k0 + kk) * DM + n0 + nn, sv);
        tR[nn][kk] = VR[gi];
        tI[nn][kk] = VI[gi];
    }
    __syncthreads();

    const int kp  = tid & 15;
    const int nn2 = tid >> 4;
    #pragma unroll
    for (int half = 0; half < 2; half++) {
        int n = nn2 + half * 16;
        int k = kp * 2;
        float r0 = tR[n][k], r1 = tR[n][k + 1];
        float i0 = tI[n][k], i1 = tI[n][k + 1];
        int oi = (n0 + n) * PATCH_ + k0 + k;
        store_split2(g_VtR_hi, g_VtR_lo, oi, r0, r1);
        store_split2(g_VtI_hi, g_VtI_lo, oi, i0, i1);
    }
}

// ---------------------------------------------------------------------------
// Kernel 1: gemm_v via mma.sync split-bf16 (3-pass).
//   vr = x @ vR_k + br ; vi = x @ vI_k + bi
// Epilogue writes 6 bf16 hi/lo v panels DIRECTLY ([q][DM] layout) — no fp32
// round trip, no separate transpose/split kernel.
// ---------------------------------------------------------------------------
__global__ void __launch_bounds__(256)
gemm_v_mma(const float* __restrict__ br, const float* __restrict__ bi, int sb)
{
    extern __shared__ __align__(16) char smem[];
    const uint32_t sbase = smem_u32(smem);

    const int tid  = threadIdx.x;
    const int lane = tid & 31, wid = tid >> 5;
    const int g    = lane >> 2, tig = lane & 3;
    const int wm   = wid >> 2, wn = wid & 3;
    const int m0   = blockIdx.y * BM, n0 = blockIdx.x * BN;

    const int a_row_off = (lane & 7) + ((lane >> 3) & 1) * 8;
    const int a_col_off = (lane >> 4) * 8;
    const int b_row_off = (lane & 7) + (lane >> 4) * 8;
    const int b_col_off = ((lane >> 3) & 1) * 8;

    float acc[2][2][2][4] = {};

    const int ch_row0 = tid >> 2;
    const int ch_q0   = (tid & 3);
    const int ch_q1   = (tid & 3) + 4;

    auto issue_stage = [&](int t) {
        const int pass = t >> 2, kt = t & 3, k0 = kt * KC;
        const __nv_bfloat16* Ap = (pass < 2) ? g_X_hi : g_X_lo;
        const __nv_bfloat16* B0 = (pass == 1) ? g_VtR_lo : g_VtR_hi;
        const __nv_bfloat16* B1 = (pass == 1) ? g_VtI_lo : g_VtI_hi;
        const uint32_t sb_ = sbase + (t & 1) * VSTAGE;
        {
            const __nv_bfloat16* ga = Ap + (m0 + ch_row0) * PATCH_ + k0;
            uint32_t sa = sb_ + ch_row0 * 144;
            cpasync16(sa + ch_q0 * 16, ga + ch_q0 * 8);
            cpasync16(sa + ch_q1 * 16, ga + ch_q1 * 8);
        }
        {
            const __nv_bfloat16* gb = B0 + (n0 + ch_row0) * PATCH_ + k0;
            uint32_t sbb = sb_ + PANEL + ch_row0 * 144;
            cpasync16(sbb + ch_q0 * 16, gb + ch_q0 * 8);
            cpasync16(sbb + ch_q1 * 16, gb + ch_q1 * 8);
        }
        {
            const __nv_bfloat16* gb = B1 + (n0 + ch_row0) * PATCH_ + k0;
            uint32_t sbb = sb_ + 2 * PANEL + ch_row0 * 144;
            cpasync16(sbb + ch_q0 * 16, gb + ch_q0 * 8);
            cpasync16(sbb + ch_q1 * 16, gb + ch_q1 * 8);
        }
        cp_commit();
    };

    issue_stage(0);

    for (int t = 0; t < NV_TILES; t++) {
        const int s = t & 1;
        if (t + 1 < NV_TILES) { issue_stage(t + 1); cp_wait1(); }
        else                  { cp_wait0(); }
        __syncthreads();

        const uint32_t base = sbase + s * VSTAGE;
        #pragma unroll
        for (int kk = 0; kk < KC; kk += 16) {
            uint32_t a[2][4];
            #pragma unroll
            for (int mm = 0; mm < 2; mm++) {
                int r0 = wm * 32 + mm * 16;
                ldmx4(a[mm], base + (r0 + a_row_off) * 144 + (kk + a_col_off) * 2);
            }
            #pragma unroll
            for (int c = 0; c < 2; c++) {
                uint32_t b[4];
                int nr = wn * 16;
                ldmx4(b, base + (1 + c) * PANEL +
                         (nr + b_row_off) * 144 + (kk + b_col_off) * 2);
                #pragma unroll
                for (int mm = 0; mm < 2; mm++)
                    #pragma unroll
                    for (int nn = 0; nn < 2; nn++)
                        MMA_BF16(acc[c][mm][nn], a[mm], b[nn * 2], b[nn * 2 + 1]);
            }
        }
        __syncthreads();
    }

    // fused epilogue: bias + hi/lo split of vr, vi, vs = vr+vi
    #pragma unroll
    for (int mm = 0; mm < 2; mm++) {
        #pragma unroll
        for (int nn = 0; nn < 2; nn++) {
            int mi = m0 + wm * 32 + mm * 16 + g;
            int ni = n0 + wn * 16 + nn * 8 + tig * 2;
            float b0r = br[clampi(ni, sb)],     b1r = br[clampi(ni + 1, sb)];
            float b0i = bi[clampi(ni, sb)],     b1i = bi[clampi(ni + 1, sb)];
            #pragma unroll
            for (int half = 0; half < 2; half++) {
                int m = mi + half * 8;
                float vr0 = acc[0][mm][nn][half * 2]     + b0r;
                float vr1 = acc[0][mm][nn][half * 2 + 1] + b1r;
                float vi0 = acc[1][mm][nn][half * 2]     + b0i;
                float vi1 = acc[1][mm][nn][half * 2 + 1] + b1i;
                float vs0 = vr0 + vi0, vs1 = vr1 + vi1;
                int oi = m * DM + ni;
                store_split2(g_vr_hi, g_vr_lo, oi, vr0, vr1);
                store_split2(g_vi_hi, g_vi_lo, oi, vi0, vi1);
                store_split2(g_vs_hi, g_vs_lo, oi, vs0, vs1);
            }
        }
    }
}

// ---------------------------------------------------------------------------
// Kernel 2: circulant attention via mma.sync.
//   A[s][q] = J[(s+q) % 256] — synthesized from smem pair table (circulant).
//   B = v[q][h*64+d] loaded from [k][n]-layout panels via ldmatrix.trans.
//   Karatsuba: C1=Jr*vr, C2=Ji*vi, C3=Js*vs; yr=C1-C2, yi=C3-C1-C2.
// grid (P_/64=4, H=32), 256 threads.
// ---------------------------------------------------------------------------
__global__ void __launch_bounds__(256)
circ_att_mma(const float* __restrict__ JR, const float* __restrict__ JI, int sj)
{
    extern __shared__ __align__(16) char smem[];
    const uint32_t sbase = smem_u32(smem);
    uint32_t* pair = (uint32_t*)(smem + 2 * CSTAGE);   // [6][512]

    const int tid  = threadIdx.x;
    const int lane = tid & 31, wid = tid >> 5;
    const int g    = lane >> 2, tig = lane & 3;
    const int wm   = wid >> 2, wn = wid & 3;
    const int h    = blockIdx.y;
    const int s0   = blockIdx.x * 64;

    // trans-B lane offsets (source [k][n]): rows = k, cols = n
    const int bt_row = (lane & 7) + ((lane >> 3) & 1) * 8;
    const int bt_col = (lane >> 4) * 8;

    // build circulant pair tables: pair[v][t] = (J2v[t], J2v[t+1])
    for (int t = tid; t < 512; t += 256) {
        float jr0 = JR[clampi(((t) & 255) * H_ + h, sj)];
        float jr1 = JR[clampi(((t + 1) & 255) * H_ + h, sj)];
        float ji0 = JI[clampi(((t) & 255) * H_ + h, sj)];
        float ji1 = JI[clampi(((t + 1) & 255) * H_ + h, sj)];
        float v0[3] = {jr0, ji0, jr0 + ji0};
        float v1[3] = {jr1, ji1, jr1 + ji1};
        #pragma unroll
        for (int c = 0; c < 3; c++) {
            __nv_bfloat16 h0 = __float2bfloat16(v0[c]);
            __nv_bfloat16 h1 = __float2bfloat16(v1[c]);
            __nv_bfloat16 l0 = __float2bfloat16(v0[c] - __bfloat162float(h0));
            __nv_bfloat16 l1 = __float2bfloat16(v1[c] - __bfloat162float(h1));
            pair[(c * 2 + 0) * 512 + t] =
                (uint32_t)bf_bits(h0) | ((uint32_t)bf_bits(h1) << 16);
            pair[(c * 2 + 1) * 512 + t] =
                (uint32_t)bf_bits(l0) | ((uint32_t)bf_bits(l1) << 16);
        }
    }

    float acc[3][2][2][4] = {};

    const int ch_row0 = tid >> 2;
    const int ch_q0   = (tid & 3);
    const int ch_q1   = (tid & 3) + 4;

    auto issue_stage = [&](int t) {
        const int pass = t >> 2, kt = t & 3, k0 = kt * KC;
        const __nv_bfloat16* Bp[3];
        Bp[0] = (pass == 1) ? g_vr_lo : g_vr_hi;
        Bp[1] = (pass == 1) ? g_vi_lo : g_vi_hi;
        Bp[2] = (pass == 1) ? g_vs_lo : g_vs_hi;
        const uint32_t sb_ = sbase + (t & 1) * CSTAGE;
        #pragma unroll
        for (int c = 0; c < 3; c++) {
            const __nv_bfloat16* gb = Bp[c] + (k0 + ch_row0) * DM + h * HD;
            uint32_t s = sb_ + c * CPANEL + ch_row0 * 144;
            cpasync16(s + ch_q0 * 16, gb + ch_q0 * 8);
            cpasync16(s + ch_q1 * 16, gb + ch_q1 * 8);
        }
        cp_commit();
    };

    __syncthreads();   // pair table ready before mainloop reads it
    issue_stage(0);

    for (int t = 0; t < NC_TILES; t++) {
        const int s = t & 1;
        if (t + 1 < NC_TILES) { issue_stage(t + 1); cp_wait1(); }
        else                  { cp_wait0(); }
        __syncthreads();

        const uint32_t base = sbase + s * CSTAGE;
        const int pass = t >> 2, kt = t & 3;
        const int aoff = (pass < 2) ? 0 : 1;     // A hi for passes 0,1; lo for 2
        #pragma unroll
        for (int kk = 0; kk < KC; kk += 16) {
            const int tbase = s0 + wm * 32 + g + kt * 64 + kk + tig * 2;
            #pragma unroll
            for (int c = 0; c < 3; c++) {
                const uint32_t* Pt = &pair[(c * 2 + aoff) * 512];
                uint32_t u0 = Pt[tbase],      u1 = Pt[tbase + 8];
                uint32_t u2 = Pt[tbase + 16], u3 = Pt[tbase + 24];
                uint32_t u4 = Pt[tbase + 32];
                uint32_t a0[4] = {u0, u1, u1, u2};
                uint32_t a1[4] = {u2, u3, u3, u4};
                uint32_t b[4];
                ldmx4t(b, base + c * CPANEL +
                          (kk + bt_row) * 144 + (wn * 16 + bt_col) * 2);
                MMA_BF16(acc[c][0][0], a0, b[0], b[1]);
                MMA_BF16(acc[c][0][1], a0, b[2], b[3]);
                MMA_BF16(acc[c][1][0], a1, b[0], b[1]);
                MMA_BF16(acc[c][1][1], a1, b[2], b[3]);
            }
        }
        __syncthreads();
    }

    // epilogue: Karatsuba combine + split write of 6 Y panels
    #pragma unroll
    for (int mm = 0; mm < 2; mm++) {
        #pragma unroll
        for (int nn = 0; nn < 2; nn++) {
            #pragma unroll
            for (int c2 = 0; c2 < 4; c2++) {
                int m = s0 + wm * 32 + mm * 16 + g + (c2 >> 1) * 8;
                int n = h * HD + wn * 16 + nn * 8 + tig * 2 + (c2 & 1);
                float C1 = acc[0][mm][nn][c2];
                float C2 = acc[1][mm][nn][c2];
                float C3 = acc[2][mm][nn][c2];
                float a  = C1 - C2;
                float b  = C3 - C1 - C2;
                float sm = a + b;
                int idx = m * DM + n;
                __nv_bfloat16 ha = __float2bfloat16(a);
                __nv_bfloat16 hb = __float2bfloat16(b);
                __nv_bfloat16 hs = __float2bfloat16(sm);
                g_Yr_hi[idx] = ha;
                g_Yr_lo[idx] = __float2bfloat16(a - __bfloat162float(ha));
                g_Yi_hi[idx] = hb;
                g_Yi_lo[idx] = __float2bfloat16(b - __bfloat162float(hb));
                g_Ys_hi[idx] = hs;
                g_Ys_lo[idx] = __float2bfloat16(sm - __bfloat162float(hs));
            }
        }
    }
}

// ---------------------------------------------------------------------------
// Kernel 3: fused transpose + split of WR, WI, WR+WI -> 6 bf16 panels [n][k]
// ---------------------------------------------------------------------------
__global__ void split_wt(const float* __restrict__ WR,
                         const float* __restrict__ WI, int sw)
{
    __shared__ float tR[32][33];
    __shared__ float tI[32][33];
    const int tid = threadIdx.x;
    const int n0 = blockIdx.x * 32, k0 = blockIdx.y * 32;

    #pragma unroll
    for (int i = 0; i < 4; i++) {
        int idx = tid + i * 256;
        int kk = idx >> 5, nn = idx & 31;
        int gi = clampi((k0 + kk) * DM + n0 + nn, sw);
        tR[nn][kk] = WR[gi];
        tI[nn][kk] = WI[gi];
    }
    __syncthreads();

    const int kp  = tid & 15;
    const int nn2 = tid >> 4;
    #pragma unroll
    for (int half = 0; half < 2; half++) {
        int n = nn2 + half * 16;
        int k = kp * 2;
        float r0 = tR[n][k],     r1 = tR[n][k + 1];
        float i0 = tI[n][k],     i1 = tI[n][k + 1];
        float s0 = r0 + i0,      s1 = r1 + i1;
        int oi = (n0 + n) * DM + k0 + k;
        store_split2(g_WtR_hi, g_WtR_lo, oi, r0, r1);
        store_split2(g_WtI_hi, g_WtI_lo, oi, i0, i1);
        store_split2(g_WtS_hi, g_WtS_lo, oi, s0, s1);
    }
}

// ---------------------------------------------------------------------------
// Kernel 4: Karatsuba bf16-split GEMM, 256 threads (8 warps, 32x16 warp tile)
// ---------------------------------------------------------------------------
__global__ void __launch_bounds__(256)
gemm_out_mma(const float* __restrict__ bR, const float* __restrict__ bI, int sb,
             float* __restrict__ out, int out_floats, int mode)
{
    extern __shared__ __align__(16) char smem[];
    const uint32_t sbase = smem_u32(smem);

    const int tid  = threadIdx.x;
    const int lane = tid & 31, wid = tid >> 5;
    const int g    = lane >> 2, tig = lane & 3;
    const int wm   = wid >> 2, wn = wid & 3;
    const int m0   = blockIdx.y * BM, n0 = blockIdx.x * BN;

    const int a_row_off = (lane & 7) + ((lane >> 3) & 1) * 8;
    const int a_col_off = (lane >> 4) * 8;
    const int b_row_off = (lane & 7) + (lane >> 4) * 8;
    const int b_col_off = ((lane >> 3) & 1) * 8;

    float acc[3][2][2][4] = {};

    const int ch_row0 = tid >> 2;
    const int ch_q0   = (tid & 3);
    const int ch_q1   = (tid & 3) + 4;

    auto issue_stage = [&](int t) {
        const int pass = t >> 5, kt = t & 31, k0 = kt * KC;
        const __nv_bfloat16* Ap[3];
        const __nv_bfloat16* Bp[3];
        Ap[0] = (pass < 2) ? g_Yr_hi : g_Yr_lo;
        Ap[1] = (pass < 2) ? g_Yi_hi : g_Yi_lo;
        Ap[2] = (pass < 2) ? g_Ys_hi : g_Ys_lo;
        Bp[0] = (pass == 1) ? g_WtR_lo : g_WtR_hi;
        Bp[1] = (pass == 1) ? g_WtI_lo : g_WtI_hi;
        Bp[2] = (pass == 1) ? g_WtS_lo : g_WtS_hi;
        const uint32_t sb_ = sbase + (t & 1) * STAGE;
        #pragma unroll
        for (int p = 0; p < 3; p++) {
            const __nv_bfloat16* ga = Ap[p] + (m0 + ch_row0) * DM + k0;
            uint32_t sa = sb_ + p * PANEL + ch_row0 * 144;
            cpasync16(sa + ch_q0 * 16, ga + ch_q0 * 8);
            cpasync16(sa + ch_q1 * 16, ga + ch_q1 * 8);
            const __nv_bfloat16* gb = Bp[p] + (n0 + ch_row0) * DM + k0;
            uint32_t sbb = sb_ + (3 + p) * PANEL + ch_row0 * 144;
            cpasync16(sbb + ch_q0 * 16, gb + ch_q0 * 8);
            cpasync16(sbb + ch_q1 * 16, gb + ch_q1 * 8);
        }
        cp_commit();
    };

    issue_stage(0);

    for (int t = 0; t < N_TILES; t++) {
        const int s = t & 1;
        if (t + 1 < N_TILES) { issue_stage(t + 1); cp_wait1(); }
        else                 { cp_wait0(); }
        __syncthreads();

        const uint32_t base = sbase + s * STAGE;
        #pragma unroll
        for (int kk = 0; kk < KC; kk += 16) {
            #pragma unroll
            for (int c = 0; c < 3; c++) {
                uint32_t a[2][4];
                #pragma unroll
                for (int mm = 0; mm < 2; mm++) {
                    int r0 = wm * 32 + mm * 16;
                    ldmx4(a[mm], base + c * PANEL +
                                 (r0 + a_row_off) * 144 + (kk + a_col_off) * 2);
                }
                uint32_t b[4];
                {
                    int nr = wn * 16;
                    ldmx4(b, base + (3 + c) * PANEL +
                             (nr + b_row_off) * 144 + (kk + b_col_off) * 2);
                }
                #pragma unroll
                for (int mm = 0; mm < 2; mm++)
                    #pragma unroll
                    for (int nn = 0; nn < 2; nn++)
                        MMA_BF16(acc[c][mm][nn], a[mm], b[nn * 2], b[nn * 2 + 1]);
            }
        }
        __syncthreads();
    }

    const float LN2 = 0.69314718055994531f;
    #pragma unroll
    for (int mm = 0; mm < 2; mm++) {
        #pragma unroll
        for (int nn = 0; nn < 2; nn++) {
            int mi = m0 + wm * 32 + mm * 16 + g;
            int ni = n0 + wn * 16 + nn * 8 + tig * 2;
            #pragma unroll
            for (int c = 0; c < 4; c++) {
                int m = mi + (c >> 1) * 8;
                int n = ni + (c & 1);
                float C1 = acc[0][mm][nn][c];
                float C2 = acc[1][mm][nn][c];
                float C3 = acc[2][mm][nn][c];
                float re = C1 - C2 + bR[clampi(n, sb)];
                float im = C3 - C1 - C2 + bI[clampi(n, sb)];
                float sgn = (__float_as_int(re) < 0) ? -1.0f : 1.0f;
                float a = re * sgn;
                float b = im * sgn;
                float e = expf(-2.0f * a);
                float s2, c2;
                __sincosf(2.0f * b, &s2, &c2);
                float wr = e * c2, wi = -e * s2;
                float u = 1.0f + wr;
                float res_re = a + 0.5f * logf(u * u + wi * wi) - LN2;
                if (mode == 0) {
                    int fi = m * DM + n;
                    if (fi < out_floats) out[fi] = res_re;
                } else {
                    float res_im = b + atan2f(wi, u);
                    int fi = (m * DM + n) * 2;
                    if (fi < out_floats)     out[fi]     = res_re;
                    if (fi + 1 < out_floats) out[fi + 1] = res_im;
                }
            }
        }
    }
}

// ---------------------------------------------------------------------------
extern "C" void kernel_launch(void* const* d_in, const int* in_sizes, int n_in,
                              void* d_out, int out_size)
{
    const float* x = nullptr;   int sx = 0;
    const float* vk[2] = {};    int svk = 0;
    const float* J[2]  = {};    int sj = 0;
    const float* wk[2] = {};    int swk = 0;
    const float* bs[4] = {};    int sb = 0;
    int nvk = 0, nj = 0, nwk = 0, nb = 0;

    for (int i = 0; i < n_in; i++) {
        const float* p = (const float*)d_in[i];
        int sz = in_sizes[i];
        if      (sz == 65536   && !x)      { x = p; sx = sz; }
        else if (sz == 524288  && nvk < 2) { vk[nvk++] = p; svk = sz; }
        else if (sz == 8192    && nj  < 2) { J[nj++]   = p; sj  = sz; }
        else if (sz == 4194304 && nwk < 2) { wk[nwk++] = p; swk = sz; }
        else if (sz == 2048    && nb  < 4) { bs[nb++]  = p; sb  = sz; }
    }

    if (!(x && nvk == 2 && nj == 2 && nwk == 2 && nb == 4)) {
        if (n_in < 11) return;
        x     = (const float*)d_in[0];  sx  = in_sizes[0];
        vk[0] = (const float*)d_in[1];  bs[0] = (const float*)d_in[2];
        vk[1] = (const float*)d_in[3];  bs[1] = (const float*)d_in[4];
        J[0]  = (const float*)d_in[5];  J[1]  = (const float*)d_in[6];
        wk[0] = (const float*)d_in[7];  bs[2] = (const float*)d_in[8];
        wk[1] = (const float*)d_in[9];  bs[3] = (const float*)d_in[10];
        svk = in_sizes[1]; sj = in_sizes[5]; swk = in_sizes[7]; sb = in_sizes[2];
    }

    int mode       = (out_size == 2 * P_ * DM) ? 1 : 0;
    int out_floats = out_size;

    static bool attr_done = false;
    static cudaStream_t s_side = nullptr;
    static cudaEvent_t ev_fork = nullptr, ev_join = nullptr;
    if (!attr_done) {
        cudaFuncSetAttribute(gemm_out_mma,
                             cudaFuncAttributeMaxDynamicSharedMemorySize, SMEM_GEMM);
        cudaFuncSetAttribute(gemm_v_mma,
                             cudaFuncAttributeMaxDynamicSharedMemorySize, SMEM_V);
        cudaFuncSetAttribute(circ_att_mma,
                             cudaFuncAttributeMaxDynamicSharedMemorySize, SMEM_C);
        cudaStreamCreateWithFlags(&s_side, cudaStreamNonBlocking);
        cudaEventCreateWithFlags(&ev_fork, cudaEventDisableTiming);
        cudaEventCreateWithFlags(&ev_join, cudaEventDisableTiming);
        attr_done = true;
    }

    // fork: split_wt (independent of the v/att chain) runs on side stream
    cudaEventRecord(ev_fork, 0);
    cudaStreamWaitEvent(s_side, ev_fork, 0);
    split_wt<<<dim3(DM / 32, DM / 32), 256, 0, s_side>>>(wk[0], wk[1], swk);
    cudaEventRecord(ev_join, s_side);

    // main chain (default stream)
    split_x   <<<(P_ * PATCH_ + 255) / 256, 256>>>(x, sx);
    split_vk  <<<dim3(DM / 32, PATCH_ / 32), 256>>>(vk[0], vk[1], svk);
    gemm_v_mma<<<dim3(DM / BN, P_ / BM), 256, SMEM_V>>>(bs[0], bs[1], sb);
    circ_att_mma<<<dim3(P_ / 64, H_), 256, SMEM_C>>>(J[0], J[1], sj);

    // join: gemm_out needs both Y panels (chain) and W panels (side)
    cudaStreamWaitEvent(0, ev_join, 0);
    gemm_out_mma<<<dim3(DM / BN, P_ / BM), 256, SMEM_GEMM>>>(
        bs[2], bs[3], sb, (float*)d_out, out_floats, mode);
}

// round 12
// speedup vs baseline: 1.6200x; 1.3134x over previous
#include <cuda_runtime.h>
#include <cuda_bf16.h>
#include <cstdint>

namespace {
constexpr int P_     = 256;
constexpr int H_     = 32;
constexpr int DM     = 2048;
constexpr int HD     = 64;
constexpr int PATCH_ = 256;

constexpr int BM = 64;
constexpr int BN = 64;
constexpr int KC = 64;                  // k per smem stage
constexpr int N_TILES  = DM / KC;       // gemm_out: 32 stages (fused passes)
constexpr int NV_TILES = PATCH_ / KC;   // gemm_v:   4 stages
constexpr int NC_TILES = P_ / KC;       // circ_att: 4 stages
constexpr int PADK  = 72;               // bf16 stride: 144B (conflict-free)
constexpr int PANEL = BM * PADK * 2;    // 9216 B

// gemm_out: 3 chains x (A_hi, A_lo, B_hi, B_lo) = 12 panels / stage
constexpr int STAGE = 12 * PANEL;       // 110592 B
constexpr int SMEM_GEMM = 2 * STAGE;    // 221184 B
// gemm_v: X_hi, X_lo, VtR_hi, VtR_lo, VtI_hi, VtI_lo = 6 panels
constexpr int VSTAGE = 6 * PANEL;       // 55296 B
constexpr int SMEM_V  = 2 * VSTAGE;     // 110592 B
// circ_att: 3 chains x (B_hi, B_lo) = 6 panels + pair tables
constexpr int CSTAGE = 6 * PANEL;       // 55296 B
constexpr int SMEM_C = 2 * CSTAGE + 6 * 512 * 4;  // 122880 B
}

// ------------------------- device scratch (static) -------------------------
__device__ __nv_bfloat16 g_X_hi[P_ * PATCH_];
__device__ __nv_bfloat16 g_X_lo[P_ * PATCH_];
__device__ __nv_bfloat16 g_VtR_hi[DM * PATCH_];   // [n][k] = vR_k[k][n]
__device__ __nv_bfloat16 g_VtR_lo[DM * PATCH_];
__device__ __nv_bfloat16 g_VtI_hi[DM * PATCH_];
__device__ __nv_bfloat16 g_VtI_lo[DM * PATCH_];

// v panels in natural [q][DM] layout (written by gemm_v_mma epilogue)
__device__ __nv_bfloat16 g_vr_hi[P_ * DM];
__device__ __nv_bfloat16 g_vr_lo[P_ * DM];
__device__ __nv_bfloat16 g_vi_hi[P_ * DM];
__device__ __nv_bfloat16 g_vi_lo[P_ * DM];
__device__ __nv_bfloat16 g_vs_hi[P_ * DM];
__device__ __nv_bfloat16 g_vs_lo[P_ * DM];

__device__ __nv_bfloat16 g_Yr_hi[P_ * DM];
__device__ __nv_bfloat16 g_Yr_lo[P_ * DM];
__device__ __nv_bfloat16 g_Yi_hi[P_ * DM];
__device__ __nv_bfloat16 g_Yi_lo[P_ * DM];
__device__ __nv_bfloat16 g_Ys_hi[P_ * DM];
__device__ __nv_bfloat16 g_Ys_lo[P_ * DM];

__device__ __nv_bfloat16 g_WtR_hi[DM * DM];   // [n][k] = w0R_k[k][n]
__device__ __nv_bfloat16 g_WtR_lo[DM * DM];
__device__ __nv_bfloat16 g_WtI_hi[DM * DM];
__device__ __nv_bfloat16 g_WtI_lo[DM * DM];
__device__ __nv_bfloat16 g_WtS_hi[DM * DM];   // WR + WI
__device__ __nv_bfloat16 g_WtS_lo[DM * DM];

__device__ __forceinline__ int clampi(int i, int sz) { return i < sz ? i : sz - 1; }

// ------------------------- asm helpers -------------------------
__device__ __forceinline__ uint32_t smem_u32(const void* p) {
    uint32_t a;
    asm("{ .reg .u64 t; cvta.to.shared.u64 t, %1; cvt.u32.u64 %0, t; }"
        : "=r"(a) : "l"(p));
    return a;
}
__device__ __forceinline__ void cpasync16(uint32_t s, const void* g) {
    asm volatile("cp.async.cg.shared.global [%0], [%1], 16;" :: "r"(s), "l"(g));
}
__device__ __forceinline__ void cp_commit() { asm volatile("cp.async.commit_group;"); }
__device__ __forceinline__ void cp_wait1()  { asm volatile("cp.async.wait_group 1;"); }
__device__ __forceinline__ void cp_wait0()  { asm volatile("cp.async.wait_group 0;"); }
__device__ __forceinline__ void ldmx4(uint32_t* r, uint32_t addr) {
    asm volatile("ldmatrix.sync.aligned.m8n8.x4.shared.b16 {%0,%1,%2,%3}, [%4];"
                 : "=r"(r[0]), "=r"(r[1]), "=r"(r[2]), "=r"(r[3]) : "r"(addr));
}
__device__ __forceinline__ void ldmx4t(uint32_t* r, uint32_t addr) {
    asm volatile("ldmatrix.sync.aligned.m8n8.x4.trans.shared.b16 {%0,%1,%2,%3}, [%4];"
                 : "=r"(r[0]), "=r"(r[1]), "=r"(r[2]), "=r"(r[3]) : "r"(addr));
}
#define MMA_BF16(d, a, b0_, b1_)                                               \
    asm volatile(                                                              \
        "mma.sync.aligned.m16n8k16.row.col.f32.bf16.bf16.f32 "                 \
        "{%0,%1,%2,%3}, {%4,%5,%6,%7}, {%8,%9}, {%0,%1,%2,%3};"                \
        : "+f"(d[0]), "+f"(d[1]), "+f"(d[2]), "+f"(d[3])                       \
        : "r"(a[0]), "r"(a[1]), "r"(a[2]), "r"(a[3]), "r"(b0_), "r"(b1_))

__device__ __forceinline__ uint16_t bf_bits(__nv_bfloat16 h) {
    return *reinterpret_cast<uint16_t*>(&h);
}
__device__ __forceinline__ void store_split2(__nv_bfloat16* hi, __nv_bfloat16* lo,
                                             int oi, float a, float b) {
    __nv_bfloat16 h0 = __float2bfloat16(a);
    __nv_bfloat16 h1 = __float2bfloat16(b);
    *(__nv_bfloat162*)&hi[oi] = __nv_bfloat162(h0, h1);
    *(__nv_bfloat162*)&lo[oi] = __nv_bfloat162(
        __float2bfloat16(a - __bfloat162float(h0)),
        __float2bfloat16(b - __bfloat162float(h1)));
}

// ---------------------------------------------------------------------------
// Kernel 0a: split x into bf16 hi/lo
// ---------------------------------------------------------------------------
__global__ void split_x(const float* __restrict__ x, int sx)
{
    int i = blockIdx.x * 256 + threadIdx.x;
    if (i >= P_ * PATCH_) return;
    float a = x[clampi(i, sx)];
    __nv_bfloat16 h = __float2bfloat16(a);
    g_X_hi[i] = h;
    g_X_lo[i] = __float2bfloat16(a - __bfloat162float(h));
}

// ---------------------------------------------------------------------------
// Kernel 0b: transpose + split vR_k, vI_k -> 4 bf16 panels [n][k]
// ---------------------------------------------------------------------------
__global__ void split_vk(const float* __restrict__ VR,
                         const float* __restrict__ VI, int sv)
{
    __shared__ float tR[32][33];
    __shared__ float tI[32][33];
    const int tid = threadIdx.x;
    const int n0 = blockIdx.x * 32, k0 = blockIdx.y * 32;

    #pragma unroll
    for (int i = 0; i < 4; i++) {
        int idx = tid + i * 256;
        int kk = idx >> 5, nn = idx & 31;
        int gi = clampi((k0 + kk) * DM + n0 + nn, sv);
        tR[nn][kk] = VR[gi];
        tI[nn][kk] = VI[gi];
    }
    __syncthreads();

    const int kp  = tid & 15;
    const int nn2 = tid >> 4;
    #pragma unroll
    for (int half = 0; half < 2; half++) {
        int n = nn2 + half * 16;
        int k = kp * 2;
        int oi = (n0 + n) * PATCH_ + k0 + k;
        store_split2(g_VtR_hi, g_VtR_lo, oi, tR[n][k], tR[n][k + 1]);
        store_split2(g_VtI_hi, g_VtI_lo, oi, tI[n][k], tI[n][k + 1]);
    }
}

// ---------------------------------------------------------------------------
// Kernel 1: gemm_v via mma.sync, FUSED 3-term split (single K sweep).
//   Per k-tile: load X_hi, X_lo, VtR_hi/lo, VtI_hi/lo; issue hihi+hilo+lohi.
// Epilogue writes 6 bf16 hi/lo v panels directly ([q][DM] layout).
// ---------------------------------------------------------------------------
__global__ void __launch_bounds__(256)
gemm_v_mma(const float* __restrict__ br, const float* __restrict__ bi, int sb)
{
    extern __shared__ __align__(16) char smem[];
    const uint32_t sbase = smem_u32(smem);

    const int tid  = threadIdx.x;
    const int lane = tid & 31, wid = tid >> 5;
    const int g    = lane >> 2, tig = lane & 3;
    const int wm   = wid >> 2, wn = wid & 3;
    const int m0   = blockIdx.y * BM, n0 = blockIdx.x * BN;

    const int a_row_off = (lane & 7) + ((lane >> 3) & 1) * 8;
    const int a_col_off = (lane >> 4) * 8;
    const int b_row_off = (lane & 7) + (lane >> 4) * 8;
    const int b_col_off = ((lane >> 3) & 1) * 8;

    float acc[2][2][2][4] = {};   // [chain][mm][nn][c]

    const int ch_row0 = tid >> 2;
    const int ch_q0   = (tid & 3);
    const int ch_q1   = (tid & 3) + 4;

    // stage panels: 0 X_hi, 1 X_lo, 2 VtR_hi, 3 VtR_lo, 4 VtI_hi, 5 VtI_lo
    auto issue_stage = [&](int t) {
        const int k0 = t * KC;
        const __nv_bfloat16* Gp[6] = {g_X_hi, g_X_lo, g_VtR_hi, g_VtR_lo,
                                      g_VtI_hi, g_VtI_lo};
        const int rowbase[6] = {m0, m0, n0, n0, n0, n0};
        const uint32_t sb_ = sbase + (t & 1) * VSTAGE;
        #pragma unroll
        for (int p = 0; p < 6; p++) {
            const __nv_bfloat16* gp = Gp[p] + (rowbase[p] + ch_row0) * PATCH_ + k0;
            uint32_t sa = sb_ + p * PANEL + ch_row0 * 144;
            cpasync16(sa + ch_q0 * 16, gp + ch_q0 * 8);
            cpasync16(sa + ch_q1 * 16, gp + ch_q1 * 8);
        }
        cp_commit();
    };

    issue_stage(0);

    for (int t = 0; t < NV_TILES; t++) {
        const int s = t & 1;
        if (t + 1 < NV_TILES) { issue_stage(t + 1); cp_wait1(); }
        else                  { cp_wait0(); }
        __syncthreads();

        const uint32_t base = sbase + s * VSTAGE;
        #pragma unroll
        for (int kk = 0; kk < KC; kk += 16) {
            uint32_t ah[2][4], al[2][4];
            #pragma unroll
            for (int mm = 0; mm < 2; mm++) {
                int r0 = wm * 32 + mm * 16;
                ldmx4(ah[mm], base + 0 * PANEL + (r0 + a_row_off) * 144 + (kk + a_col_off) * 2);
                ldmx4(al[mm], base + 1 * PANEL + (r0 + a_row_off) * 144 + (kk + a_col_off) * 2);
            }
            #pragma unroll
            for (int c = 0; c < 2; c++) {
                uint32_t bh[4], bl[4];
                int nr = wn * 16;
                ldmx4(bh, base + (2 + c * 2) * PANEL + (nr + b_row_off) * 144 + (kk + b_col_off) * 2);
                ldmx4(bl, base + (3 + c * 2) * PANEL + (nr + b_row_off) * 144 + (kk + b_col_off) * 2);
                #pragma unroll
                for (int mm = 0; mm < 2; mm++)
                    #pragma unroll
                    for (int nn = 0; nn < 2; nn++) {
                        MMA_BF16(acc[c][mm][nn], ah[mm], bh[nn * 2], bh[nn * 2 + 1]);
                        MMA_BF16(acc[c][mm][nn], ah[mm], bl[nn * 2], bl[nn * 2 + 1]);
                        MMA_BF16(acc[c][mm][nn], al[mm], bh[nn * 2], bh[nn * 2 + 1]);
                    }
            }
        }
        __syncthreads();
    }

    // fused epilogue: bias + hi/lo split of vr, vi, vs = vr+vi
    #pragma unroll
    for (int mm = 0; mm < 2; mm++) {
        #pragma unroll
        for (int nn = 0; nn < 2; nn++) {
            int mi = m0 + wm * 32 + mm * 16 + g;
            int ni = n0 + wn * 16 + nn * 8 + tig * 2;
            float b0r = br[clampi(ni, sb)],     b1r = br[clampi(ni + 1, sb)];
            float b0i = bi[clampi(ni, sb)],     b1i = bi[clampi(ni + 1, sb)];
            #pragma unroll
            for (int half = 0; half < 2; half++) {
                int m = mi + half * 8;
                float vr0 = acc[0][mm][nn][half * 2]     + b0r;
                float vr1 = acc[0][mm][nn][half * 2 + 1] + b1r;
                float vi0 = acc[1][mm][nn][half * 2]     + b0i;
                float vi1 = acc[1][mm][nn][half * 2 + 1] + b1i;
                float vs0 = vr0 + vi0, vs1 = vr1 + vi1;
                int oi = m * DM + ni;
                store_split2(g_vr_hi, g_vr_lo, oi, vr0, vr1);
                store_split2(g_vi_hi, g_vi_lo, oi, vi0, vi1);
                store_split2(g_vs_hi, g_vs_lo, oi, vs0, vs1);
            }
        }
    }
}

// ---------------------------------------------------------------------------
// Kernel 2: circulant attention via mma.sync, FUSED split (single K sweep).
//   A hi/lo synthesized from pair table; B hi/lo via ldmatrix.trans.
//   Per k-step per chain: hihi + hilo + lohi.
// ---------------------------------------------------------------------------
__global__ void __launch_bounds__(256)
circ_att_mma(const float* __restrict__ JR, const float* __restrict__ JI, int sj)
{
    extern __shared__ __align__(16) char smem[];
    const uint32_t sbase = smem_u32(smem);
    uint32_t* pair = (uint32_t*)(smem + 2 * CSTAGE);   // [6][512]

    const int tid  = threadIdx.x;
    const int lane = tid & 31, wid = tid >> 5;
    const int g    = lane >> 2, tig = lane & 3;
    const int wm   = wid >> 2, wn = wid & 3;
    const int h    = blockIdx.y;
    const int s0   = blockIdx.x * 64;

    const int bt_row = (lane & 7) + ((lane >> 3) & 1) * 8;
    const int bt_col = (lane >> 4) * 8;

    // build circulant pair tables: pair[v][t] = (J2v[t], J2v[t+1])
    for (int t = tid; t < 512; t += 256) {
        float jr0 = JR[clampi(((t) & 255) * H_ + h, sj)];
        float jr1 = JR[clampi(((t + 1) & 255) * H_ + h, sj)];
        float ji0 = JI[clampi(((t) & 255) * H_ + h, sj)];
        float ji1 = JI[clampi(((t + 1) & 255) * H_ + h, sj)];
        float v0[3] = {jr0, ji0, jr0 + ji0};
        float v1[3] = {jr1, ji1, jr1 + ji1};
        #pragma unroll
        for (int c = 0; c < 3; c++) {
            __nv_bfloat16 h0 = __float2bfloat16(v0[c]);
            __nv_bfloat16 h1 = __float2bfloat16(v1[c]);
            __nv_bfloat16 l0 = __float2bfloat16(v0[c] - __bfloat162float(h0));
            __nv_bfloat16 l1 = __float2bfloat16(v1[c] - __bfloat162float(h1));
            pair[(c * 2 + 0) * 512 + t] =
                (uint32_t)bf_bits(h0) | ((uint32_t)bf_bits(h1) << 16);
            pair[(c * 2 + 1) * 512 + t] =
                (uint32_t)bf_bits(l0) | ((uint32_t)bf_bits(l1) << 16);
        }
    }

    float acc[3][2][2][4] = {};

    const int ch_row0 = tid >> 2;
    const int ch_q0   = (tid & 3);
    const int ch_q1   = (tid & 3) + 4;

    // stage panels: c*2+0 = B_hi chain c; c*2+1 = B_lo chain c  ([k][n] layout)
    auto issue_stage = [&](int t) {
        const int k0 = t * KC;
        const __nv_bfloat16* Gp[6] = {g_vr_hi, g_vr_lo, g_vi_hi, g_vi_lo,
                                      g_vs_hi, g_vs_lo};
        const uint32_t sb_ = sbase + (t & 1) * CSTAGE;
        #pragma unroll
        for (int p = 0; p < 6; p++) {
            const __nv_bfloat16* gb = Gp[p] + (k0 + ch_row0) * DM + h * HD;
            uint32_t s = sb_ + p * PANEL + ch_row0 * 144;
            cpasync16(s + ch_q0 * 16, gb + ch_q0 * 8);
            cpasync16(s + ch_q1 * 16, gb + ch_q1 * 8);
        }
        cp_commit();
    };

    __syncthreads();   // pair table ready before mainloop reads it
    issue_stage(0);

    for (int t = 0; t < NC_TILES; t++) {
        const int s = t & 1;
        if (t + 1 < NC_TILES) { issue_stage(t + 1); cp_wait1(); }
        else                  { cp_wait0(); }
        __syncthreads();

        const uint32_t base = sbase + s * CSTAGE;
        #pragma unroll
        for (int kk = 0; kk < KC; kk += 16) {
            const int tbase = s0 + wm * 32 + g + t * 64 + kk + tig * 2;
            #pragma unroll
            for (int c = 0; c < 3; c++) {
                const uint32_t* Ph = &pair[(c * 2 + 0) * 512];
                const uint32_t* Pl = &pair[(c * 2 + 1) * 512];
                uint32_t h0 = Ph[tbase],      h1 = Ph[tbase + 8];
                uint32_t h2 = Ph[tbase + 16], h3 = Ph[tbase + 24];
                uint32_t h4 = Ph[tbase + 32];
                uint32_t l0 = Pl[tbase],      l1 = Pl[tbase + 8];
                uint32_t l2 = Pl[tbase + 16], l3 = Pl[tbase + 24];
                uint32_t l4 = Pl[tbase + 32];
                uint32_t ah0[4] = {h0, h1, h1, h2};
                uint32_t ah1[4] = {h2, h3, h3, h4};
                uint32_t al0[4] = {l0, l1, l1, l2};
                uint32_t al1[4] = {l2, l3, l3, l4};
                uint32_t bh[4], bl[4];
                ldmx4t(bh, base + (c * 2 + 0) * PANEL +
                           (kk + bt_row) * 144 + (wn * 16 + bt_col) * 2);
                ldmx4t(bl, base + (c * 2 + 1) * PANEL +
                           (kk + bt_row) * 144 + (wn * 16 + bt_col) * 2);
                MMA_BF16(acc[c][0][0], ah0, bh[0], bh[1]);
                MMA_BF16(acc[c][0][1], ah0, bh[2], bh[3]);
                MMA_BF16(acc[c][1][0], ah1, bh[0], bh[1]);
                MMA_BF16(acc[c][1][1], ah1, bh[2], bh[3]);
                MMA_BF16(acc[c][0][0], ah0, bl[0], bl[1]);
                MMA_BF16(acc[c][0][1], ah0, bl[2], bl[3]);
                MMA_BF16(acc[c][1][0], ah1, bl[0], bl[1]);
                MMA_BF16(acc[c][1][1], ah1, bl[2], bl[3]);
                MMA_BF16(acc[c][0][0], al0, bh[0], bh[1]);
                MMA_BF16(acc[c][0][1], al0, bh[2], bh[3]);
                MMA_BF16(acc[c][1][0], al1, bh[0], bh[1]);
                MMA_BF16(acc[c][1][1], al1, bh[2], bh[3]);
            }
        }
        __syncthreads();
    }

    // epilogue: Karatsuba combine + split write of 6 Y panels
    #pragma unroll
    for (int mm = 0; mm < 2; mm++) {
        #pragma unroll
        for (int nn = 0; nn < 2; nn++) {
            #pragma unroll
            for (int c2 = 0; c2 < 4; c2++) {
                int m = s0 + wm * 32 + mm * 16 + g + (c2 >> 1) * 8;
                int n = h * HD + wn * 16 + nn * 8 + tig * 2 + (c2 & 1);
                float C1 = acc[0][mm][nn][c2];
                float C2 = acc[1][mm][nn][c2];
                float C3 = acc[2][mm][nn][c2];
                float a  = C1 - C2;
                float b  = C3 - C1 - C2;
                float sm = a + b;
                int idx = m * DM + n;
                __nv_bfloat16 ha = __float2bfloat16(a);
                __nv_bfloat16 hb = __float2bfloat16(b);
                __nv_bfloat16 hs = __float2bfloat16(sm);
                g_Yr_hi[idx] = ha;
                g_Yr_lo[idx] = __float2bfloat16(a - __bfloat162float(ha));
                g_Yi_hi[idx] = hb;
                g_Yi_lo[idx] = __float2bfloat16(b - __bfloat162float(hb));
                g_Ys_hi[idx] = hs;
                g_Ys_lo[idx] = __float2bfloat16(sm - __bfloat162float(hs));
            }
        }
    }
}

// ---------------------------------------------------------------------------
// Kernel 3: fused transpose + split of WR, WI, WR+WI -> 6 bf16 panels [n][k]
// ---------------------------------------------------------------------------
__global__ void split_wt(const float* __restrict__ WR,
                         const float* __restrict__ WI, int sw)
{
    __shared__ float tR[32][33];
    __shared__ float tI[32][33];
    const int tid = threadIdx.x;
    const int n0 = blockIdx.x * 32, k0 = blockIdx.y * 32;

    #pragma unroll
    for (int i = 0; i < 4; i++) {
        int idx = tid + i * 256;
        int kk = idx >> 5, nn = idx & 31;
        int gi = clampi((k0 + kk) * DM + n0 + nn, sw);
        tR[nn][kk] = WR[gi];
        tI[nn][kk] = WI[gi];
    }
    __syncthreads();

    const int kp  = tid & 15;
    const int nn2 = tid >> 4;
    #pragma unroll
    for (int half = 0; half < 2; half++) {
        int n = nn2 + half * 16;
        int k = kp * 2;
        float r0 = tR[n][k],     r1 = tR[n][k + 1];
        float i0 = tI[n][k],     i1 = tI[n][k + 1];
        int oi = (n0 + n) * DM + k0 + k;
        store_split2(g_WtR_hi, g_WtR_lo, oi, r0, r1);
        store_split2(g_WtI_hi, g_WtI_lo, oi, i0, i1);
        store_split2(g_WtS_hi, g_WtS_lo, oi, r0 + i0, r1 + i1);
    }
}

// ---------------------------------------------------------------------------
// Kernel 4: Karatsuba bf16 GEMM, FUSED split (single K sweep of 32 stages).
//   Per k-tile: 12 panels (3 chains x A_hi/A_lo/B_hi/B_lo); per k-step per
//   chain: hihi + hilo + lohi from registers.
// ---------------------------------------------------------------------------
__global__ void __launch_bounds__(256)
gemm_out_mma(const float* __restrict__ bR, const float* __restrict__ bI, int sb,
             float* __restrict__ out, int out_floats, int mode)
{
    extern __shared__ __align__(16) char smem[];
    const uint32_t sbase = smem_u32(smem);

    const int tid  = threadIdx.x;
    const int lane = tid & 31, wid = tid >> 5;
    const int g    = lane >> 2, tig = lane & 3;
    const int wm   = wid >> 2, wn = wid & 3;
    const int m0   = blockIdx.y * BM, n0 = blockIdx.x * BN;

    const int a_row_off = (lane & 7) + ((lane >> 3) & 1) * 8;
    const int a_col_off = (lane >> 4) * 8;
    const int b_row_off = (lane & 7) + (lane >> 4) * 8;
    const int b_col_off = ((lane >> 3) & 1) * 8;

    float acc[3][2][2][4] = {};

    const int ch_row0 = tid >> 2;
    const int ch_q0   = (tid & 3);
    const int ch_q1   = (tid & 3) + 4;

    // stage panels: chain c -> c*4+0 A_hi, c*4+1 A_lo, c*4+2 B_hi, c*4+3 B_lo
    auto issue_stage = [&](int t) {
        const int k0 = t * KC;
        const __nv_bfloat16* Gp[12] = {
            g_Yr_hi, g_Yr_lo, g_WtR_hi, g_WtR_lo,
            g_Yi_hi, g_Yi_lo, g_WtI_hi, g_WtI_lo,
            g_Ys_hi, g_Ys_lo, g_WtS_hi, g_WtS_lo};
        const uint32_t sb_ = sbase + (t & 1) * STAGE;
        #pragma unroll
        for (int p = 0; p < 12; p++) {
            const int rowbase = (p & 2) ? n0 : m0;   // A panels (bit1=0) use m0
            const __nv_bfloat16* gp = Gp[p] + (rowbase + ch_row0) * DM + k0;
            uint32_t sa = sb_ + p * PANEL + ch_row0 * 144;
            cpasync16(sa + ch_q0 * 16, gp + ch_q0 * 8);
            cpasync16(sa + ch_q1 * 16, gp + ch_q1 * 8);
        }
        cp_commit();
    };

    issue_stage(0);

    for (int t = 0; t < N_TILES; t++) {
        const int s = t & 1;
        if (t + 1 < N_TILES) { issue_stage(t + 1); cp_wait1(); }
        else                 { cp_wait0(); }
        __syncthreads();

        const uint32_t base = sbase + s * STAGE;
        #pragma unroll
        for (int kk = 0; kk < KC; kk += 16) {
            #pragma unroll
            for (int c = 0; c < 3; c++) {
                uint32_t ah[2][4], al[2][4];
                #pragma unroll
                for (int mm = 0; mm < 2; mm++) {
                    int r0 = wm * 32 + mm * 16;
                    ldmx4(ah[mm], base + (c * 4 + 0) * PANEL +
                                  (r0 + a_row_off) * 144 + (kk + a_col_off) * 2);
                    ldmx4(al[mm], base + (c * 4 + 1) * PANEL +
                                  (r0 + a_row_off) * 144 + (kk + a_col_off) * 2);
                }
                uint32_t bh[4], bl[4];
                {
                    int nr = wn * 16;
                    ldmx4(bh, base + (c * 4 + 2) * PANEL +
                              (nr + b_row_off) * 144 + (kk + b_col_off) * 2);
                    ldmx4(bl, base + (c * 4 + 3) * PANEL +
                              (nr + b_row_off) * 144 + (kk + b_col_off) * 2);
                }
                #pragma unroll
                for (int mm = 0; mm < 2; mm++)
                    #pragma unroll
                    for (int nn = 0; nn < 2; nn++) {
                        MMA_BF16(acc[c][mm][nn], ah[mm], bh[nn * 2], bh[nn * 2 + 1]);
                        MMA_BF16(acc[c][mm][nn], ah[mm], bl[nn * 2], bl[nn * 2 + 1]);
                        MMA_BF16(acc[c][mm][nn], al[mm], bh[nn * 2], bh[nn * 2 + 1]);
                    }
            }
        }
        __syncthreads();
    }

    const float LN2 = 0.69314718055994531f;
    #pragma unroll
    for (int mm = 0; mm < 2; mm++) {
        #pragma unroll
        for (int nn = 0; nn < 2; nn++) {
            int mi = m0 + wm * 32 + mm * 16 + g;
            int ni = n0 + wn * 16 + nn * 8 + tig * 2;
            #pragma unroll
            for (int c = 0; c < 4; c++) {
                int m = mi + (c >> 1) * 8;
                int n = ni + (c & 1);
                float C1 = acc[0][mm][nn][c];
                float C2 = acc[1][mm][nn][c];
                float C3 = acc[2][mm][nn][c];
                float re = C1 - C2 + bR[clampi(n, sb)];
                float im = C3 - C1 - C2 + bI[clampi(n, sb)];
                float sgn = (__float_as_int(re) < 0) ? -1.0f : 1.0f;
                float a = re * sgn;
                float b = im * sgn;
                float e = expf(-2.0f * a);
                float s2, c2;
                __sincosf(2.0f * b, &s2, &c2);
                float wr = e * c2, wi = -e * s2;
                float u = 1.0f + wr;
                float res_re = a + 0.5f * logf(u * u + wi * wi) - LN2;
                if (mode == 0) {
                    int fi = m * DM + n;
                    if (fi < out_floats) out[fi] = res_re;
                } else {
                    float res_im = b + atan2f(wi, u);
                    int fi = (m * DM + n) * 2;
                    if (fi < out_floats)     out[fi]     = res_re;
                    if (fi + 1 < out_floats) out[fi + 1] = res_im;
                }
            }
        }
    }
}

// ---------------------------------------------------------------------------
extern "C" void kernel_launch(void* const* d_in, const int* in_sizes, int n_in,
                              void* d_out, int out_size)
{
    const float* x = nullptr;   int sx = 0;
    const float* vk[2] = {};    int svk = 0;
    const float* J[2]  = {};    int sj = 0;
    const float* wk[2] = {};    int swk = 0;
    const float* bs[4] = {};    int sb = 0;
    int nvk = 0, nj = 0, nwk = 0, nb = 0;

    for (int i = 0; i < n_in; i++) {
        const float* p = (const float*)d_in[i];
        int sz = in_sizes[i];
        if      (sz == 65536   && !x)      { x = p; sx = sz; }
        else if (sz == 524288  && nvk < 2) { vk[nvk++] = p; svk = sz; }
        else if (sz == 8192    && nj  < 2) { J[nj++]   = p; sj  = sz; }
        else if (sz == 4194304 && nwk < 2) { wk[nwk++] = p; swk = sz; }
        else if (sz == 2048    && nb  < 4) { bs[nb++]  = p; sb  = sz; }
    }

    if (!(x && nvk == 2 && nj == 2 && nwk == 2 && nb == 4)) {
        if (n_in < 11) return;
        x     = (const float*)d_in[0];  sx  = in_sizes[0];
        vk[0] = (const float*)d_in[1];  bs[0] = (const float*)d_in[2];
        vk[1] = (const float*)d_in[3];  bs[1] = (const float*)d_in[4];
        J[0]  = (const float*)d_in[5];  J[1]  = (const float*)d_in[6];
        wk[0] = (const float*)d_in[7];  bs[2] = (const float*)d_in[8];
        wk[1] = (const float*)d_in[9];  bs[3] = (const float*)d_in[10];
        svk = in_sizes[1]; sj = in_sizes[5]; swk = in_sizes[7]; sb = in_sizes[2];
    }

    int mode       = (out_size == 2 * P_ * DM) ? 1 : 0;
    int out_floats = out_size;

    static bool attr_done = false;
    static cudaStream_t s_side = nullptr;
    static cudaEvent_t ev_fork = nullptr, ev_join = nullptr;
    if (!attr_done) {
        cudaFuncSetAttribute(gemm_out_mma,
                             cudaFuncAttributeMaxDynamicSharedMemorySize, SMEM_GEMM);
        cudaFuncSetAttribute(gemm_v_mma,
                             cudaFuncAttributeMaxDynamicSharedMemorySize, SMEM_V);
        cudaFuncSetAttribute(circ_att_mma,
                             cudaFuncAttributeMaxDynamicSharedMemorySize, SMEM_C);
        cudaStreamCreateWithFlags(&s_side, cudaStreamNonBlocking);
        cudaEventCreateWithFlags(&ev_fork, cudaEventDisableTiming);
        cudaEventCreateWithFlags(&ev_join, cudaEventDisableTiming);
        attr_done = true;
    }

    // fork: split_wt (independent of the v/att chain) runs on side stream
    cudaEventRecord(ev_fork, 0);
    cudaStreamWaitEvent(s_side, ev_fork, 0);
    split_wt<<<dim3(DM / 32, DM / 32), 256, 0, s_side>>>(wk[0], wk[1], swk);
    cudaEventRecord(ev_join, s_side);

    // main chain (default stream)
    split_x   <<<(P_ * PATCH_ + 255) / 256, 256>>>(x, sx);
    split_vk  <<<dim3(DM / 32, PATCH_ / 32), 256>>>(vk[0], vk[1], svk);
    gemm_v_mma<<<dim3(DM / BN, P_ / BM), 256, SMEM_V>>>(bs[0], bs[1], sb);
    circ_att_mma<<<dim3(P_ / 64, H_), 256, SMEM_C>>>(J[0], J[1], sj);

    // join: gemm_out needs both Y panels (chain) and W panels (side)
    cudaStreamWaitEvent(0, ev_join, 0);
    gemm_out_mma<<<dim3(DM / BN, P_ / BM), 256, SMEM_GEMM>>>(
        bs[2], bs[3], sb, (float*)d_out, out_floats, mode);
}

// round 13
// speedup vs baseline: 1.6395x; 1.0120x over previous
#include <cuda_runtime.h>
#include <cuda_bf16.h>
#include <cstdint>

namespace {
constexpr int P_     = 256;
constexpr int H_     = 32;
constexpr int DM     = 2048;
constexpr int HD     = 64;
constexpr int PATCH_ = 256;

constexpr int BM = 64;
constexpr int BN = 64;
constexpr int KC = 64;                  // k per smem stage
constexpr int N_TILES  = DM / KC;       // gemm_out: 32 stages (fused passes)
constexpr int NV_TILES = PATCH_ / KC;   // gemm_v:   4 stages
constexpr int NC_TILES = P_ / KC;       // circ_att: 4 stages
constexpr int PADK  = 72;               // bf16 stride: 144B (conflict-free)
constexpr int PANEL = BM * PADK * 2;    // 9216 B

// gemm_out: 3 chains x (A_hi, A_lo, B_hi, B_lo) = 12 panels / stage
constexpr int STAGE = 12 * PANEL;       // 110592 B
constexpr int SMEM_GEMM = 2 * STAGE;    // 221184 B
// gemm_v: X_hi, X_lo, VtR_hi, VtR_lo, VtI_hi, VtI_lo = 6 panels; 4-deep
constexpr int VSTAGE = 6 * PANEL;       // 55296 B
constexpr int SMEM_V  = 4 * VSTAGE;     // 221184 B (all 4 k-tiles resident)
// circ_att: 3 chains x (B_hi, B_lo) = 6 panels + pair tables
constexpr int CSTAGE = 6 * PANEL;       // 55296 B
constexpr int SMEM_C = 2 * CSTAGE + 6 * 512 * 4;  // 122880 B
}

// ------------------------- device scratch (static) -------------------------
__device__ __nv_bfloat16 g_X_hi[P_ * PATCH_];
__device__ __nv_bfloat16 g_X_lo[P_ * PATCH_];
__device__ __nv_bfloat16 g_VtR_hi[DM * PATCH_];   // [n][k] = vR_k[k][n]
__device__ __nv_bfloat16 g_VtR_lo[DM * PATCH_];
__device__ __nv_bfloat16 g_VtI_hi[DM * PATCH_];
__device__ __nv_bfloat16 g_VtI_lo[DM * PATCH_];

// v panels in natural [q][DM] layout (written by gemm_v_mma epilogue)
__device__ __nv_bfloat16 g_vr_hi[P_ * DM];
__device__ __nv_bfloat16 g_vr_lo[P_ * DM];
__device__ __nv_bfloat16 g_vi_hi[P_ * DM];
__device__ __nv_bfloat16 g_vi_lo[P_ * DM];
__device__ __nv_bfloat16 g_vs_hi[P_ * DM];
__device__ __nv_bfloat16 g_vs_lo[P_ * DM];

__device__ __nv_bfloat16 g_Yr_hi[P_ * DM];
__device__ __nv_bfloat16 g_Yr_lo[P_ * DM];
__device__ __nv_bfloat16 g_Yi_hi[P_ * DM];
__device__ __nv_bfloat16 g_Yi_lo[P_ * DM];
__device__ __nv_bfloat16 g_Ys_hi[P_ * DM];
__device__ __nv_bfloat16 g_Ys_lo[P_ * DM];

__device__ __nv_bfloat16 g_WtR_hi[DM * DM];   // [n][k] = w0R_k[k][n]
__device__ __nv_bfloat16 g_WtR_lo[DM * DM];
__device__ __nv_bfloat16 g_WtI_hi[DM * DM];
__device__ __nv_bfloat16 g_WtI_lo[DM * DM];
__device__ __nv_bfloat16 g_WtS_hi[DM * DM];   // WR + WI
__device__ __nv_bfloat16 g_WtS_lo[DM * DM];

__device__ __forceinline__ int clampi(int i, int sz) { return i < sz ? i : sz - 1; }

// ------------------------- asm helpers -------------------------
__device__ __forceinline__ uint32_t smem_u32(const void* p) {
    uint32_t a;
    asm("{ .reg .u64 t; cvta.to.shared.u64 t, %1; cvt.u32.u64 %0, t; }"
        : "=r"(a) : "l"(p));
    return a;
}
__device__ __forceinline__ void cpasync16(uint32_t s, const void* g) {
    asm volatile("cp.async.cg.shared.global [%0], [%1], 16;" :: "r"(s), "l"(g));
}
__device__ __forceinline__ void cp_commit() { asm volatile("cp.async.commit_group;"); }
__device__ __forceinline__ void cp_wait1()  { asm volatile("cp.async.wait_group 1;"); }
__device__ __forceinline__ void cp_wait0()  { asm volatile("cp.async.wait_group 0;"); }
template <int N>
__device__ __forceinline__ void cp_waitn() {
    asm volatile("cp.async.wait_group %0;" :: "n"(N));
}
__device__ __forceinline__ void ldmx4(uint32_t* r, uint32_t addr) {
    asm volatile("ldmatrix.sync.aligned.m8n8.x4.shared.b16 {%0,%1,%2,%3}, [%4];"
                 : "=r"(r[0]), "=r"(r[1]), "=r"(r[2]), "=r"(r[3]) : "r"(addr));
}
__device__ __forceinline__ void ldmx4t(uint32_t* r, uint32_t addr) {
    asm volatile("ldmatrix.sync.aligned.m8n8.x4.trans.shared.b16 {%0,%1,%2,%3}, [%4];"
                 : "=r"(r[0]), "=r"(r[1]), "=r"(r[2]), "=r"(r[3]) : "r"(addr));
}
#define MMA_BF16(d, a, b0_, b1_)                                               \
    asm volatile(                                                              \
        "mma.sync.aligned.m16n8k16.row.col.f32.bf16.bf16.f32 "                 \
        "{%0,%1,%2,%3}, {%4,%5,%6,%7}, {%8,%9}, {%0,%1,%2,%3};"                \
        : "+f"(d[0]), "+f"(d[1]), "+f"(d[2]), "+f"(d[3])                       \
        : "r"(a[0]), "r"(a[1]), "r"(a[2]), "r"(a[3]), "r"(b0_), "r"(b1_))

__device__ __forceinline__ uint16_t bf_bits(__nv_bfloat16 h) {
    return *reinterpret_cast<uint16_t*>(&h);
}
__device__ __forceinline__ void store_split2(__nv_bfloat16* hi, __nv_bfloat16* lo,
                                             int oi, float a, float b) {
    __nv_bfloat16 h0 = __float2bfloat16(a);
    __nv_bfloat16 h1 = __float2bfloat16(b);
    *(__nv_bfloat162*)&hi[oi] = __nv_bfloat162(h0, h1);
    *(__nv_bfloat162*)&lo[oi] = __nv_bfloat162(
        __float2bfloat16(a - __bfloat162float(h0)),
        __float2bfloat16(b - __bfloat162float(h1)));
}

// ---------------------------------------------------------------------------
// Kernel 0a: split x into bf16 hi/lo
// ---------------------------------------------------------------------------
__global__ void split_x(const float* __restrict__ x, int sx)
{
    int i = blockIdx.x * 256 + threadIdx.x;
    if (i >= P_ * PATCH_) return;
    float a = x[clampi(i, sx)];
    __nv_bfloat16 h = __float2bfloat16(a);
    g_X_hi[i] = h;
    g_X_lo[i] = __float2bfloat16(a - __bfloat162float(h));
}

// ---------------------------------------------------------------------------
// Kernel 0b: transpose + split vR_k, vI_k -> 4 bf16 panels [n][k]
// ---------------------------------------------------------------------------
__global__ void split_vk(const float* __restrict__ VR,
                         const float* __restrict__ VI, int sv)
{
    __shared__ float tR[32][33];
    __shared__ float tI[32][33];
    const int tid = threadIdx.x;
    const int n0 = blockIdx.x * 32, k0 = blockIdx.y * 32;

    #pragma unroll
    for (int i = 0; i < 4; i++) {
        int idx = tid + i * 256;
        int kk = idx >> 5, nn = idx & 31;
        int gi = clampi((k0 + kk) * DM + n0 + nn, sv);
        tR[nn][kk] = VR[gi];
        tI[nn][kk] = VI[gi];
    }
    __syncthreads();

    const int kp  = tid & 15;
    const int nn2 = tid >> 4;
    #pragma unroll
    for (int half = 0; half < 2; half++) {
        int n = nn2 + half * 16;
        int k = kp * 2;
        int oi = (n0 + n) * PATCH_ + k0 + k;
        store_split2(g_VtR_hi, g_VtR_lo, oi, tR[n][k], tR[n][k + 1]);
        store_split2(g_VtI_hi, g_VtI_lo, oi, tI[n][k], tI[n][k + 1]);
    }
}

// ---------------------------------------------------------------------------
// Kernel 1: gemm_v via mma.sync, FUSED 3-term split, DEPTH-4 pipeline:
// all 4 k-tiles issued up front (4 resident buffers, no reuse), waits are
// wait_group 3/2/1/0 — one gmem round-trip total instead of 4 serial ones.
// ---------------------------------------------------------------------------
__global__ void __launch_bounds__(256)
gemm_v_mma(const float* __restrict__ br, const float* __restrict__ bi, int sb)
{
    extern __shared__ __align__(16) char smem[];
    const uint32_t sbase = smem_u32(smem);

    const int tid  = threadIdx.x;
    const int lane = tid & 31, wid = tid >> 5;
    const int g    = lane >> 2, tig = lane & 3;
    const int wm   = wid >> 2, wn = wid & 3;
    const int m0   = blockIdx.y * BM, n0 = blockIdx.x * BN;

    const int a_row_off = (lane & 7) + ((lane >> 3) & 1) * 8;
    const int a_col_off = (lane >> 4) * 8;
    const int b_row_off = (lane & 7) + (lane >> 4) * 8;
    const int b_col_off = ((lane >> 3) & 1) * 8;

    float acc[2][2][2][4] = {};   // [chain][mm][nn][c]

    const int ch_row0 = tid >> 2;
    const int ch_q0   = (tid & 3);
    const int ch_q1   = (tid & 3) + 4;

    // stage panels: 0 X_hi, 1 X_lo, 2 VtR_hi, 3 VtR_lo, 4 VtI_hi, 5 VtI_lo
    auto issue_stage = [&](int t) {
        const int k0 = t * KC;
        const __nv_bfloat16* Gp[6] = {g_X_hi, g_X_lo, g_VtR_hi, g_VtR_lo,
                                      g_VtI_hi, g_VtI_lo};
        const int rowbase[6] = {m0, m0, n0, n0, n0, n0};
        const uint32_t sb_ = sbase + t * VSTAGE;
        #pragma unroll
        for (int p = 0; p < 6; p++) {
            const __nv_bfloat16* gp = Gp[p] + (rowbase[p] + ch_row0) * PATCH_ + k0;
            uint32_t sa = sb_ + p * PANEL + ch_row0 * 144;
            cpasync16(sa + ch_q0 * 16, gp + ch_q0 * 8);
            cpasync16(sa + ch_q1 * 16, gp + ch_q1 * 8);
        }
        cp_commit();
    };

    issue_stage(0);
    issue_stage(1);
    issue_stage(2);
    issue_stage(3);

    #pragma unroll
    for (int t = 0; t < NV_TILES; t++) {
        if      (t == 0) cp_waitn<3>();
        else if (t == 1) cp_waitn<2>();
        else if (t == 2) cp_waitn<1>();
        else             cp_waitn<0>();
        __syncthreads();

        const uint32_t base = sbase + t * VSTAGE;
        #pragma unroll
        for (int kk = 0; kk < KC; kk += 16) {
            uint32_t ah[2][4], al[2][4];
            #pragma unroll
            for (int mm = 0; mm < 2; mm++) {
                int r0 = wm * 32 + mm * 16;
                ldmx4(ah[mm], base + 0 * PANEL + (r0 + a_row_off) * 144 + (kk + a_col_off) * 2);
                ldmx4(al[mm], base + 1 * PANEL + (r0 + a_row_off) * 144 + (kk + a_col_off) * 2);
            }
            #pragma unroll
            for (int c = 0; c < 2; c++) {
                uint32_t bh[4], bl[4];
                int nr = wn * 16;
                ldmx4(bh, base + (2 + c * 2) * PANEL + (nr + b_row_off) * 144 + (kk + b_col_off) * 2);
                ldmx4(bl, base + (3 + c * 2) * PANEL + (nr + b_row_off) * 144 + (kk + b_col_off) * 2);
                #pragma unroll
                for (int mm = 0; mm < 2; mm++)
                    #pragma unroll
                    for (int nn = 0; nn < 2; nn++) {
                        MMA_BF16(acc[c][mm][nn], ah[mm], bh[nn * 2], bh[nn * 2 + 1]);
                        MMA_BF16(acc[c][mm][nn], ah[mm], bl[nn * 2], bl[nn * 2 + 1]);
                        MMA_BF16(acc[c][mm][nn], al[mm], bh[nn * 2], bh[nn * 2 + 1]);
                    }
            }
        }
        // no trailing barrier: each stage has its own buffer, never reused
    }

    // fused epilogue: bias + hi/lo split of vr, vi, vs = vr+vi
    #pragma unroll
    for (int mm = 0; mm < 2; mm++) {
        #pragma unroll
        for (int nn = 0; nn < 2; nn++) {
            int mi = m0 + wm * 32 + mm * 16 + g;
            int ni = n0 + wn * 16 + nn * 8 + tig * 2;
            float b0r = br[clampi(ni, sb)],     b1r = br[clampi(ni + 1, sb)];
            float b0i = bi[clampi(ni, sb)],     b1i = bi[clampi(ni + 1, sb)];
            #pragma unroll
            for (int half = 0; half < 2; half++) {
                int m = mi + half * 8;
                float vr0 = acc[0][mm][nn][half * 2]     + b0r;
                float vr1 = acc[0][mm][nn][half * 2 + 1] + b1r;
                float vi0 = acc[1][mm][nn][half * 2]     + b0i;
                float vi1 = acc[1][mm][nn][half * 2 + 1] + b1i;
                float vs0 = vr0 + vi0, vs1 = vr1 + vi1;
                int oi = m * DM + ni;
                store_split2(g_vr_hi, g_vr_lo, oi, vr0, vr1);
                store_split2(g_vi_hi, g_vi_lo, oi, vi0, vi1);
                store_split2(g_vs_hi, g_vs_lo, oi, vs0, vs1);
            }
        }
    }
}

// ---------------------------------------------------------------------------
// Kernel 2: circulant attention via mma.sync, FUSED split (single K sweep).
// ---------------------------------------------------------------------------
__global__ void __launch_bounds__(256)
circ_att_mma(const float* __restrict__ JR, const float* __restrict__ JI, int sj)
{
    extern __shared__ __align__(16) char smem[];
    const uint32_t sbase = smem_u32(smem);
    uint32_t* pair = (uint32_t*)(smem + 2 * CSTAGE);   // [6][512]

    const int tid  = threadIdx.x;
    const int lane = tid & 31, wid = tid >> 5;
    const int g    = lane >> 2, tig = lane & 3;
    const int wm   = wid >> 2, wn = wid & 3;
    const int h    = blockIdx.y;
    const int s0   = blockIdx.x * 64;

    const int bt_row = (lane & 7) + ((lane >> 3) & 1) * 8;
    const int bt_col = (lane >> 4) * 8;

    // build circulant pair tables: pair[v][t] = (J2v[t], J2v[t+1])
    for (int t = tid; t < 512; t += 256) {
        float jr0 = JR[clampi(((t) & 255) * H_ + h, sj)];
        float jr1 = JR[clampi(((t + 1) & 255) * H_ + h, sj)];
        float ji0 = JI[clampi(((t) & 255) * H_ + h, sj)];
        float ji1 = JI[clampi(((t + 1) & 255) * H_ + h, sj)];
        float v0[3] = {jr0, ji0, jr0 + ji0};
        float v1[3] = {jr1, ji1, jr1 + ji1};
        #pragma unroll
        for (int c = 0; c < 3; c++) {
            __nv_bfloat16 h0 = __float2bfloat16(v0[c]);
            __nv_bfloat16 h1 = __float2bfloat16(v1[c]);
            __nv_bfloat16 l0 = __float2bfloat16(v0[c] - __bfloat162float(h0));
            __nv_bfloat16 l1 = __float2bfloat16(v1[c] - __bfloat162float(h1));
            pair[(c * 2 + 0) * 512 + t] =
                (uint32_t)bf_bits(h0) | ((uint32_t)bf_bits(h1) << 16);
            pair[(c * 2 + 1) * 512 + t] =
                (uint32_t)bf_bits(l0) | ((uint32_t)bf_bits(l1) << 16);
        }
    }

    float acc[3][2][2][4] = {};

    const int ch_row0 = tid >> 2;
    const int ch_q0   = (tid & 3);
    const int ch_q1   = (tid & 3) + 4;

    auto issue_stage = [&](int t) {
        const int k0 = t * KC;
        const __nv_bfloat16* Gp[6] = {g_vr_hi, g_vr_lo, g_vi_hi, g_vi_lo,
                                      g_vs_hi, g_vs_lo};
        const uint32_t sb_ = sbase + (t & 1) * CSTAGE;
        #pragma unroll
        for (int p = 0; p < 6; p++) {
            const __nv_bfloat16* gb = Gp[p] + (k0 + ch_row0) * DM + h * HD;
            uint32_t s = sb_ + p * PANEL + ch_row0 * 144;
            cpasync16(s + ch_q0 * 16, gb + ch_q0 * 8);
            cpasync16(s + ch_q1 * 16, gb + ch_q1 * 8);
        }
        cp_commit();
    };

    __syncthreads();   // pair table ready before mainloop reads it
    issue_stage(0);

    for (int t = 0; t < NC_TILES; t++) {
        const int s = t & 1;
        if (t + 1 < NC_TILES) { issue_stage(t + 1); cp_wait1(); }
        else                  { cp_wait0(); }
        __syncthreads();

        const uint32_t base = sbase + s * CSTAGE;
        #pragma unroll
        for (int kk = 0; kk < KC; kk += 16) {
            const int tbase = s0 + wm * 32 + g + t * 64 + kk + tig * 2;
            #pragma unroll
            for (int c = 0; c < 3; c++) {
                const uint32_t* Ph = &pair[(c * 2 + 0) * 512];
                const uint32_t* Pl = &pair[(c * 2 + 1) * 512];
                uint32_t h0 = Ph[tbase],      h1 = Ph[tbase + 8];
                uint32_t h2 = Ph[tbase + 16], h3 = Ph[tbase + 24];
                uint32_t h4 = Ph[tbase + 32];
                uint32_t l0 = Pl[tbase],      l1 = Pl[tbase + 8];
                uint32_t l2 = Pl[tbase + 16], l3 = Pl[tbase + 24];
                uint32_t l4 = Pl[tbase + 32];
                uint32_t ah0[4] = {h0, h1, h1, h2};
                uint32_t ah1[4] = {h2, h3, h3, h4};
                uint32_t al0[4] = {l0, l1, l1, l2};
                uint32_t al1[4] = {l2, l3, l3, l4};
                uint32_t bh[4], bl[4];
                ldmx4t(bh, base + (c * 2 + 0) * PANEL +
                           (kk + bt_row) * 144 + (wn * 16 + bt_col) * 2);
                ldmx4t(bl, base + (c * 2 + 1) * PANEL +
                           (kk + bt_row) * 144 + (wn * 16 + bt_col) * 2);
                MMA_BF16(acc[c][0][0], ah0, bh[0], bh[1]);
                MMA_BF16(acc[c][0][1], ah0, bh[2], bh[3]);
                MMA_BF16(acc[c][1][0], ah1, bh[0], bh[1]);
                MMA_BF16(acc[c][1][1], ah1, bh[2], bh[3]);
                MMA_BF16(acc[c][0][0], ah0, bl[0], bl[1]);
                MMA_BF16(acc[c][0][1], ah0, bl[2], bl[3]);
                MMA_BF16(acc[c][1][0], ah1, bl[0], bl[1]);
                MMA_BF16(acc[c][1][1], ah1, bl[2], bl[3]);
                MMA_BF16(acc[c][0][0], al0, bh[0], bh[1]);
                MMA_BF16(acc[c][0][1], al0, bh[2], bh[3]);
                MMA_BF16(acc[c][1][0], al1, bh[0], bh[1]);
                MMA_BF16(acc[c][1][1], al1, bh[2], bh[3]);
            }
        }
        __syncthreads();
    }

    // epilogue: Karatsuba combine + split write of 6 Y panels
    #pragma unroll
    for (int mm = 0; mm < 2; mm++) {
        #pragma unroll
        for (int nn = 0; nn < 2; nn++) {
            #pragma unroll
            for (int c2 = 0; c2 < 4; c2++) {
                int m = s0 + wm * 32 + mm * 16 + g + (c2 >> 1) * 8;
                int n = h * HD + wn * 16 + nn * 8 + tig * 2 + (c2 & 1);
                float C1 = acc[0][mm][nn][c2];
                float C2 = acc[1][mm][nn][c2];
                float C3 = acc[2][mm][nn][c2];
                float a  = C1 - C2;
                float b  = C3 - C1 - C2;
                float sm = a + b;
                int idx = m * DM + n;
                __nv_bfloat16 ha = __float2bfloat16(a);
                __nv_bfloat16 hb = __float2bfloat16(b);
                __nv_bfloat16 hs = __float2bfloat16(sm);
                g_Yr_hi[idx] = ha;
                g_Yr_lo[idx] = __float2bfloat16(a - __bfloat162float(ha));
                g_Yi_hi[idx] = hb;
                g_Yi_lo[idx] = __float2bfloat16(b - __bfloat162float(hb));
                g_Ys_hi[idx] = hs;
                g_Ys_lo[idx] = __float2bfloat16(sm - __bfloat162float(hs));
            }
        }
    }
}

// ---------------------------------------------------------------------------
// Kernel 3: fused transpose + split of WR, WI, WR+WI -> 6 bf16 panels [n][k]
// ---------------------------------------------------------------------------
__global__ void split_wt(const float* __restrict__ WR,
                         const float* __restrict__ WI, int sw)
{
    __shared__ float tR[32][33];
    __shared__ float tI[32][33];
    const int tid = threadIdx.x;
    const int n0 = blockIdx.x * 32, k0 = blockIdx.y * 32;

    #pragma unroll
    for (int i = 0; i < 4; i++) {
        int idx = tid + i * 256;
        int kk = idx >> 5, nn = idx & 31;
        int gi = clampi((k0 + kk) * DM + n0 + nn, sw);
        tR[nn][kk] = WR[gi];
        tI[nn][kk] = WI[gi];
    }
    __syncthreads();

    const int kp  = tid & 15;
    const int nn2 = tid >> 4;
    #pragma unroll
    for (int half = 0; half < 2; half++) {
        int n = nn2 + half * 16;
        int k = kp * 2;
        float r0 = tR[n][k],     r1 = tR[n][k + 1];
        float i0 = tI[n][k],     i1 = tI[n][k + 1];
        int oi = (n0 + n) * DM + k0 + k;
        store_split2(g_WtR_hi, g_WtR_lo, oi, r0, r1);
        store_split2(g_WtI_hi, g_WtI_lo, oi, i0, i1);
        store_split2(g_WtS_hi, g_WtS_lo, oi, r0 + i0, r1 + i1);
    }
}

// ---------------------------------------------------------------------------
// Kernel 4: Karatsuba bf16 GEMM, FUSED split (single K sweep of 32 stages).
// Fast-math epilogue (__expf/__logf) to shrink the serialized MUFU tail.
// ---------------------------------------------------------------------------
__global__ void __launch_bounds__(256)
gemm_out_mma(const float* __restrict__ bR, const float* __restrict__ bI, int sb,
             float* __restrict__ out, int out_floats, int mode)
{
    extern __shared__ __align__(16) char smem[];
    const uint32_t sbase = smem_u32(smem);

    const int tid  = threadIdx.x;
    const int lane = tid & 31, wid = tid >> 5;
    const int g    = lane >> 2, tig = lane & 3;
    const int wm   = wid >> 2, wn = wid & 3;
    const int m0   = blockIdx.y * BM, n0 = blockIdx.x * BN;

    const int a_row_off = (lane & 7) + ((lane >> 3) & 1) * 8;
    const int a_col_off = (lane >> 4) * 8;
    const int b_row_off = (lane & 7) + (lane >> 4) * 8;
    const int b_col_off = ((lane >> 3) & 1) * 8;

    float acc[3][2][2][4] = {};

    const int ch_row0 = tid >> 2;
    const int ch_q0   = (tid & 3);
    const int ch_q1   = (tid & 3) + 4;

    // stage panels: chain c -> c*4+0 A_hi, c*4+1 A_lo, c*4+2 B_hi, c*4+3 B_lo
    auto issue_stage = [&](int t) {
        const int k0 = t * KC;
        const __nv_bfloat16* Gp[12] = {
            g_Yr_hi, g_Yr_lo, g_WtR_hi, g_WtR_lo,
            g_Yi_hi, g_Yi_lo, g_WtI_hi, g_WtI_lo,
            g_Ys_hi, g_Ys_lo, g_WtS_hi, g_WtS_lo};
        const uint32_t sb_ = sbase + (t & 1) * STAGE;
        #pragma unroll
        for (int p = 0; p < 12; p++) {
            const int rowbase = (p & 2) ? n0 : m0;   // A panels (bit1=0) use m0
            const __nv_bfloat16* gp = Gp[p] + (rowbase + ch_row0) * DM + k0;
            uint32_t sa = sb_ + p * PANEL + ch_row0 * 144;
            cpasync16(sa + ch_q0 * 16, gp + ch_q0 * 8);
            cpasync16(sa + ch_q1 * 16, gp + ch_q1 * 8);
        }
        cp_commit();
    };

    issue_stage(0);

    for (int t = 0; t < N_TILES; t++) {
        const int s = t & 1;
        if (t + 1 < N_TILES) { issue_stage(t + 1); cp_wait1(); }
        else                 { cp_wait0(); }
        __syncthreads();

        const uint32_t base = sbase + s * STAGE;
        #pragma unroll
        for (int kk = 0; kk < KC; kk += 16) {
            #pragma unroll
            for (int c = 0; c < 3; c++) {
                uint32_t ah[2][4], al[2][4];
                #pragma unroll
                for (int mm = 0; mm < 2; mm++) {
                    int r0 = wm * 32 + mm * 16;
                    ldmx4(ah[mm], base + (c * 4 + 0) * PANEL +
                                  (r0 + a_row_off) * 144 + (kk + a_col_off) * 2);
                    ldmx4(al[mm], base + (c * 4 + 1) * PANEL +
                                  (r0 + a_row_off) * 144 + (kk + a_col_off) * 2);
                }
                uint32_t bh[4], bl[4];
                {
                    int nr = wn * 16;
                    ldmx4(bh, base + (c * 4 + 2) * PANEL +
                              (nr + b_row_off) * 144 + (kk + b_col_off) * 2);
                    ldmx4(bl, base + (c * 4 + 3) * PANEL +
                              (nr + b_row_off) * 144 + (kk + b_col_off) * 2);
                }
                #pragma unroll
                for (int mm = 0; mm < 2; mm++)
                    #pragma unroll
                    for (int nn = 0; nn < 2; nn++) {
                        MMA_BF16(acc[c][mm][nn], ah[mm], bh[nn * 2], bh[nn * 2 + 1]);
                        MMA_BF16(acc[c][mm][nn], ah[mm], bl[nn * 2], bl[nn * 2 + 1]);
                        MMA_BF16(acc[c][mm][nn], al[mm], bh[nn * 2], bh[nn * 2 + 1]);
                    }
            }
        }
        __syncthreads();
    }

    const float LN2 = 0.69314718055994531f;
    #pragma unroll
    for (int mm = 0; mm < 2; mm++) {
        #pragma unroll
        for (int nn = 0; nn < 2; nn++) {
            int mi = m0 + wm * 32 + mm * 16 + g;
            int ni = n0 + wn * 16 + nn * 8 + tig * 2;
            #pragma unroll
            for (int c = 0; c < 4; c++) {
                int m = mi + (c >> 1) * 8;
                int n = ni + (c & 1);
                float C1 = acc[0][mm][nn][c];
                float C2 = acc[1][mm][nn][c];
                float C3 = acc[2][mm][nn][c];
                float re = C1 - C2 + bR[clampi(n, sb)];
                float im = C3 - C1 - C2 + bI[clampi(n, sb)];
                float sgn = (__float_as_int(re) < 0) ? -1.0f : 1.0f;
                float a = re * sgn;
                float b = im * sgn;
                float e = __expf(-2.0f * a);
                float s2, c2;
                __sincosf(2.0f * b, &s2, &c2);
                float wr = e * c2, wi = -e * s2;
                float u = 1.0f + wr;
                float res_re = a + 0.5f * __logf(u * u + wi * wi) - LN2;
                if (mode == 0) {
                    int fi = m * DM + n;
                    if (fi < out_floats) out[fi] = res_re;
                } else {
                    float res_im = b + atan2f(wi, u);
                    int fi = (m * DM + n) * 2;
                    if (fi < out_floats)     out[fi]     = res_re;
                    if (fi + 1 < out_floats) out[fi + 1] = res_im;
                }
            }
        }
    }
}

// ---------------------------------------------------------------------------
extern "C" void kernel_launch(void* const* d_in, const int* in_sizes, int n_in,
                              void* d_out, int out_size)
{
    const float* x = nullptr;   int sx = 0;
    const float* vk[2] = {};    int svk = 0;
    const float* J[2]  = {};    int sj = 0;
    const float* wk[2] = {};    int swk = 0;
    const float* bs[4] = {};    int sb = 0;
    int nvk = 0, nj = 0, nwk = 0, nb = 0;

    for (int i = 0; i < n_in; i++) {
        const float* p = (const float*)d_in[i];
        int sz = in_sizes[i];
        if      (sz == 65536   && !x)      { x = p; sx = sz; }
        else if (sz == 524288  && nvk < 2) { vk[nvk++] = p; svk = sz; }
        else if (sz == 8192    && nj  < 2) { J[nj++]   = p; sj  = sz; }
        else if (sz == 4194304 && nwk < 2) { wk[nwk++] = p; swk = sz; }
        else if (sz == 2048    && nb  < 4) { bs[nb++]  = p; sb  = sz; }
    }

    if (!(x && nvk == 2 && nj == 2 && nwk == 2 && nb == 4)) {
        if (n_in < 11) return;
        x     = (const float*)d_in[0];  sx  = in_sizes[0];
        vk[0] = (const float*)d_in[1];  bs[0] = (const float*)d_in[2];
        vk[1] = (const float*)d_in[3];  bs[1] = (const float*)d_in[4];
        J[0]  = (const float*)d_in[5];  J[1]  = (const float*)d_in[6];
        wk[0] = (const float*)d_in[7];  bs[2] = (const float*)d_in[8];
        wk[1] = (const float*)d_in[9];  bs[3] = (const float*)d_in[10];
        svk = in_sizes[1]; sj = in_sizes[5]; swk = in_sizes[7]; sb = in_sizes[2];
    }

    int mode       = (out_size == 2 * P_ * DM) ? 1 : 0;
    int out_floats = out_size;

    static bool attr_done = false;
    static cudaStream_t s_side = nullptr;
    static cudaEvent_t ev_fork = nullptr, ev_join = nullptr;
    if (!attr_done) {
        cudaFuncSetAttribute(gemm_out_mma,
                             cudaFuncAttributeMaxDynamicSharedMemorySize, SMEM_GEMM);
        cudaFuncSetAttribute(gemm_v_mma,
                             cudaFuncAttributeMaxDynamicSharedMemorySize, SMEM_V);
        cudaFuncSetAttribute(circ_att_mma,
                             cudaFuncAttributeMaxDynamicSharedMemorySize, SMEM_C);
        cudaStreamCreateWithFlags(&s_side, cudaStreamNonBlocking);
        cudaEventCreateWithFlags(&ev_fork, cudaEventDisableTiming);
        cudaEventCreateWithFlags(&ev_join, cudaEventDisableTiming);
        attr_done = true;
    }

    // fork: split_wt (independent of the v/att chain) runs on side stream
    cudaEventRecord(ev_fork, 0);
    cudaStreamWaitEvent(s_side, ev_fork, 0);
    split_wt<<<dim3(DM / 32, DM / 32), 256, 0, s_side>>>(wk[0], wk[1], swk);
    cudaEventRecord(ev_join, s_side);

    // main chain (default stream)
    split_x   <<<(P_ * PATCH_ + 255) / 256, 256>>>(x, sx);
    split_vk  <<<dim3(DM / 32, PATCH_ / 32), 256>>>(vk[0], vk[1], svk);
    gemm_v_mma<<<dim3(DM / BN, P_ / BM), 256, SMEM_V>>>(bs[0], bs[1], sb);
    circ_att_mma<<<dim3(P_ / 64, H_), 256, SMEM_C>>>(J[0], J[1], sj);

    // join: gemm_out needs both Y panels (chain) and W panels (side)
    cudaStreamWaitEvent(0, ev_join, 0);
    gemm_out_mma<<<dim3(DM / BN, P_ / BM), 256, SMEM_GEMM>>>(
        bs[2], bs[3], sb, (float*)d_out, out_floats, mode);
}

// round 14
// speedup vs baseline: 2.0733x; 1.2646x over previous
#include <cuda_runtime.h>
#include <cuda_bf16.h>
#include <cuda_fp16.h>
#include <cstdint>

namespace {
constexpr int P_     = 256;
constexpr int H_     = 32;
constexpr int DM     = 2048;
constexpr int HD     = 64;
constexpr int PATCH_ = 256;

constexpr int BM = 64;
constexpr int BN = 64;
constexpr int KC = 64;                  // k per smem stage
constexpr int N_TILES  = DM / KC;       // gemm_out: 32 stages
constexpr int NV_TILES = PATCH_ / KC;   // gemm_v:   4 stages
constexpr int NC_TILES = P_ / KC;       // circ_att: 4 stages
constexpr int PADK  = 72;               // 16-bit stride: 144B (conflict-free)
constexpr int PANEL = BM * PADK * 2;    // 9216 B

// gemm_out: 3 chains x (Y16, Wh, Wl) = 9 panels / stage (fp16 2-term)
constexpr int STAGE = 9 * PANEL;        // 82944 B
constexpr int SMEM_GEMM = 2 * STAGE;    // 165888 B
// gemm_v: X_hi, X_lo, VtR_hi, VtR_lo, VtI_hi, VtI_lo = 6 panels; depth-4
constexpr int VSTAGE = 6 * PANEL;       // 55296 B
constexpr int SMEM_V  = 4 * VSTAGE;     // 221184 B
// circ_att: 3 chains x (B_hi, B_lo) = 6 panels + pair tables
constexpr int CSTAGE = 6 * PANEL;       // 55296 B
constexpr int SMEM_C = 2 * CSTAGE + 6 * 512 * 4;  // 122880 B

constexpr float WSCALE   = 64.0f;
constexpr float WSCALE_I = 1.0f / 64.0f;
}

// ------------------------- device scratch (static) -------------------------
__device__ __nv_bfloat16 g_X_hi[P_ * PATCH_];
__device__ __nv_bfloat16 g_X_lo[P_ * PATCH_];
__device__ __nv_bfloat16 g_VtR_hi[DM * PATCH_];   // [n][k] = vR_k[k][n]
__device__ __nv_bfloat16 g_VtR_lo[DM * PATCH_];
__device__ __nv_bfloat16 g_VtI_hi[DM * PATCH_];
__device__ __nv_bfloat16 g_VtI_lo[DM * PATCH_];

// v panels in natural [q][DM] layout (written by gemm_v_mma epilogue)
__device__ __nv_bfloat16 g_vr_hi[P_ * DM];
__device__ __nv_bfloat16 g_vr_lo[P_ * DM];
__device__ __nv_bfloat16 g_vi_hi[P_ * DM];
__device__ __nv_bfloat16 g_vi_lo[P_ * DM];
__device__ __nv_bfloat16 g_vs_hi[P_ * DM];
__device__ __nv_bfloat16 g_vs_lo[P_ * DM];

// Y panels as single fp16 (A operand of fp16 2-term gemm_out)
__device__ __half g_Y16r[P_ * DM];
__device__ __half g_Y16i[P_ * DM];
__device__ __half g_Y16s[P_ * DM];

// W panels: (w * 64) split into fp16 hi/lo, [n][k] layout
__device__ __half g_W16R_h[DM * DM];
__device__ __half g_W16R_l[DM * DM];
__device__ __half g_W16I_h[DM * DM];
__device__ __half g_W16I_l[DM * DM];
__device__ __half g_W16S_h[DM * DM];
__device__ __half g_W16S_l[DM * DM];

__device__ __forceinline__ int clampi(int i, int sz) { return i < sz ? i : sz - 1; }

// ------------------------- asm helpers -------------------------
__device__ __forceinline__ uint32_t smem_u32(const void* p) {
    uint32_t a;
    asm("{ .reg .u64 t; cvta.to.shared.u64 t, %1; cvt.u32.u64 %0, t; }"
        : "=r"(a) : "l"(p));
    return a;
}
__device__ __forceinline__ void cpasync16(uint32_t s, const void* g) {
    asm volatile("cp.async.cg.shared.global [%0], [%1], 16;" :: "r"(s), "l"(g));
}
__device__ __forceinline__ void cp_commit() { asm volatile("cp.async.commit_group;"); }
__device__ __forceinline__ void cp_wait1()  { asm volatile("cp.async.wait_group 1;"); }
__device__ __forceinline__ void cp_wait0()  { asm volatile("cp.async.wait_group 0;"); }
template <int N>
__device__ __forceinline__ void cp_waitn() {
    asm volatile("cp.async.wait_group %0;" :: "n"(N));
}
__device__ __forceinline__ void ldmx4(uint32_t* r, uint32_t addr) {
    asm volatile("ldmatrix.sync.aligned.m8n8.x4.shared.b16 {%0,%1,%2,%3}, [%4];"
                 : "=r"(r[0]), "=r"(r[1]), "=r"(r[2]), "=r"(r[3]) : "r"(addr));
}
__device__ __forceinline__ void ldmx4t(uint32_t* r, uint32_t addr) {
    asm volatile("ldmatrix.sync.aligned.m8n8.x4.trans.shared.b16 {%0,%1,%2,%3}, [%4];"
                 : "=r"(r[0]), "=r"(r[1]), "=r"(r[2]), "=r"(r[3]) : "r"(addr));
}
#define MMA_BF16(d, a, b0_, b1_)                                               \
    asm volatile(                                                              \
        "mma.sync.aligned.m16n8k16.row.col.f32.bf16.bf16.f32 "                 \
        "{%0,%1,%2,%3}, {%4,%5,%6,%7}, {%8,%9}, {%0,%1,%2,%3};"                \
        : "+f"(d[0]), "+f"(d[1]), "+f"(d[2]), "+f"(d[3])                       \
        : "r"(a[0]), "r"(a[1]), "r"(a[2]), "r"(a[3]), "r"(b0_), "r"(b1_))
#define MMA_F16(d, a, b0_, b1_)                                                \
    asm volatile(                                                              \
        "mma.sync.aligned.m16n8k16.row.col.f32.f16.f16.f32 "                   \
        "{%0,%1,%2,%3}, {%4,%5,%6,%7}, {%8,%9}, {%0,%1,%2,%3};"                \
        : "+f"(d[0]), "+f"(d[1]), "+f"(d[2]), "+f"(d[3])                       \
        : "r"(a[0]), "r"(a[1]), "r"(a[2]), "r"(a[3]), "r"(b0_), "r"(b1_))

__device__ __forceinline__ uint16_t bf_bits(__nv_bfloat16 h) {
    return *reinterpret_cast<uint16_t*>(&h);
}
__device__ __forceinline__ void store_split2(__nv_bfloat16* hi, __nv_bfloat16* lo,
                                             int oi, float a, float b) {
    __nv_bfloat16 h0 = __float2bfloat16(a);
    __nv_bfloat16 h1 = __float2bfloat16(b);
    *(__nv_bfloat162*)&hi[oi] = __nv_bfloat162(h0, h1);
    *(__nv_bfloat162*)&lo[oi] = __nv_bfloat162(
        __float2bfloat16(a - __bfloat162float(h0)),
        __float2bfloat16(b - __bfloat162float(h1)));
}
__device__ __forceinline__ void store_split2h(__half* hi, __half* lo,
                                              int oi, float a, float b) {
    __half h0 = __float2half_rn(a);
    __half h1 = __float2half_rn(b);
    *(__half2*)&hi[oi] = __halves2half2(h0, h1);
    *(__half2*)&lo[oi] = __halves2half2(
        __float2half_rn(a - __half2float(h0)),
        __float2half_rn(b - __half2float(h1)));
}

// ---------------------------------------------------------------------------
// Kernel 0a: split x into bf16 hi/lo
// ---------------------------------------------------------------------------
__global__ void split_x(const float* __restrict__ x, int sx)
{
    int i = blockIdx.x * 256 + threadIdx.x;
    if (i >= P_ * PATCH_) return;
    float a = x[clampi(i, sx)];
    __nv_bfloat16 h = __float2bfloat16(a);
    g_X_hi[i] = h;
    g_X_lo[i] = __float2bfloat16(a - __bfloat162float(h));
}

// ---------------------------------------------------------------------------
// Kernel 0b: transpose + split vR_k, vI_k -> 4 bf16 panels [n][k]
// ---------------------------------------------------------------------------
__global__ void split_vk(const float* __restrict__ VR,
                         const float* __restrict__ VI, int sv)
{
    __shared__ float tR[32][33];
    __shared__ float tI[32][33];
    const int tid = threadIdx.x;
    const int n0 = blockIdx.x * 32, k0 = blockIdx.y * 32;

    #pragma unroll
    for (int i = 0; i < 4; i++) {
        int idx = tid + i * 256;
        int kk = idx >> 5, nn = idx & 31;
        int gi = clampi((k0 + kk) * DM + n0 + nn, sv);
        tR[nn][kk] = VR[gi];
        tI[nn][kk] = VI[gi];
    }
    __syncthreads();

    const int kp  = tid & 15;
    const int nn2 = tid >> 4;
    #pragma unroll
    for (int half = 0; half < 2; half++) {
        int n = nn2 + half * 16;
        int k = kp * 2;
        int oi = (n0 + n) * PATCH_ + k0 + k;
        store_split2(g_VtR_hi, g_VtR_lo, oi, tR[n][k], tR[n][k + 1]);
        store_split2(g_VtI_hi, g_VtI_lo, oi, tI[n][k], tI[n][k + 1]);
    }
}

// ---------------------------------------------------------------------------
// Kernel 1: gemm_v via mma.sync, FUSED 3-term split, DEPTH-4 pipeline.
// ---------------------------------------------------------------------------
__global__ void __launch_bounds__(256)
gemm_v_mma(const float* __restrict__ br, const float* __restrict__ bi, int sb)
{
    extern __shared__ __align__(16) char smem[];
    const uint32_t sbase = smem_u32(smem);

    const int tid  = threadIdx.x;
    const int lane = tid & 31, wid = tid >> 5;
    const int g    = lane >> 2, tig = lane & 3;
    const int wm   = wid >> 2, wn = wid & 3;
    const int m0   = blockIdx.y * BM, n0 = blockIdx.x * BN;

    const int a_row_off = (lane & 7) + ((lane >> 3) & 1) * 8;
    const int a_col_off = (lane >> 4) * 8;
    const int b_row_off = (lane & 7) + (lane >> 4) * 8;
    const int b_col_off = ((lane >> 3) & 1) * 8;

    float acc[2][2][2][4] = {};   // [chain][mm][nn][c]

    const int ch_row0 = tid >> 2;
    const int ch_q0   = (tid & 3);
    const int ch_q1   = (tid & 3) + 4;

    auto issue_stage = [&](int t) {
        const int k0 = t * KC;
        const __nv_bfloat16* Gp[6] = {g_X_hi, g_X_lo, g_VtR_hi, g_VtR_lo,
                                      g_VtI_hi, g_VtI_lo};
        const int rowbase[6] = {m0, m0, n0, n0, n0, n0};
        const uint32_t sb_ = sbase + t * VSTAGE;
        #pragma unroll
        for (int p = 0; p < 6; p++) {
            const __nv_bfloat16* gp = Gp[p] + (rowbase[p] + ch_row0) * PATCH_ + k0;
            uint32_t sa = sb_ + p * PANEL + ch_row0 * 144;
            cpasync16(sa + ch_q0 * 16, gp + ch_q0 * 8);
            cpasync16(sa + ch_q1 * 16, gp + ch_q1 * 8);
        }
        cp_commit();
    };

    issue_stage(0);
    issue_stage(1);
    issue_stage(2);
    issue_stage(3);

    #pragma unroll
    for (int t = 0; t < NV_TILES; t++) {
        if      (t == 0) cp_waitn<3>();
        else if (t == 1) cp_waitn<2>();
        else if (t == 2) cp_waitn<1>();
        else             cp_waitn<0>();
        __syncthreads();

        const uint32_t base = sbase + t * VSTAGE;
        #pragma unroll
        for (int kk = 0; kk < KC; kk += 16) {
            uint32_t ah[2][4], al[2][4];
            #pragma unroll
            for (int mm = 0; mm < 2; mm++) {
                int r0 = wm * 32 + mm * 16;
                ldmx4(ah[mm], base + 0 * PANEL + (r0 + a_row_off) * 144 + (kk + a_col_off) * 2);
                ldmx4(al[mm], base + 1 * PANEL + (r0 + a_row_off) * 144 + (kk + a_col_off) * 2);
            }
            #pragma unroll
            for (int c = 0; c < 2; c++) {
                uint32_t bh[4], bl[4];
                int nr = wn * 16;
                ldmx4(bh, base + (2 + c * 2) * PANEL + (nr + b_row_off) * 144 + (kk + b_col_off) * 2);
                ldmx4(bl, base + (3 + c * 2) * PANEL + (nr + b_row_off) * 144 + (kk + b_col_off) * 2);
                #pragma unroll
                for (int mm = 0; mm < 2; mm++)
                    #pragma unroll
                    for (int nn = 0; nn < 2; nn++) {
                        MMA_BF16(acc[c][mm][nn], ah[mm], bh[nn * 2], bh[nn * 2 + 1]);
                        MMA_BF16(acc[c][mm][nn], ah[mm], bl[nn * 2], bl[nn * 2 + 1]);
                        MMA_BF16(acc[c][mm][nn], al[mm], bh[nn * 2], bh[nn * 2 + 1]);
                    }
            }
        }
    }

    // fused epilogue: bias + hi/lo split of vr, vi, vs = vr+vi
    #pragma unroll
    for (int mm = 0; mm < 2; mm++) {
        #pragma unroll
        for (int nn = 0; nn < 2; nn++) {
            int mi = m0 + wm * 32 + mm * 16 + g;
            int ni = n0 + wn * 16 + nn * 8 + tig * 2;
            float b0r = br[clampi(ni, sb)],     b1r = br[clampi(ni + 1, sb)];
            float b0i = bi[clampi(ni, sb)],     b1i = bi[clampi(ni + 1, sb)];
            #pragma unroll
            for (int half = 0; half < 2; half++) {
                int m = mi + half * 8;
                float vr0 = acc[0][mm][nn][half * 2]     + b0r;
                float vr1 = acc[0][mm][nn][half * 2 + 1] + b1r;
                float vi0 = acc[1][mm][nn][half * 2]     + b0i;
                float vi1 = acc[1][mm][nn][half * 2 + 1] + b1i;
                float vs0 = vr0 + vi0, vs1 = vr1 + vi1;
                int oi = m * DM + ni;
                store_split2(g_vr_hi, g_vr_lo, oi, vr0, vr1);
                store_split2(g_vi_hi, g_vi_lo, oi, vi0, vi1);
                store_split2(g_vs_hi, g_vs_lo, oi, vs0, vs1);
            }
        }
    }
}

// ---------------------------------------------------------------------------
// Kernel 2: circulant attention via mma.sync, FUSED split (single K sweep).
// Epilogue now writes Y as single fp16 panels (A operand of fp16-2term gemm).
// ---------------------------------------------------------------------------
__global__ void __launch_bounds__(256)
circ_att_mma(const float* __restrict__ JR, const float* __restrict__ JI, int sj)
{
    extern __shared__ __align__(16) char smem[];
    const uint32_t sbase = smem_u32(smem);
    uint32_t* pair = (uint32_t*)(smem + 2 * CSTAGE);   // [6][512]

    const int tid  = threadIdx.x;
    const int lane = tid & 31, wid = tid >> 5;
    const int g    = lane >> 2, tig = lane & 3;
    const int wm   = wid >> 2, wn = wid & 3;
    const int h    = blockIdx.y;
    const int s0   = blockIdx.x * 64;

    const int bt_row = (lane & 7) + ((lane >> 3) & 1) * 8;
    const int bt_col = (lane >> 4) * 8;

    for (int t = tid; t < 512; t += 256) {
        float jr0 = JR[clampi(((t) & 255) * H_ + h, sj)];
        float jr1 = JR[clampi(((t + 1) & 255) * H_ + h, sj)];
        float ji0 = JI[clampi(((t) & 255) * H_ + h, sj)];
        float ji1 = JI[clampi(((t + 1) & 255) * H_ + h, sj)];
        float v0[3] = {jr0, ji0, jr0 + ji0};
        float v1[3] = {jr1, ji1, jr1 + ji1};
        #pragma unroll
        for (int c = 0; c < 3; c++) {
            __nv_bfloat16 h0 = __float2bfloat16(v0[c]);
            __nv_bfloat16 h1 = __float2bfloat16(v1[c]);
            __nv_bfloat16 l0 = __float2bfloat16(v0[c] - __bfloat162float(h0));
            __nv_bfloat16 l1 = __float2bfloat16(v1[c] - __bfloat162float(h1));
            pair[(c * 2 + 0) * 512 + t] =
                (uint32_t)bf_bits(h0) | ((uint32_t)bf_bits(h1) << 16);
            pair[(c * 2 + 1) * 512 + t] =
                (uint32_t)bf_bits(l0) | ((uint32_t)bf_bits(l1) << 16);
        }
    }

    float acc[3][2][2][4] = {};

    const int ch_row0 = tid >> 2;
    const int ch_q0   = (tid & 3);
    const int ch_q1   = (tid & 3) + 4;

    auto issue_stage = [&](int t) {
        const int k0 = t * KC;
        const __nv_bfloat16* Gp[6] = {g_vr_hi, g_vr_lo, g_vi_hi, g_vi_lo,
                                      g_vs_hi, g_vs_lo};
        const uint32_t sb_ = sbase + (t & 1) * CSTAGE;
        #pragma unroll
        for (int p = 0; p < 6; p++) {
            const __nv_bfloat16* gb = Gp[p] + (k0 + ch_row0) * DM + h * HD;
            uint32_t s = sb_ + p * PANEL + ch_row0 * 144;
            cpasync16(s + ch_q0 * 16, gb + ch_q0 * 8);
            cpasync16(s + ch_q1 * 16, gb + ch_q1 * 8);
        }
        cp_commit();
    };

    __syncthreads();
    issue_stage(0);

    for (int t = 0; t < NC_TILES; t++) {
        const int s = t & 1;
        if (t + 1 < NC_TILES) { issue_stage(t + 1); cp_wait1(); }
        else                  { cp_wait0(); }
        __syncthreads();

        const uint32_t base = sbase + s * CSTAGE;
        #pragma unroll
        for (int kk = 0; kk < KC; kk += 16) {
            const int tbase = s0 + wm * 32 + g + t * 64 + kk + tig * 2;
            #pragma unroll
            for (int c = 0; c < 3; c++) {
                const uint32_t* Ph = &pair[(c * 2 + 0) * 512];
                const uint32_t* Pl = &pair[(c * 2 + 1) * 512];
                uint32_t h0 = Ph[tbase],      h1 = Ph[tbase + 8];
                uint32_t h2 = Ph[tbase + 16], h3 = Ph[tbase + 24];
                uint32_t h4 = Ph[tbase + 32];
                uint32_t l0 = Pl[tbase],      l1 = Pl[tbase + 8];
                uint32_t l2 = Pl[tbase + 16], l3 = Pl[tbase + 24];
                uint32_t l4 = Pl[tbase + 32];
                uint32_t ah0[4] = {h0, h1, h1, h2};
                uint32_t ah1[4] = {h2, h3, h3, h4};
                uint32_t al0[4] = {l0, l1, l1, l2};
                uint32_t al1[4] = {l2, l3, l3, l4};
                uint32_t bh[4], bl[4];
                ldmx4t(bh, base + (c * 2 + 0) * PANEL +
                           (kk + bt_row) * 144 + (wn * 16 + bt_col) * 2);
                ldmx4t(bl, base + (c * 2 + 1) * PANEL +
                           (kk + bt_row) * 144 + (wn * 16 + bt_col) * 2);
                MMA_BF16(acc[c][0][0], ah0, bh[0], bh[1]);
                MMA_BF16(acc[c][0][1], ah0, bh[2], bh[3]);
                MMA_BF16(acc[c][1][0], ah1, bh[0], bh[1]);
                MMA_BF16(acc[c][1][1], ah1, bh[2], bh[3]);
                MMA_BF16(acc[c][0][0], ah0, bl[0], bl[1]);
                MMA_BF16(acc[c][0][1], ah0, bl[2], bl[3]);
                MMA_BF16(acc[c][1][0], ah1, bl[0], bl[1]);
                MMA_BF16(acc[c][1][1], ah1, bl[2], bl[3]);
                MMA_BF16(acc[c][0][0], al0, bh[0], bh[1]);
                MMA_BF16(acc[c][0][1], al0, bh[2], bh[3]);
                MMA_BF16(acc[c][1][0], al1, bh[0], bh[1]);
                MMA_BF16(acc[c][1][1], al1, bh[2], bh[3]);
            }
        }
        __syncthreads();
    }

    // epilogue: Karatsuba combine + single-fp16 write of 3 Y panels
    #pragma unroll
    for (int mm = 0; mm < 2; mm++) {
        #pragma unroll
        for (int nn = 0; nn < 2; nn++) {
            #pragma unroll
            for (int c2 = 0; c2 < 4; c2++) {
                int m = s0 + wm * 32 + mm * 16 + g + (c2 >> 1) * 8;
                int n = h * HD + wn * 16 + nn * 8 + tig * 2 + (c2 & 1);
                float C1 = acc[0][mm][nn][c2];
                float C2 = acc[1][mm][nn][c2];
                float C3 = acc[2][mm][nn][c2];
                float a  = C1 - C2;
                float b  = C3 - C1 - C2;
                int idx = m * DM + n;
                g_Y16r[idx] = __float2half_rn(a);
                g_Y16i[idx] = __float2half_rn(b);
                g_Y16s[idx] = __float2half_rn(a + b);
            }
        }
    }
}

// ---------------------------------------------------------------------------
// Kernel 3: transpose + scale(x64) + fp16 hi/lo split of WR, WI, WR+WI
// ---------------------------------------------------------------------------
__global__ void split_wt(const float* __restrict__ WR,
                         const float* __restrict__ WI, int sw)
{
    __shared__ float tR[32][33];
    __shared__ float tI[32][33];
    const int tid = threadIdx.x;
    const int n0 = blockIdx.x * 32, k0 = blockIdx.y * 32;

    #pragma unroll
    for (int i = 0; i < 4; i++) {
        int idx = tid + i * 256;
        int kk = idx >> 5, nn = idx & 31;
        int gi = clampi((k0 + kk) * DM + n0 + nn, sw);
        tR[nn][kk] = WR[gi];
        tI[nn][kk] = WI[gi];
    }
    __syncthreads();

    const int kp  = tid & 15;
    const int nn2 = tid >> 4;
    #pragma unroll
    for (int half = 0; half < 2; half++) {
        int n = nn2 + half * 16;
        int k = kp * 2;
        float r0 = tR[n][k] * WSCALE,     r1 = tR[n][k + 1] * WSCALE;
        float i0 = tI[n][k] * WSCALE,     i1 = tI[n][k + 1] * WSCALE;
        int oi = (n0 + n) * DM + k0 + k;
        store_split2h(g_W16R_h, g_W16R_l, oi, r0, r1);
        store_split2h(g_W16I_h, g_W16I_l, oi, i0, i1);
        store_split2h(g_W16S_h, g_W16S_l, oi, r0 + i0, r1 + i1);
    }
}

// ---------------------------------------------------------------------------
// Kernel 4: Karatsuba fp16 2-TERM GEMM (A=Y fp16 single, B=W*64 fp16 hi/lo).
//   Per k-step per chain: A*Bh + A*Bl (2 MMA combos). 9 panels / stage.
// ---------------------------------------------------------------------------
__global__ void __launch_bounds__(256)
gemm_out_mma(const float* __restrict__ bR, const float* __restrict__ bI, int sb,
             float* __restrict__ out, int out_floats, int mode)
{
    extern __shared__ __align__(16) char smem[];
    const uint32_t sbase = smem_u32(smem);

    const int tid  = threadIdx.x;
    const int lane = tid & 31, wid = tid >> 5;
    const int g    = lane >> 2, tig = lane & 3;
    const int wm   = wid >> 2, wn = wid & 3;
    const int m0   = blockIdx.y * BM, n0 = blockIdx.x * BN;

    const int a_row_off = (lane & 7) + ((lane >> 3) & 1) * 8;
    const int a_col_off = (lane >> 4) * 8;
    const int b_row_off = (lane & 7) + (lane >> 4) * 8;
    const int b_col_off = ((lane >> 3) & 1) * 8;

    float acc[3][2][2][4] = {};

    const int ch_row0 = tid >> 2;
    const int ch_q0   = (tid & 3);
    const int ch_q1   = (tid & 3) + 4;

    // stage panels: chain c -> c*3+0 Y16 (A), c*3+1 Wh, c*3+2 Wl
    auto issue_stage = [&](int t) {
        const int k0 = t * KC;
        const __half* Gp[9] = {
            g_Y16r, g_W16R_h, g_W16R_l,
            g_Y16i, g_W16I_h, g_W16I_l,
            g_Y16s, g_W16S_h, g_W16S_l};
        const uint32_t sb_ = sbase + (t & 1) * STAGE;
        #pragma unroll
        for (int p = 0; p < 9; p++) {
            const int rowbase = (p % 3 == 0) ? m0 : n0;
            const __half* gp = Gp[p] + (rowbase + ch_row0) * DM + k0;
            uint32_t sa = sb_ + p * PANEL + ch_row0 * 144;
            cpasync16(sa + ch_q0 * 16, gp + ch_q0 * 8);
            cpasync16(sa + ch_q1 * 16, gp + ch_q1 * 8);
        }
        cp_commit();
    };

    issue_stage(0);

    for (int t = 0; t < N_TILES; t++) {
        const int s = t & 1;
        if (t + 1 < N_TILES) { issue_stage(t + 1); cp_wait1(); }
        else                 { cp_wait0(); }
        __syncthreads();

        const uint32_t base = sbase + s * STAGE;
        #pragma unroll
        for (int kk = 0; kk < KC; kk += 16) {
            #pragma unroll
            for (int c = 0; c < 3; c++) {
                uint32_t a[2][4];
                #pragma unroll
                for (int mm = 0; mm < 2; mm++) {
                    int r0 = wm * 32 + mm * 16;
                    ldmx4(a[mm], base + (c * 3 + 0) * PANEL +
                                 (r0 + a_row_off) * 144 + (kk + a_col_off) * 2);
                }
                uint32_t bh[4], bl[4];
                {
                    int nr = wn * 16;
                    ldmx4(bh, base + (c * 3 + 1) * PANEL +
                              (nr + b_row_off) * 144 + (kk + b_col_off) * 2);
                    ldmx4(bl, base + (c * 3 + 2) * PANEL +
                              (nr + b_row_off) * 144 + (kk + b_col_off) * 2);
                }
                #pragma unroll
                for (int mm = 0; mm < 2; mm++)
                    #pragma unroll
                    for (int nn = 0; nn < 2; nn++) {
                        MMA_F16(acc[c][mm][nn], a[mm], bh[nn * 2], bh[nn * 2 + 1]);
                        MMA_F16(acc[c][mm][nn], a[mm], bl[nn * 2], bl[nn * 2 + 1]);
                    }
            }
        }
        __syncthreads();
    }

    const float LN2 = 0.69314718055994531f;
    #pragma unroll
    for (int mm = 0; mm < 2; mm++) {
        #pragma unroll
        for (int nn = 0; nn < 2; nn++) {
            int mi = m0 + wm * 32 + mm * 16 + g;
            int ni = n0 + wn * 16 + nn * 8 + tig * 2;
            #pragma unroll
            for (int c = 0; c < 4; c++) {
                int m = mi + (c >> 1) * 8;
                int n = ni + (c & 1);
                float C1 = acc[0][mm][nn][c];
                float C2 = acc[1][mm][nn][c];
                float C3 = acc[2][mm][nn][c];
                float re = (C1 - C2) * WSCALE_I + bR[clampi(n, sb)];
                float im = (C3 - C1 - C2) * WSCALE_I + bI[clampi(n, sb)];
                float sgn = (__float_as_int(re) < 0) ? -1.0f : 1.0f;
                float a = re * sgn;
                float b = im * sgn;
                float e = __expf(-2.0f * a);
                float s2, c2;
                __sincosf(2.0f * b, &s2, &c2);
                float wr = e * c2, wi = -e * s2;
                float u = 1.0f + wr;
                float res_re = a + 0.5f * __logf(u * u + wi * wi) - LN2;
                if (mode == 0) {
                    int fi = m * DM + n;
                    if (fi < out_floats) out[fi] = res_re;
                } else {
                    float res_im = b + atan2f(wi, u);
                    int fi = (m * DM + n) * 2;
                    if (fi < out_floats)     out[fi]     = res_re;
                    if (fi + 1 < out_floats) out[fi + 1] = res_im;
                }
            }
        }
    }
}

// ---------------------------------------------------------------------------
extern "C" void kernel_launch(void* const* d_in, const int* in_sizes, int n_in,
                              void* d_out, int out_size)
{
    const float* x = nullptr;   int sx = 0;
    const float* vk[2] = {};    int svk = 0;
    const float* J[2]  = {};    int sj = 0;
    const float* wk[2] = {};    int swk = 0;
    const float* bs[4] = {};    int sb = 0;
    int nvk = 0, nj = 0, nwk = 0, nb = 0;

    for (int i = 0; i < n_in; i++) {
        const float* p = (const float*)d_in[i];
        int sz = in_sizes[i];
        if      (sz == 65536   && !x)      { x = p; sx = sz; }
        else if (sz == 524288  && nvk < 2) { vk[nvk++] = p; svk = sz; }
        else if (sz == 8192    && nj  < 2) { J[nj++]   = p; sj  = sz; }
        else if (sz == 4194304 && nwk < 2) { wk[nwk++] = p; swk = sz; }
        else if (sz == 2048    && nb  < 4) { bs[nb++]  = p; sb  = sz; }
    }

    if (!(x && nvk == 2 && nj == 2 && nwk == 2 && nb == 4)) {
        if (n_in < 11) return;
        x     = (const float*)d_in[0];  sx  = in_sizes[0];
        vk[0] = (const float*)d_in[1];  bs[0] = (const float*)d_in[2];
        vk[1] = (const float*)d_in[3];  bs[1] = (const float*)d_in[4];
        J[0]  = (const float*)d_in[5];  J[1]  = (const float*)d_in[6];
        wk[0] = (const float*)d_in[7];  bs[2] = (const float*)d_in[8];
        wk[1] = (const float*)d_in[9];  bs[3] = (const float*)d_in[10];
        svk = in_sizes[1]; sj = in_sizes[5]; swk = in_sizes[7]; sb = in_sizes[2];
    }

    int mode       = (out_size == 2 * P_ * DM) ? 1 : 0;
    int out_floats = out_size;

    static bool attr_done = false;
    static cudaStream_t s_side = nullptr;
    static cudaEvent_t ev_fork = nullptr, ev_join = nullptr;
    if (!attr_done) {
        cudaFuncSetAttribute(gemm_out_mma,
                             cudaFuncAttributeMaxDynamicSharedMemorySize, SMEM_GEMM);
        cudaFuncSetAttribute(gemm_v_mma,
                             cudaFuncAttributeMaxDynamicSharedMemorySize, SMEM_V);
        cudaFuncSetAttribute(circ_att_mma,
                             cudaFuncAttributeMaxDynamicSharedMemorySize, SMEM_C);
        cudaStreamCreateWithFlags(&s_side, cudaStreamNonBlocking);
        cudaEventCreateWithFlags(&ev_fork, cudaEventDisableTiming);
        cudaEventCreateWithFlags(&ev_join, cudaEventDisableTiming);
        attr_done = true;
    }

    // fork: split_wt (independent of the v/att chain) runs on side stream
    cudaEventRecord(ev_fork, 0);
    cudaStreamWaitEvent(s_side, ev_fork, 0);
    split_wt<<<dim3(DM / 32, DM / 32), 256, 0, s_side>>>(wk[0], wk[1], swk);
    cudaEventRecord(ev_join, s_side);

    // main chain (default stream)
    split_x   <<<(P_ * PATCH_ + 255) / 256, 256>>>(x, sx);
    split_vk  <<<dim3(DM / 32, PATCH_ / 32), 256>>>(vk[0], vk[1], svk);
    gemm_v_mma<<<dim3(DM / BN, P_ / BM), 256, SMEM_V>>>(bs[0], bs[1], sb);
    circ_att_mma<<<dim3(P_ / 64, H_), 256, SMEM_C>>>(J[0], J[1], sj);

    // join: gemm_out needs both Y panels (chain) and W panels (side)
    cudaStreamWaitEvent(0, ev_join, 0);
    gemm_out_mma<<<dim3(DM / BN, P_ / BM), 256, SMEM_GEMM>>>(
        bs[2], bs[3], sb, (float*)d_out, out_floats, mode);
}